// round 9
// baseline (speedup 1.0000x reference)
#include <cuda_runtime.h>
#include <cuda_fp16.h>
#include <mma.h>
#include <cstdint>
#include <string.h>
#include <math.h>
#include <type_traits>

using namespace nvcuda;

// ===========================================================================
//  h   = lrelu(x) @ W_enc + b         [32768,512]  WMMA 3-term split
//  M_n = (WQ_n @ WK_n^T)/sqrt(512)    [8,512,512]  WMMA 3-term (WK no transp)
//  Q'  = ha @ M_n                     [8,8192,512] WMMA 3-term
//  attn fused: S=Q'@h^T (3-term) -> softmax -> U=P@h (1-term fp16)
//  out = (1/8) U @ WVcat              [8192,512]   WMMA 1-term fp16
// This round: __launch_bounds__(256,2) to force 2 CTAs/SM (was 1 at 178 regs,
// occ 12.4%, tensor pipe 37.5% — register file was the occupancy limiter).
// ===========================================================================

// -------------------- scratch (device globals) -----------------------------
static __device__ float  g_M [8u * 512u * 512u];
static __device__ __half g_h0[32768u * 512u],  g_h1[32768u * 512u];
static __device__ __half g_Q0[8u * 8192u * 512u], g_Q1[8u * 8192u * 512u];
static __device__ __half g_U0[8192u * 4096u];                              // 1-term
static __device__ __half g_Te0[512u * 256u],  g_Te1[512u * 256u];          // W_enc^T
static __device__ __half g_Tm0[8u * 512u * 512u], g_Tm1[8u * 512u * 512u]; // M^T
static __device__ __half g_Tw0[512u * 4096u], g_Tw1[512u * 4096u];         // WVcat^T
static __device__ __half g_Wk0[8u * 512u * 512u], g_Wk1[8u * 512u * 512u]; // WK split

__device__ __forceinline__ float lrelu(float v) { return v > 0.0f ? v : 0.01f * v; }

__device__ __forceinline__ void split2(float v, __half& h0, __half& h1) {
    h0 = __float2half_rn(v);
    h1 = __float2half_rn(v - __half2float(h0));
}

__device__ __forceinline__ uint32_t h2u(__half2 v) {
    uint32_t u;
    memcpy(&u, &v, 4);
    return u;
}

// ---------------------------------------------------------------------------
// elementwise fp16 split2 (no transpose)
// ---------------------------------------------------------------------------
__global__ __launch_bounds__(256) void k_split2e(const float* __restrict__ B,
                                                 __half* __restrict__ T0,
                                                 __half* __restrict__ T1,
                                                 size_t total) {
    for (size_t i = (size_t)blockIdx.x * 256 + threadIdx.x; i < total;
         i += (size_t)gridDim.x * 256) {
        split2(B[i], T0[i], T1[i]);
    }
}

// ---------------------------------------------------------------------------
// tiled transpose + fp16 split2:  T*[n*K+k] = split(B[k*N+n])  (coalesced)
// grid (K/32, N/32, batch), block (32,8)
// ---------------------------------------------------------------------------
__global__ __launch_bounds__(256) void k_tsplit2(const float* __restrict__ B,
                                                 __half* __restrict__ T0,
                                                 __half* __restrict__ T1,
                                                 int K, int N) {
    __shared__ __half s0[32][33];
    __shared__ __half s1[32][33];
    const size_t base = (size_t)blockIdx.z * (size_t)K * N;
    const int k0 = blockIdx.x * 32, n0 = blockIdx.y * 32;
    const int tx = threadIdx.x, ty = threadIdx.y;
#pragma unroll
    for (int i = 0; i < 4; i++) {
        int row = ty * 4 + i;
        float v = B[base + (size_t)(k0 + row) * N + n0 + tx];
        split2(v, s0[row][tx], s1[row][tx]);
    }
    __syncthreads();
#pragma unroll
    for (int i = 0; i < 4; i++) {
        int nrow = ty * 4 + i;
        size_t o = base + (size_t)(n0 + nrow) * K + k0 + tx;
        T0[o] = s0[tx][nrow];
        T1[o] = s1[tx][nrow];
    }
}

// ---------------------------------------------------------------------------
// Generic WMMA GEMM (BM=128 rows, 128 cols).  NT=3: split-pair 3-product.
// NT=1: plain fp16 single product (plane 0 only).
// Epilogue stages C fp32 through smem: needs >= BM*128*4 bytes dynamic smem.
// ---------------------------------------------------------------------------
template <int BM, int NT>
__global__ __launch_bounds__(256, 2) void k_mma(
    const float* __restrict__ Afp,
    const __half* __restrict__ A0g, const __half* __restrict__ A1g,
    const __half* __restrict__ B0g, const __half* __restrict__ B1g,
    float* __restrict__ Cf, __half* __restrict__ C0g, __half* __restrict__ C1g,
    const float* __restrict__ bias, float alpha,
    int Ktot, int lda, int ldb, int ldc,
    int flags,  // 1 = lrelu on fp32 A, 2 = gather rows (b*256+a map)
    long long aHi, long long bHi, long long cHi)
{
    constexpr int WMG = 4;
    constexpr int WN  = 64;
    constexpr int NF  = 4;
    constexpr int LDA = 40;
    constexpr int LDB = 40;
    constexpr int PL  = (NT > 1) ? 2 : 1;
    constexpr int APL = BM * LDA * 2;
    constexpr int BPL = 128 * LDB * 2;
    constexpr int STAGE = PL * (APL + BPL);
    constexpr int ACH = BM * 4 / 256;
    constexpr int AF4 = BM * 8 / 256;

    extern __shared__ __align__(1024) char sm[];

    const int tid = threadIdx.x;
    const int w = tid >> 5;
    const int wm = w & (WMG - 1);
    const int wn = w / WMG;
    const long long aoff = (long long)blockIdx.z * aHi;
    const long long boff = (long long)blockIdx.z * bHi;
    const long long coff = (long long)blockIdx.z * cHi;
    const int m0 = blockIdx.y * BM;
    const int n0 = blockIdx.x * 128;
    const bool a_fp32 = (Afp != nullptr);
    const bool gather = (flags & 2) != 0;
    const bool do_lrelu = (flags & 1) != 0;

    int aprow[ACH], apk[ACH];
    int afrow[AF4], afk[AF4];
#pragma unroll
    for (int i = 0; i < ACH; i++) {
        int id = tid + i * 256;
        aprow[i] = id >> 2;
        apk[i] = (id & 3) * 8;
    }
#pragma unroll
    for (int i = 0; i < AF4; i++) {
        int id = tid + i * 256;
        afrow[i] = id >> 3;
        afk[i] = (id & 7) * 4;
    }
    int brow[2], bk[2];
#pragma unroll
    for (int i = 0; i < 2; i++) {
        int id = tid + i * 256;
        brow[i] = id >> 2;
        bk[i] = (id & 3) * 8;
    }

    auto a_grow = [&](int r) -> long long {
        int g = m0 + r;
        return gather ? (long long)(((g >> 6) << 8) + (g & 63)) : (long long)g;
    };

    wmma::fragment<wmma::accumulator, 16, 16, 16, float> acc[2][NF];
#pragma unroll
    for (int mf = 0; mf < 2; mf++)
#pragma unroll
        for (int nf = 0; nf < NF; nf++) wmma::fill_fragment(acc[mf][nf], 0.0f);

    uint4 ra0[ACH], ra1[ACH];
    float4 rf[AF4];
    uint4 rb0[2], rb1[2];

    auto load_tile = [&](int k0) {
        if (a_fp32) {
#pragma unroll
            for (int i = 0; i < AF4; i++)
                rf[i] = *(const float4*)(Afp + aoff + a_grow(afrow[i]) * lda + k0 + afk[i]);
        } else {
#pragma unroll
            for (int i = 0; i < ACH; i++) {
                long long r = aoff + a_grow(aprow[i]) * lda + k0 + apk[i];
                ra0[i] = *(const uint4*)(A0g + r);
                if (NT > 1) ra1[i] = *(const uint4*)(A1g + r);
            }
        }
#pragma unroll
        for (int i = 0; i < 2; i++) {
            long long r = boff + (long long)(n0 + brow[i]) * ldb + k0 + bk[i];
            rb0[i] = *(const uint4*)(B0g + r);
            if (NT > 1) rb1[i] = *(const uint4*)(B1g + r);
        }
    };

    auto store_tile = [&](int buf) {
        char* base = sm + buf * STAGE;
        char* sA0 = base;
        char* sA1 = base + APL;
        char* sB0 = base + PL * APL;
        char* sB1 = base + PL * APL + BPL;
        if (a_fp32) {
#pragma unroll
            for (int i = 0; i < AF4; i++) {
                float4 v = rf[i];
                if (do_lrelu) { v.x = lrelu(v.x); v.y = lrelu(v.y); v.z = lrelu(v.z); v.w = lrelu(v.w); }
                __half x0, x1, y0, y1, z0, z1, w0, w1;
                split2(v.x, x0, x1); split2(v.y, y0, y1);
                split2(v.z, z0, z1); split2(v.w, w0, w1);
                int off = afrow[i] * (LDA * 2) + afk[i] * 2;
                __half2 p0 = __halves2half2(x0, y0), q0 = __halves2half2(z0, w0);
                *(uint2*)(sA0 + off) = make_uint2(h2u(p0), h2u(q0));
                if (NT > 1) {
                    __half2 p1 = __halves2half2(x1, y1), q1 = __halves2half2(z1, w1);
                    *(uint2*)(sA1 + off) = make_uint2(h2u(p1), h2u(q1));
                }
            }
        } else {
#pragma unroll
            for (int i = 0; i < ACH; i++) {
                int off = aprow[i] * (LDA * 2) + apk[i] * 2;
                *(uint4*)(sA0 + off) = ra0[i];
                if (NT > 1) *(uint4*)(sA1 + off) = ra1[i];
            }
        }
#pragma unroll
        for (int i = 0; i < 2; i++) {
            int off = brow[i] * (LDB * 2) + bk[i] * 2;
            *(uint4*)(sB0 + off) = rb0[i];
            if (NT > 1) *(uint4*)(sB1 + off) = rb1[i];
        }
    };

    auto mma_tile = [&](int buf) {
        const char* base = sm + buf * STAGE;
        const __half* sA0 = (const __half*)(base);
        const __half* sA1 = (const __half*)(base + APL);
        const __half* sB0 = (const __half*)(base + PL * APL);
        const __half* sB1 = (const __half*)(base + PL * APL + BPL);
#pragma unroll
        for (int ks = 0; ks < 32; ks += 16) {
            wmma::fragment<wmma::matrix_a, 16, 16, 16, __half, wmma::row_major> a0f[2], a1f[2];
#pragma unroll
            for (int mf = 0; mf < 2; mf++) {
                int r0 = wm * 32 + mf * 16;
                wmma::load_matrix_sync(a0f[mf], sA0 + r0 * LDA + ks, LDA);
                if (NT > 1) wmma::load_matrix_sync(a1f[mf], sA1 + r0 * LDA + ks, LDA);
            }
#pragma unroll
            for (int nf = 0; nf < NF; nf++) {
                int col = wn * WN + nf * 16;
                wmma::fragment<wmma::matrix_b, 16, 16, 16, __half, wmma::col_major> b0f, b1f;
                wmma::load_matrix_sync(b0f, sB0 + col * LDB + ks, LDB);
                if (NT > 1) wmma::load_matrix_sync(b1f, sB1 + col * LDB + ks, LDB);
#pragma unroll
                for (int mf = 0; mf < 2; mf++) {
                    wmma::mma_sync(acc[mf][nf], a0f[mf], b0f, acc[mf][nf]);
                    if (NT > 1) {
                        wmma::mma_sync(acc[mf][nf], a0f[mf], b1f, acc[mf][nf]);
                        wmma::mma_sync(acc[mf][nf], a1f[mf], b0f, acc[mf][nf]);
                    }
                }
            }
        }
    };

    const int numK = Ktot >> 5;
    load_tile(0);
    for (int t = 0; t < numK; t++) {
        store_tile(t & 1);
        __syncthreads();
        if (t + 1 < numK) load_tile((t + 1) << 5);
        mma_tile(t & 1);
    }

    __syncthreads();
    float* Csm = (float*)sm;
#pragma unroll
    for (int mf = 0; mf < 2; mf++)
#pragma unroll
        for (int nf = 0; nf < NF; nf++) {
            int r0 = wm * 32 + mf * 16, c0 = wn * WN + nf * 16;
            wmma::store_matrix_sync(Csm + r0 * 128 + c0, acc[mf][nf], 128, wmma::mem_row_major);
        }
    __syncthreads();

    const int NOUT = BM * 128 / 4 / 256;
#pragma unroll
    for (int i = 0; i < NOUT; i++) {
        int f = tid + i * 256;
        int row = f >> 5, c4 = (f & 31) * 4;
        float4 v = *(float4*)(Csm + row * 128 + c4);
        v.x *= alpha; v.y *= alpha; v.z *= alpha; v.w *= alpha;
        if (bias) {
            v.x += bias[n0 + c4 + 0]; v.y += bias[n0 + c4 + 1];
            v.z += bias[n0 + c4 + 2]; v.w += bias[n0 + c4 + 3];
        }
        long long o = coff + (long long)(m0 + row) * ldc + n0 + c4;
        if (Cf) {
            *(float4*)(Cf + o) = v;
        } else {
            __half x0, x1, y0, y1, z0, z1, w0, w1;
            split2(v.x, x0, x1); split2(v.y, y0, y1);
            split2(v.z, z0, z1); split2(v.w, w0, w1);
            __half2 p0 = __halves2half2(x0, y0), q0 = __halves2half2(z0, w0);
            *(uint2*)(C0g + o) = make_uint2(h2u(p0), h2u(q0));
            if (C1g) {
                __half2 p1 = __halves2half2(x1, y1), q1 = __halves2half2(z1, w1);
                *(uint2*)(C1g + o) = make_uint2(h2u(p1), h2u(q1));
            }
        }
    }
}

// ---------------------------------------------------------------------------
// Fused attention per (b, n) CTA:
//   S[64,256] = Q'@h^T (3-term) -> softmax -> P fp16 -> U[64,512] = P@h (1-term)
// smem (102400):
//   phase1 stage 2x51200 @0 | then Ssm fp32 64x264 @0, Psm0 @67584 (33792)
//   phase3 stage 2x16896 @0 | epilogue Csm fp32 64x264 @0
// ---------------------------------------------------------------------------
#define ATTN_SMEM 102400

__global__ __launch_bounds__(256, 2) void k_attn() {
    extern __shared__ __align__(1024) char sm[];
    const int tid = threadIdx.x;
    const int w = tid >> 5, lane = tid & 31;
    const int wm = w & 1, wn = w >> 1;     // 2 x 4 warp grid, warp tile 32x64
    const int b = blockIdx.x, n = blockIdx.y;

    float* Ssm = (float*)sm;                               // 64 x 264 fp32
    __half* Psm0 = (__half*)(sm + 67584);                  // 64 x 264

    const __half* Qb0 = g_Q0 + ((size_t)n * 8192 + (size_t)b * 64) * 512;
    const __half* Qb1 = g_Q1 + ((size_t)n * 8192 + (size_t)b * 64) * 512;
    const __half* Hb0 = g_h0 + (size_t)b * 256 * 512;
    const __half* Hb1 = g_h1 + (size_t)b * 256 * 512;

    wmma::fragment<wmma::accumulator, 16, 16, 16, float> acc[2][4];
#pragma unroll
    for (int mf = 0; mf < 2; mf++)
#pragma unroll
        for (int nf = 0; nf < 4; nf++) wmma::fill_fragment(acc[mf][nf], 0.0f);

    // ======== phase 1: S = Q' @ h^T  (K=512, 16 chunks of 32, 3-term) =====
    {
        const int arow = tid >> 2, akc = (tid & 3) * 8;
        uint4 ra0, ra1, rb0[4], rb1[4];
        auto p1_load = [&](int k0) {
            ra0 = *(const uint4*)(Qb0 + (size_t)arow * 512 + k0 + akc);
            ra1 = *(const uint4*)(Qb1 + (size_t)arow * 512 + k0 + akc);
#pragma unroll
            for (int i = 0; i < 4; i++) {
                int id = tid + i * 256;
                int br = id >> 2, bkc = (id & 3) * 8;
                rb0[i] = *(const uint4*)(Hb0 + (size_t)br * 512 + k0 + bkc);
                rb1[i] = *(const uint4*)(Hb1 + (size_t)br * 512 + k0 + bkc);
            }
        };
        auto p1_store = [&](int buf) {
            char* base = sm + buf * 51200;
            __half* sA0 = (__half*)base;
            __half* sA1 = (__half*)(base + 5120);
            __half* sB0 = (__half*)(base + 10240);
            __half* sB1 = (__half*)(base + 30720);
            *(uint4*)(sA0 + arow * 40 + akc) = ra0;
            *(uint4*)(sA1 + arow * 40 + akc) = ra1;
#pragma unroll
            for (int i = 0; i < 4; i++) {
                int id = tid + i * 256;
                int br = id >> 2, bkc = (id & 3) * 8;
                *(uint4*)(sB0 + br * 40 + bkc) = rb0[i];
                *(uint4*)(sB1 + br * 40 + bkc) = rb1[i];
            }
        };
        auto p1_mma = [&](int buf) {
            const char* base = sm + buf * 51200;
            const __half* sA0 = (const __half*)base;
            const __half* sA1 = (const __half*)(base + 5120);
            const __half* sB0 = (const __half*)(base + 10240);
            const __half* sB1 = (const __half*)(base + 30720);
#pragma unroll
            for (int ks = 0; ks < 32; ks += 16) {
                wmma::fragment<wmma::matrix_a, 16, 16, 16, __half, wmma::row_major> a0f[2], a1f[2];
#pragma unroll
                for (int mf = 0; mf < 2; mf++) {
                    int r0 = wm * 32 + mf * 16;
                    wmma::load_matrix_sync(a0f[mf], sA0 + r0 * 40 + ks, 40);
                    wmma::load_matrix_sync(a1f[mf], sA1 + r0 * 40 + ks, 40);
                }
#pragma unroll
                for (int nf = 0; nf < 4; nf++) {
                    int col = wn * 64 + nf * 16;
                    wmma::fragment<wmma::matrix_b, 16, 16, 16, __half, wmma::col_major> b0f, b1f;
                    wmma::load_matrix_sync(b0f, sB0 + col * 40 + ks, 40);
                    wmma::load_matrix_sync(b1f, sB1 + col * 40 + ks, 40);
#pragma unroll
                    for (int mf = 0; mf < 2; mf++) {
                        wmma::mma_sync(acc[mf][nf], a0f[mf], b0f, acc[mf][nf]);
                        wmma::mma_sync(acc[mf][nf], a0f[mf], b1f, acc[mf][nf]);
                        wmma::mma_sync(acc[mf][nf], a1f[mf], b0f, acc[mf][nf]);
                    }
                }
            }
        };
        p1_load(0);
        for (int t = 0; t < 16; t++) {
            p1_store(t & 1);
            __syncthreads();
            if (t + 1 < 16) p1_load((t + 1) << 5);
            p1_mma(t & 1);
        }
    }

    // ======== stage S -> smem fp32 ========
    __syncthreads();
#pragma unroll
    for (int mf = 0; mf < 2; mf++)
#pragma unroll
        for (int nf = 0; nf < 4; nf++) {
            int r0 = wm * 32 + mf * 16, c0 = wn * 64 + nf * 16;
            wmma::store_matrix_sync(Ssm + r0 * 264 + c0, acc[mf][nf], 264, wmma::mem_row_major);
        }
    __syncthreads();

    // ======== softmax: warp w owns rows w*8 .. w*8+7; P fp16 single plane ==
#pragma unroll
    for (int i = 0; i < 8; i++) {
        int r = w * 8 + i;
        float* srow = Ssm + (size_t)r * 264 + lane * 8;
        float4 v0 = *(float4*)srow;
        float4 v1 = *(float4*)(srow + 4);
        float m = fmaxf(fmaxf(fmaxf(v0.x, v0.y), fmaxf(v0.z, v0.w)),
                        fmaxf(fmaxf(v1.x, v1.y), fmaxf(v1.z, v1.w)));
#pragma unroll
        for (int off = 16; off > 0; off >>= 1)
            m = fmaxf(m, __shfl_xor_sync(0xffffffffu, m, off));
        v0.x = __expf(v0.x - m); v0.y = __expf(v0.y - m);
        v0.z = __expf(v0.z - m); v0.w = __expf(v0.w - m);
        v1.x = __expf(v1.x - m); v1.y = __expf(v1.y - m);
        v1.z = __expf(v1.z - m); v1.w = __expf(v1.w - m);
        float s = v0.x + v0.y + v0.z + v0.w + v1.x + v1.y + v1.z + v1.w;
#pragma unroll
        for (int off = 16; off > 0; off >>= 1)
            s += __shfl_xor_sync(0xffffffffu, s, off);
        const float inv = 1.0f / s;
        __align__(16) __half h0[8];
        h0[0] = __float2half_rn(v0.x * inv); h0[1] = __float2half_rn(v0.y * inv);
        h0[2] = __float2half_rn(v0.z * inv); h0[3] = __float2half_rn(v0.w * inv);
        h0[4] = __float2half_rn(v1.x * inv); h0[5] = __float2half_rn(v1.y * inv);
        h0[6] = __float2half_rn(v1.z * inv); h0[7] = __float2half_rn(v1.w * inv);
        *(uint4*)(Psm0 + (size_t)r * 264 + lane * 8) = *(uint4*)h0;
    }
    __syncthreads();

    // ======== phase 3: U = P @ h  (1-term; two 256-col halves; K=256) =====
    for (int hh = 0; hh < 2; hh++) {
        const int d0 = hh * 256;
#pragma unroll
        for (int mf = 0; mf < 2; mf++)
#pragma unroll
            for (int nf = 0; nf < 4; nf++) wmma::fill_fragment(acc[mf][nf], 0.0f);

        uint4 rh0[4];
        auto p3_load = [&](int k0) {
#pragma unroll
            for (int i = 0; i < 4; i++) {
                int id = tid + i * 256;
                int er = id >> 5, dc = id & 31;
                rh0[i] = *(const uint4*)(Hb0 + (size_t)(k0 + er) * 512 + d0 + dc * 8);
            }
        };
        auto p3_store = [&](int buf) {
            __half* sH0 = (__half*)(sm + buf * 16896);
#pragma unroll
            for (int i = 0; i < 4; i++) {
                int id = tid + i * 256;
                int er = id >> 5, dc = id & 31;
                *(uint4*)(sH0 + er * 264 + dc * 8) = rh0[i];
            }
        };
        auto p3_mma = [&](int buf, int c) {
            const __half* sH0 = (const __half*)(sm + buf * 16896);
#pragma unroll
            for (int ks = 0; ks < 32; ks += 16) {
                wmma::fragment<wmma::matrix_a, 16, 16, 16, __half, wmma::row_major> a0f[2];
#pragma unroll
                for (int mf = 0; mf < 2; mf++) {
                    int r0 = wm * 32 + mf * 16;
                    wmma::load_matrix_sync(a0f[mf], Psm0 + r0 * 264 + c * 32 + ks, 264);
                }
#pragma unroll
                for (int nf = 0; nf < 4; nf++) {
                    int col = wn * 64 + nf * 16;
                    wmma::fragment<wmma::matrix_b, 16, 16, 16, __half, wmma::row_major> b0f;
                    wmma::load_matrix_sync(b0f, sH0 + ks * 264 + col, 264);
#pragma unroll
                    for (int mf = 0; mf < 2; mf++)
                        wmma::mma_sync(acc[mf][nf], a0f[mf], b0f, acc[mf][nf]);
                }
            }
        };
        p3_load(0);
        for (int c = 0; c < 8; c++) {
            p3_store(c & 1);
            __syncthreads();
            if (c + 1 < 8) p3_load((c + 1) << 5);
            p3_mma(c & 1, c);
        }

        __syncthreads();
        float* Csm = (float*)sm;
#pragma unroll
        for (int mf = 0; mf < 2; mf++)
#pragma unroll
            for (int nf = 0; nf < 4; nf++) {
                int r0 = wm * 32 + mf * 16, c0 = wn * 64 + nf * 16;
                wmma::store_matrix_sync(Csm + r0 * 264 + c0, acc[mf][nf], 264, wmma::mem_row_major);
            }
        __syncthreads();
#pragma unroll
        for (int i = 0; i < 16; i++) {
            int id = tid + i * 256;
            int row = id >> 6, c4 = (id & 63) * 4;
            float4 v = *(float4*)(Csm + row * 264 + c4);
            __align__(8) __half h4[4];
            h4[0] = __float2half_rn(v.x); h4[1] = __float2half_rn(v.y);
            h4[2] = __float2half_rn(v.z); h4[3] = __float2half_rn(v.w);
            size_t o = (((size_t)(b * 64 + row)) * 8 + n) * 512 + d0 + c4;
            *(uint2*)(g_U0 + o) = *(uint2*)h4;
        }
        __syncthreads();
    }
}

// ---------------------------------------------------------------------------
extern "C" void kernel_launch(void* const* d_in, const int* in_sizes, int n_in,
                              void* d_out, int out_size) {
    const float* x     = (const float*)d_in[0];
    const float* W_enc = (const float*)d_in[1];
    const float* b_enc = (const float*)d_in[2];
    const float* WQ    = (const float*)d_in[3];
    const float* WK    = (const float*)d_in[4];
    const float* WV    = (const float*)d_in[5];
    float* out = (float*)d_out;

    const int SM128_3 = 2 * 2 * (128 * 40 * 2 + 128 * 40 * 2);   // 81920
    const int SM128_1 = 128 * 128 * 4;                            // 65536
    cudaFuncSetAttribute(k_mma<128, 3>, cudaFuncAttributeMaxDynamicSharedMemorySize, SM128_3);
    cudaFuncSetAttribute(k_mma<128, 1>, cudaFuncAttributeMaxDynamicSharedMemorySize, SM128_1);
    cudaFuncSetAttribute(k_attn, cudaFuncAttributeMaxDynamicSharedMemorySize, ATTN_SMEM);

    void *p_M, *p_h0, *p_h1, *p_Q0, *p_Q1, *p_U0;
    void *p_e0, *p_e1, *p_m0, *p_m1, *p_w0, *p_w1, *p_k0, *p_k1;
    cudaGetSymbolAddress(&p_M, g_M);
    cudaGetSymbolAddress(&p_h0, g_h0); cudaGetSymbolAddress(&p_h1, g_h1);
    cudaGetSymbolAddress(&p_Q0, g_Q0); cudaGetSymbolAddress(&p_Q1, g_Q1);
    cudaGetSymbolAddress(&p_U0, g_U0);
    cudaGetSymbolAddress(&p_e0, g_Te0); cudaGetSymbolAddress(&p_e1, g_Te1);
    cudaGetSymbolAddress(&p_m0, g_Tm0); cudaGetSymbolAddress(&p_m1, g_Tm1);
    cudaGetSymbolAddress(&p_w0, g_Tw0); cudaGetSymbolAddress(&p_w1, g_Tw1);
    cudaGetSymbolAddress(&p_k0, g_Wk0); cudaGetSymbolAddress(&p_k1, g_Wk1);

    // ---- weight prep
    k_tsplit2<<<dim3(8, 16, 1), dim3(32, 8)>>>(W_enc, (__half*)p_e0, (__half*)p_e1, 256, 512);
    k_tsplit2<<<dim3(128, 16, 1), dim3(32, 8)>>>(WV, (__half*)p_w0, (__half*)p_w1, 4096, 512);
    k_split2e<<<dim3(512), 256>>>(WK, (__half*)p_k0, (__half*)p_k1, (size_t)8 * 512 * 512);

    // ---- M_n = (WQ_n @ WK_n^T) * scale   (WMMA 3-term; WK is already [N,K])
    k_mma<128, 3><<<dim3(4, 4, 8), 256, SM128_3>>>(
        WQ, nullptr, nullptr, (const __half*)p_k0, (const __half*)p_k1,
        (float*)p_M, nullptr, nullptr, nullptr, 0.04419417382415922f,
        512, 512, 512, 512, /*flags*/0,
        (long long)512 * 512, (long long)512 * 512, (long long)512 * 512);

    k_tsplit2<<<dim3(16, 16, 8), dim3(32, 8)>>>((const float*)p_M, (__half*)p_m0, (__half*)p_m1, 512, 512);

    // ---- encode: h planes = lrelu(x) @ W_enc + b
    k_mma<128, 3><<<dim3(4, 256, 1), 256, SM128_3>>>(
        x, nullptr, nullptr, (const __half*)p_e0, (const __half*)p_e1,
        nullptr, (__half*)p_h0, (__half*)p_h1, b_enc, 1.0f,
        256, 256, 256, 512, /*flags*/1, 0, 0, 0);

    // ---- Q' planes = ha @ M_n   (gather, batched over heads)
    k_mma<128, 3><<<dim3(4, 64, 8), 256, SM128_3>>>(
        nullptr, (const __half*)p_h0, (const __half*)p_h1,
        (const __half*)p_m0, (const __half*)p_m1,
        nullptr, (__half*)p_Q0, (__half*)p_Q1, nullptr, 1.0f,
        512, 512, 512, 512, /*flags*/2,
        0, (long long)512 * 512, (long long)8192 * 512);

    // ---- fused attention (S 3-term -> softmax -> U 1-term fp16)
    k_attn<<<dim3(128, 8), 256, ATTN_SMEM>>>();

    // ---- out = (1/8) U @ WVcat   (1-term fp16)
    k_mma<128, 1><<<dim3(4, 64, 1), 256, SM128_1>>>(
        nullptr, (const __half*)p_U0, nullptr,
        (const __half*)p_w0, nullptr,
        out, nullptr, nullptr, nullptr, 0.125f,
        4096, 4096, 4096, 512, 0, 0, 0, 0);
}

// round 10
// speedup vs baseline: 1.1498x; 1.1498x over previous
#include <cuda_runtime.h>
#include <cuda_fp16.h>
#include <mma.h>
#include <cstdint>
#include <string.h>
#include <math.h>
#include <type_traits>

using namespace nvcuda;

// ===========================================================================
//  h   = lrelu(x) @ W_enc + b         [32768,512]  WMMA 3-term split
//  M_n = (WQ_n @ WK_n^T)/sqrt(512)    [8,512,512]  WMMA 3-term (WK no transp)
//  Q'  = ha @ M_n                     [8,8192,512] WMMA 3-term
//  attn fused: S=Q'@h^T (3-term) -> softmax -> U=P@h (1-term fp16)
//  out = (1/8) U @ WVcat              [8192,512]   WMMA 1-term fp16
// This round: k_mma CTAs shrunk to 128 threads / 64x128 tile so TWO CTAs fit
// per SM by natural register count (no reg cap, no spills) — cross-CTA
// overlap of load/sync phases with MMA phases.
// ===========================================================================

// -------------------- scratch (device globals) -----------------------------
static __device__ float  g_M [8u * 512u * 512u];
static __device__ __half g_h0[32768u * 512u],  g_h1[32768u * 512u];
static __device__ __half g_Q0[8u * 8192u * 512u], g_Q1[8u * 8192u * 512u];
static __device__ __half g_U0[8192u * 4096u];                              // 1-term
static __device__ __half g_Te0[512u * 256u],  g_Te1[512u * 256u];          // W_enc^T
static __device__ __half g_Tm0[8u * 512u * 512u], g_Tm1[8u * 512u * 512u]; // M^T
static __device__ __half g_Tw0[512u * 4096u], g_Tw1[512u * 4096u];         // WVcat^T
static __device__ __half g_Wk0[8u * 512u * 512u], g_Wk1[8u * 512u * 512u]; // WK split

__device__ __forceinline__ float lrelu(float v) { return v > 0.0f ? v : 0.01f * v; }

__device__ __forceinline__ void split2(float v, __half& h0, __half& h1) {
    h0 = __float2half_rn(v);
    h1 = __float2half_rn(v - __half2float(h0));
}

__device__ __forceinline__ uint32_t h2u(__half2 v) {
    uint32_t u;
    memcpy(&u, &v, 4);
    return u;
}

// ---------------------------------------------------------------------------
// elementwise fp16 split2 (no transpose)
// ---------------------------------------------------------------------------
__global__ __launch_bounds__(256) void k_split2e(const float* __restrict__ B,
                                                 __half* __restrict__ T0,
                                                 __half* __restrict__ T1,
                                                 size_t total) {
    for (size_t i = (size_t)blockIdx.x * 256 + threadIdx.x; i < total;
         i += (size_t)gridDim.x * 256) {
        split2(B[i], T0[i], T1[i]);
    }
}

// ---------------------------------------------------------------------------
// tiled transpose + fp16 split2:  T*[n*K+k] = split(B[k*N+n])  (coalesced)
// grid (K/32, N/32, batch), block (32,8)
// ---------------------------------------------------------------------------
__global__ __launch_bounds__(256) void k_tsplit2(const float* __restrict__ B,
                                                 __half* __restrict__ T0,
                                                 __half* __restrict__ T1,
                                                 int K, int N) {
    __shared__ __half s0[32][33];
    __shared__ __half s1[32][33];
    const size_t base = (size_t)blockIdx.z * (size_t)K * N;
    const int k0 = blockIdx.x * 32, n0 = blockIdx.y * 32;
    const int tx = threadIdx.x, ty = threadIdx.y;
#pragma unroll
    for (int i = 0; i < 4; i++) {
        int row = ty * 4 + i;
        float v = B[base + (size_t)(k0 + row) * N + n0 + tx];
        split2(v, s0[row][tx], s1[row][tx]);
    }
    __syncthreads();
#pragma unroll
    for (int i = 0; i < 4; i++) {
        int nrow = ty * 4 + i;
        size_t o = base + (size_t)(n0 + nrow) * K + k0 + tx;
        T0[o] = s0[tx][nrow];
        T1[o] = s1[tx][nrow];
    }
}

// ---------------------------------------------------------------------------
// WMMA GEMM, 128 threads, tile 64(M) x 128(N).  NT=3: split-pair 3-product.
// NT=1: plain fp16 single product (plane 0 only).
// Warp grid 2x2, warp tile 32x64.  2 (NT=3) / 3 (NT=1) CTAs per SM.
// Epilogue stages C fp32 through smem: needs >= 64*128*4 = 32768 B.
// ---------------------------------------------------------------------------
template <int NT>
__global__ __launch_bounds__(128, (NT == 1) ? 3 : 2) void k_mma(
    const float* __restrict__ Afp,
    const __half* __restrict__ A0g, const __half* __restrict__ A1g,
    const __half* __restrict__ B0g, const __half* __restrict__ B1g,
    float* __restrict__ Cf, __half* __restrict__ C0g, __half* __restrict__ C1g,
    const float* __restrict__ bias, float alpha,
    int Ktot, int lda, int ldb, int ldc,
    int flags,  // 1 = lrelu on fp32 A, 2 = gather rows (b*256+a map)
    long long aHi, long long bHi, long long cHi)
{
    constexpr int BM  = 64;
    constexpr int NF  = 4;           // 64-wide warp N / 16
    constexpr int LDA = 40;
    constexpr int LDB = 40;
    constexpr int PL  = (NT > 1) ? 2 : 1;
    constexpr int APL = BM * LDA * 2;           // 5120 per plane
    constexpr int BPL = 128 * LDB * 2;          // 10240 per plane
    constexpr int STAGE = PL * (APL + BPL);
    constexpr int ACH = BM * 4 / 128;           // 2 uint4 per thread per plane
    constexpr int BCH = 128 * 4 / 128;          // 4 uint4 per thread per plane
    constexpr int AF4 = BM * 8 / 128;           // 4 float4 per thread (fp32 A)

    extern __shared__ __align__(1024) char sm[];

    const int tid = threadIdx.x;
    const int w = tid >> 5;
    const int wm = w & 1;            // 2 warps along M (32 rows each)
    const int wn = w >> 1;           // 2 warps along N (64 cols each)
    const long long aoff = (long long)blockIdx.z * aHi;
    const long long boff = (long long)blockIdx.z * bHi;
    const long long coff = (long long)blockIdx.z * cHi;
    const int m0 = blockIdx.y * BM;
    const int n0 = blockIdx.x * 128;
    const bool a_fp32 = (Afp != nullptr);
    const bool gather = (flags & 2) != 0;
    const bool do_lrelu = (flags & 1) != 0;

    int aprow[ACH], apk[ACH];
    int afrow[AF4], afk[AF4];
#pragma unroll
    for (int i = 0; i < ACH; i++) {
        int id = tid + i * 128;
        aprow[i] = id >> 2;
        apk[i] = (id & 3) * 8;
    }
#pragma unroll
    for (int i = 0; i < AF4; i++) {
        int id = tid + i * 128;
        afrow[i] = id >> 3;
        afk[i] = (id & 7) * 4;
    }
    int brow[BCH], bk[BCH];
#pragma unroll
    for (int i = 0; i < BCH; i++) {
        int id = tid + i * 128;
        brow[i] = id >> 2;
        bk[i] = (id & 3) * 8;
    }

    auto a_grow = [&](int r) -> long long {
        int g = m0 + r;
        return gather ? (long long)(((g >> 6) << 8) + (g & 63)) : (long long)g;
    };

    wmma::fragment<wmma::accumulator, 16, 16, 16, float> acc[2][NF];
#pragma unroll
    for (int mf = 0; mf < 2; mf++)
#pragma unroll
        for (int nf = 0; nf < NF; nf++) wmma::fill_fragment(acc[mf][nf], 0.0f);

    uint4 ra0[ACH], ra1[ACH];
    float4 rf[AF4];
    uint4 rb0[BCH], rb1[BCH];

    auto load_tile = [&](int k0) {
        if (a_fp32) {
#pragma unroll
            for (int i = 0; i < AF4; i++)
                rf[i] = *(const float4*)(Afp + aoff + a_grow(afrow[i]) * lda + k0 + afk[i]);
        } else {
#pragma unroll
            for (int i = 0; i < ACH; i++) {
                long long r = aoff + a_grow(aprow[i]) * lda + k0 + apk[i];
                ra0[i] = *(const uint4*)(A0g + r);
                if (NT > 1) ra1[i] = *(const uint4*)(A1g + r);
            }
        }
#pragma unroll
        for (int i = 0; i < BCH; i++) {
            long long r = boff + (long long)(n0 + brow[i]) * ldb + k0 + bk[i];
            rb0[i] = *(const uint4*)(B0g + r);
            if (NT > 1) rb1[i] = *(const uint4*)(B1g + r);
        }
    };

    auto store_tile = [&](int buf) {
        char* base = sm + buf * STAGE;
        char* sA0 = base;
        char* sA1 = base + APL;
        char* sB0 = base + PL * APL;
        char* sB1 = base + PL * APL + BPL;
        if (a_fp32) {
#pragma unroll
            for (int i = 0; i < AF4; i++) {
                float4 v = rf[i];
                if (do_lrelu) { v.x = lrelu(v.x); v.y = lrelu(v.y); v.z = lrelu(v.z); v.w = lrelu(v.w); }
                __half x0, x1, y0, y1, z0, z1, w0, w1;
                split2(v.x, x0, x1); split2(v.y, y0, y1);
                split2(v.z, z0, z1); split2(v.w, w0, w1);
                int off = afrow[i] * (LDA * 2) + afk[i] * 2;
                __half2 p0 = __halves2half2(x0, y0), q0 = __halves2half2(z0, w0);
                *(uint2*)(sA0 + off) = make_uint2(h2u(p0), h2u(q0));
                if (NT > 1) {
                    __half2 p1 = __halves2half2(x1, y1), q1 = __halves2half2(z1, w1);
                    *(uint2*)(sA1 + off) = make_uint2(h2u(p1), h2u(q1));
                }
            }
        } else {
#pragma unroll
            for (int i = 0; i < ACH; i++) {
                int off = aprow[i] * (LDA * 2) + apk[i] * 2;
                *(uint4*)(sA0 + off) = ra0[i];
                if (NT > 1) *(uint4*)(sA1 + off) = ra1[i];
            }
        }
#pragma unroll
        for (int i = 0; i < BCH; i++) {
            int off = brow[i] * (LDB * 2) + bk[i] * 2;
            *(uint4*)(sB0 + off) = rb0[i];
            if (NT > 1) *(uint4*)(sB1 + off) = rb1[i];
        }
    };

    auto mma_tile = [&](int buf) {
        const char* base = sm + buf * STAGE;
        const __half* sA0 = (const __half*)(base);
        const __half* sA1 = (const __half*)(base + APL);
        const __half* sB0 = (const __half*)(base + PL * APL);
        const __half* sB1 = (const __half*)(base + PL * APL + BPL);
#pragma unroll
        for (int ks = 0; ks < 32; ks += 16) {
            wmma::fragment<wmma::matrix_a, 16, 16, 16, __half, wmma::row_major> a0f[2], a1f[2];
#pragma unroll
            for (int mf = 0; mf < 2; mf++) {
                int r0 = wm * 32 + mf * 16;
                wmma::load_matrix_sync(a0f[mf], sA0 + r0 * LDA + ks, LDA);
                if (NT > 1) wmma::load_matrix_sync(a1f[mf], sA1 + r0 * LDA + ks, LDA);
            }
#pragma unroll
            for (int nf = 0; nf < NF; nf++) {
                int col = wn * 64 + nf * 16;
                wmma::fragment<wmma::matrix_b, 16, 16, 16, __half, wmma::col_major> b0f, b1f;
                wmma::load_matrix_sync(b0f, sB0 + col * LDB + ks, LDB);
                if (NT > 1) wmma::load_matrix_sync(b1f, sB1 + col * LDB + ks, LDB);
#pragma unroll
                for (int mf = 0; mf < 2; mf++) {
                    wmma::mma_sync(acc[mf][nf], a0f[mf], b0f, acc[mf][nf]);
                    if (NT > 1) {
                        wmma::mma_sync(acc[mf][nf], a0f[mf], b1f, acc[mf][nf]);
                        wmma::mma_sync(acc[mf][nf], a1f[mf], b0f, acc[mf][nf]);
                    }
                }
            }
        }
    };

    const int numK = Ktot >> 5;
    load_tile(0);
    for (int t = 0; t < numK; t++) {
        store_tile(t & 1);
        __syncthreads();
        if (t + 1 < numK) load_tile((t + 1) << 5);
        mma_tile(t & 1);
    }

    __syncthreads();
    float* Csm = (float*)sm;
#pragma unroll
    for (int mf = 0; mf < 2; mf++)
#pragma unroll
        for (int nf = 0; nf < NF; nf++) {
            int r0 = wm * 32 + mf * 16, c0 = wn * 64 + nf * 16;
            wmma::store_matrix_sync(Csm + r0 * 128 + c0, acc[mf][nf], 128, wmma::mem_row_major);
        }
    __syncthreads();

    const int NOUT = BM * 128 / 4 / 128;   // 16 float4 per thread
#pragma unroll
    for (int i = 0; i < NOUT; i++) {
        int f = tid + i * 128;
        int row = f >> 5, c4 = (f & 31) * 4;
        float4 v = *(float4*)(Csm + row * 128 + c4);
        v.x *= alpha; v.y *= alpha; v.z *= alpha; v.w *= alpha;
        if (bias) {
            v.x += bias[n0 + c4 + 0]; v.y += bias[n0 + c4 + 1];
            v.z += bias[n0 + c4 + 2]; v.w += bias[n0 + c4 + 3];
        }
        long long o = coff + (long long)(m0 + row) * ldc + n0 + c4;
        if (Cf) {
            *(float4*)(Cf + o) = v;
        } else {
            __half x0, x1, y0, y1, z0, z1, w0, w1;
            split2(v.x, x0, x1); split2(v.y, y0, y1);
            split2(v.z, z0, z1); split2(v.w, w0, w1);
            __half2 p0 = __halves2half2(x0, y0), q0 = __halves2half2(z0, w0);
            *(uint2*)(C0g + o) = make_uint2(h2u(p0), h2u(q0));
            if (C1g) {
                __half2 p1 = __halves2half2(x1, y1), q1 = __halves2half2(z1, w1);
                *(uint2*)(C1g + o) = make_uint2(h2u(p1), h2u(q1));
            }
        }
    }
}

// ---------------------------------------------------------------------------
// Fused attention per (b, n) CTA (round-8 version, 256 threads):
//   S[64,256] = Q'@h^T (3-term) -> softmax -> P fp16 -> U[64,512] = P@h (1-term)
// smem (102400):
//   phase1 stage 2x51200 @0 | then Ssm fp32 64x264 @0, Psm0 @67584 (33792)
//   phase3 stage 2x16896 @0 | epilogue Csm fp32 64x264 @0
// ---------------------------------------------------------------------------
#define ATTN_SMEM 102400

__global__ __launch_bounds__(256) void k_attn() {
    extern __shared__ __align__(1024) char sm[];
    const int tid = threadIdx.x;
    const int w = tid >> 5, lane = tid & 31;
    const int wm = w & 1, wn = w >> 1;     // 2 x 4 warp grid, warp tile 32x64
    const int b = blockIdx.x, n = blockIdx.y;

    float* Ssm = (float*)sm;                               // 64 x 264 fp32
    __half* Psm0 = (__half*)(sm + 67584);                  // 64 x 264

    const __half* Qb0 = g_Q0 + ((size_t)n * 8192 + (size_t)b * 64) * 512;
    const __half* Qb1 = g_Q1 + ((size_t)n * 8192 + (size_t)b * 64) * 512;
    const __half* Hb0 = g_h0 + (size_t)b * 256 * 512;
    const __half* Hb1 = g_h1 + (size_t)b * 256 * 512;

    wmma::fragment<wmma::accumulator, 16, 16, 16, float> acc[2][4];
#pragma unroll
    for (int mf = 0; mf < 2; mf++)
#pragma unroll
        for (int nf = 0; nf < 4; nf++) wmma::fill_fragment(acc[mf][nf], 0.0f);

    // ======== phase 1: S = Q' @ h^T  (K=512, 16 chunks of 32, 3-term) =====
    {
        const int arow = tid >> 2, akc = (tid & 3) * 8;
        uint4 ra0, ra1, rb0[4], rb1[4];
        auto p1_load = [&](int k0) {
            ra0 = *(const uint4*)(Qb0 + (size_t)arow * 512 + k0 + akc);
            ra1 = *(const uint4*)(Qb1 + (size_t)arow * 512 + k0 + akc);
#pragma unroll
            for (int i = 0; i < 4; i++) {
                int id = tid + i * 256;
                int br = id >> 2, bkc = (id & 3) * 8;
                rb0[i] = *(const uint4*)(Hb0 + (size_t)br * 512 + k0 + bkc);
                rb1[i] = *(const uint4*)(Hb1 + (size_t)br * 512 + k0 + bkc);
            }
        };
        auto p1_store = [&](int buf) {
            char* base = sm + buf * 51200;
            __half* sA0 = (__half*)base;
            __half* sA1 = (__half*)(base + 5120);
            __half* sB0 = (__half*)(base + 10240);
            __half* sB1 = (__half*)(base + 30720);
            *(uint4*)(sA0 + arow * 40 + akc) = ra0;
            *(uint4*)(sA1 + arow * 40 + akc) = ra1;
#pragma unroll
            for (int i = 0; i < 4; i++) {
                int id = tid + i * 256;
                int br = id >> 2, bkc = (id & 3) * 8;
                *(uint4*)(sB0 + br * 40 + bkc) = rb0[i];
                *(uint4*)(sB1 + br * 40 + bkc) = rb1[i];
            }
        };
        auto p1_mma = [&](int buf) {
            const char* base = sm + buf * 51200;
            const __half* sA0 = (const __half*)base;
            const __half* sA1 = (const __half*)(base + 5120);
            const __half* sB0 = (const __half*)(base + 10240);
            const __half* sB1 = (const __half*)(base + 30720);
#pragma unroll
            for (int ks = 0; ks < 32; ks += 16) {
                wmma::fragment<wmma::matrix_a, 16, 16, 16, __half, wmma::row_major> a0f[2], a1f[2];
#pragma unroll
                for (int mf = 0; mf < 2; mf++) {
                    int r0 = wm * 32 + mf * 16;
                    wmma::load_matrix_sync(a0f[mf], sA0 + r0 * 40 + ks, 40);
                    wmma::load_matrix_sync(a1f[mf], sA1 + r0 * 40 + ks, 40);
                }
#pragma unroll
                for (int nf = 0; nf < 4; nf++) {
                    int col = wn * 64 + nf * 16;
                    wmma::fragment<wmma::matrix_b, 16, 16, 16, __half, wmma::col_major> b0f, b1f;
                    wmma::load_matrix_sync(b0f, sB0 + col * 40 + ks, 40);
                    wmma::load_matrix_sync(b1f, sB1 + col * 40 + ks, 40);
#pragma unroll
                    for (int mf = 0; mf < 2; mf++) {
                        wmma::mma_sync(acc[mf][nf], a0f[mf], b0f, acc[mf][nf]);
                        wmma::mma_sync(acc[mf][nf], a0f[mf], b1f, acc[mf][nf]);
                        wmma::mma_sync(acc[mf][nf], a1f[mf], b0f, acc[mf][nf]);
                    }
                }
            }
        };
        p1_load(0);
        for (int t = 0; t < 16; t++) {
            p1_store(t & 1);
            __syncthreads();
            if (t + 1 < 16) p1_load((t + 1) << 5);
            p1_mma(t & 1);
        }
    }

    // ======== stage S -> smem fp32 ========
    __syncthreads();
#pragma unroll
    for (int mf = 0; mf < 2; mf++)
#pragma unroll
        for (int nf = 0; nf < 4; nf++) {
            int r0 = wm * 32 + mf * 16, c0 = wn * 64 + nf * 16;
            wmma::store_matrix_sync(Ssm + r0 * 264 + c0, acc[mf][nf], 264, wmma::mem_row_major);
        }
    __syncthreads();

    // ======== softmax: warp w owns rows w*8 .. w*8+7; P fp16 single plane ==
#pragma unroll
    for (int i = 0; i < 8; i++) {
        int r = w * 8 + i;
        float* srow = Ssm + (size_t)r * 264 + lane * 8;
        float4 v0 = *(float4*)srow;
        float4 v1 = *(float4*)(srow + 4);
        float m = fmaxf(fmaxf(fmaxf(v0.x, v0.y), fmaxf(v0.z, v0.w)),
                        fmaxf(fmaxf(v1.x, v1.y), fmaxf(v1.z, v1.w)));
#pragma unroll
        for (int off = 16; off > 0; off >>= 1)
            m = fmaxf(m, __shfl_xor_sync(0xffffffffu, m, off));
        v0.x = __expf(v0.x - m); v0.y = __expf(v0.y - m);
        v0.z = __expf(v0.z - m); v0.w = __expf(v0.w - m);
        v1.x = __expf(v1.x - m); v1.y = __expf(v1.y - m);
        v1.z = __expf(v1.z - m); v1.w = __expf(v1.w - m);
        float s = v0.x + v0.y + v0.z + v0.w + v1.x + v1.y + v1.z + v1.w;
#pragma unroll
        for (int off = 16; off > 0; off >>= 1)
            s += __shfl_xor_sync(0xffffffffu, s, off);
        const float inv = 1.0f / s;
        __align__(16) __half h0[8];
        h0[0] = __float2half_rn(v0.x * inv); h0[1] = __float2half_rn(v0.y * inv);
        h0[2] = __float2half_rn(v0.z * inv); h0[3] = __float2half_rn(v0.w * inv);
        h0[4] = __float2half_rn(v1.x * inv); h0[5] = __float2half_rn(v1.y * inv);
        h0[6] = __float2half_rn(v1.z * inv); h0[7] = __float2half_rn(v1.w * inv);
        *(uint4*)(Psm0 + (size_t)r * 264 + lane * 8) = *(uint4*)h0;
    }
    __syncthreads();

    // ======== phase 3: U = P @ h  (1-term; two 256-col halves; K=256) =====
    for (int hh = 0; hh < 2; hh++) {
        const int d0 = hh * 256;
#pragma unroll
        for (int mf = 0; mf < 2; mf++)
#pragma unroll
            for (int nf = 0; nf < 4; nf++) wmma::fill_fragment(acc[mf][nf], 0.0f);

        uint4 rh0[4];
        auto p3_load = [&](int k0) {
#pragma unroll
            for (int i = 0; i < 4; i++) {
                int id = tid + i * 256;
                int er = id >> 5, dc = id & 31;
                rh0[i] = *(const uint4*)(Hb0 + (size_t)(k0 + er) * 512 + d0 + dc * 8);
            }
        };
        auto p3_store = [&](int buf) {
            __half* sH0 = (__half*)(sm + buf * 16896);
#pragma unroll
            for (int i = 0; i < 4; i++) {
                int id = tid + i * 256;
                int er = id >> 5, dc = id & 31;
                *(uint4*)(sH0 + er * 264 + dc * 8) = rh0[i];
            }
        };
        auto p3_mma = [&](int buf, int c) {
            const __half* sH0 = (const __half*)(sm + buf * 16896);
#pragma unroll
            for (int ks = 0; ks < 32; ks += 16) {
                wmma::fragment<wmma::matrix_a, 16, 16, 16, __half, wmma::row_major> a0f[2];
#pragma unroll
                for (int mf = 0; mf < 2; mf++) {
                    int r0 = wm * 32 + mf * 16;
                    wmma::load_matrix_sync(a0f[mf], Psm0 + r0 * 264 + c * 32 + ks, 264);
                }
#pragma unroll
                for (int nf = 0; nf < 4; nf++) {
                    int col = wn * 64 + nf * 16;
                    wmma::fragment<wmma::matrix_b, 16, 16, 16, __half, wmma::row_major> b0f;
                    wmma::load_matrix_sync(b0f, sH0 + ks * 264 + col, 264);
#pragma unroll
                    for (int mf = 0; mf < 2; mf++)
                        wmma::mma_sync(acc[mf][nf], a0f[mf], b0f, acc[mf][nf]);
                }
            }
        };
        p3_load(0);
        for (int c = 0; c < 8; c++) {
            p3_store(c & 1);
            __syncthreads();
            if (c + 1 < 8) p3_load((c + 1) << 5);
            p3_mma(c & 1, c);
        }

        __syncthreads();
        float* Csm = (float*)sm;
#pragma unroll
        for (int mf = 0; mf < 2; mf++)
#pragma unroll
            for (int nf = 0; nf < 4; nf++) {
                int r0 = wm * 32 + mf * 16, c0 = wn * 64 + nf * 16;
                wmma::store_matrix_sync(Csm + r0 * 264 + c0, acc[mf][nf], 264, wmma::mem_row_major);
            }
        __syncthreads();
#pragma unroll
        for (int i = 0; i < 16; i++) {
            int id = tid + i * 256;
            int row = id >> 6, c4 = (id & 63) * 4;
            float4 v = *(float4*)(Csm + row * 264 + c4);
            __align__(8) __half h4[4];
            h4[0] = __float2half_rn(v.x); h4[1] = __float2half_rn(v.y);
            h4[2] = __float2half_rn(v.z); h4[3] = __float2half_rn(v.w);
            size_t o = (((size_t)(b * 64 + row)) * 8 + n) * 512 + d0 + c4;
            *(uint2*)(g_U0 + o) = *(uint2*)h4;
        }
        __syncthreads();
    }
}

// ---------------------------------------------------------------------------
extern "C" void kernel_launch(void* const* d_in, const int* in_sizes, int n_in,
                              void* d_out, int out_size) {
    const float* x     = (const float*)d_in[0];
    const float* W_enc = (const float*)d_in[1];
    const float* b_enc = (const float*)d_in[2];
    const float* WQ    = (const float*)d_in[3];
    const float* WK    = (const float*)d_in[4];
    const float* WV    = (const float*)d_in[5];
    float* out = (float*)d_out;

    const int SM64_3 = 2 * 2 * (64 * 40 * 2 + 128 * 40 * 2);   // 61440
    const int SM64_1 = 64 * 128 * 4;                            // 32768 (epilogue floor)
    cudaFuncSetAttribute(k_mma<3>, cudaFuncAttributeMaxDynamicSharedMemorySize, SM64_3);
    cudaFuncSetAttribute(k_mma<1>, cudaFuncAttributeMaxDynamicSharedMemorySize, SM64_1);
    cudaFuncSetAttribute(k_attn, cudaFuncAttributeMaxDynamicSharedMemorySize, ATTN_SMEM);

    void *p_M, *p_h0, *p_h1, *p_Q0, *p_Q1, *p_U0;
    void *p_e0, *p_e1, *p_m0, *p_m1, *p_w0, *p_w1, *p_k0, *p_k1;
    cudaGetSymbolAddress(&p_M, g_M);
    cudaGetSymbolAddress(&p_h0, g_h0); cudaGetSymbolAddress(&p_h1, g_h1);
    cudaGetSymbolAddress(&p_Q0, g_Q0); cudaGetSymbolAddress(&p_Q1, g_Q1);
    cudaGetSymbolAddress(&p_U0, g_U0);
    cudaGetSymbolAddress(&p_e0, g_Te0); cudaGetSymbolAddress(&p_e1, g_Te1);
    cudaGetSymbolAddress(&p_m0, g_Tm0); cudaGetSymbolAddress(&p_m1, g_Tm1);
    cudaGetSymbolAddress(&p_w0, g_Tw0); cudaGetSymbolAddress(&p_w1, g_Tw1);
    cudaGetSymbolAddress(&p_k0, g_Wk0); cudaGetSymbolAddress(&p_k1, g_Wk1);

    // ---- weight prep
    k_tsplit2<<<dim3(8, 16, 1), dim3(32, 8)>>>(W_enc, (__half*)p_e0, (__half*)p_e1, 256, 512);
    k_tsplit2<<<dim3(128, 16, 1), dim3(32, 8)>>>(WV, (__half*)p_w0, (__half*)p_w1, 4096, 512);
    k_split2e<<<dim3(512), 256>>>(WK, (__half*)p_k0, (__half*)p_k1, (size_t)8 * 512 * 512);

    // ---- M_n = (WQ_n @ WK_n^T) * scale   (WMMA 3-term; WK is already [N,K])
    k_mma<3><<<dim3(4, 8, 8), 128, SM64_3>>>(
        WQ, nullptr, nullptr, (const __half*)p_k0, (const __half*)p_k1,
        (float*)p_M, nullptr, nullptr, nullptr, 0.04419417382415922f,
        512, 512, 512, 512, /*flags*/0,
        (long long)512 * 512, (long long)512 * 512, (long long)512 * 512);

    k_tsplit2<<<dim3(16, 16, 8), dim3(32, 8)>>>((const float*)p_M, (__half*)p_m0, (__half*)p_m1, 512, 512);

    // ---- encode: h planes = lrelu(x) @ W_enc + b
    k_mma<3><<<dim3(4, 512, 1), 128, SM64_3>>>(
        x, nullptr, nullptr, (const __half*)p_e0, (const __half*)p_e1,
        nullptr, (__half*)p_h0, (__half*)p_h1, b_enc, 1.0f,
        256, 256, 256, 512, /*flags*/1, 0, 0, 0);

    // ---- Q' planes = ha @ M_n   (gather, batched over heads)
    k_mma<3><<<dim3(4, 128, 8), 128, SM64_3>>>(
        nullptr, (const __half*)p_h0, (const __half*)p_h1,
        (const __half*)p_m0, (const __half*)p_m1,
        nullptr, (__half*)p_Q0, (__half*)p_Q1, nullptr, 1.0f,
        512, 512, 512, 512, /*flags*/2,
        0, (long long)512 * 512, (long long)8192 * 512);

    // ---- fused attention (S 3-term -> softmax -> U 1-term fp16)
    k_attn<<<dim3(128, 8), 256, ATTN_SMEM>>>();

    // ---- out = (1/8) U @ WVcat   (1-term fp16)
    k_mma<1><<<dim3(4, 128, 1), 128, SM64_1>>>(
        nullptr, (const __half*)p_U0, nullptr,
        (const __half*)p_w0, nullptr,
        out, nullptr, nullptr, nullptr, 0.125f,
        4096, 4096, 4096, 512, 0, 0, 0, 0);
}

// round 11
// speedup vs baseline: 1.3491x; 1.1734x over previous
#include <cuda_runtime.h>
#include <cuda_fp16.h>
#include <mma.h>
#include <cstdint>
#include <string.h>
#include <math.h>
#include <type_traits>

using namespace nvcuda;

// ===========================================================================
//  M_n = (WQ_n @ WK_n^T)/sqrt(512)    [8,512,512]  WMMA 3-term (WK no transp)
//  E_n = W_enc @ M_n                  [8,256,512]  WMMA 3-term fp32 (tiny)
//  bv_n = b_enc @ M_n                 [8,512]      FFMA GEMV (tiny)
//  h   = lrelu(x) @ W_enc + b         [32768,512]  WMMA 3-term split planes
//  Q'  = lrelu(x_a) @ E_n + bv_n      [8,8192,512] WMMA 3-term, K=256 (!)
//  attn fused: S=Q'@h^T (3-term) -> softmax -> U=P@h (1-term fp16)
//  out = (1/8) U @ WVcat              [8192,512]   WMMA 1-term fp16
// Fusion Q' = lrelu(x_a)@ (W_enc@M_n) halves qprime's K (512->256),
// removing ~190us of the former biggest kernel.
// ===========================================================================

// -------------------- scratch (device globals) -----------------------------
static __device__ float  g_M [8u * 512u * 512u];
static __device__ float  g_E [8u * 256u * 512u];
static __device__ float  g_bv[8u * 512u];
static __device__ __half g_h0[32768u * 512u],  g_h1[32768u * 512u];
static __device__ __half g_Q0[8u * 8192u * 512u], g_Q1[8u * 8192u * 512u];
static __device__ __half g_U0[8192u * 4096u];
static __device__ __half g_Te0[512u * 256u],  g_Te1[512u * 256u];          // W_enc^T
static __device__ __half g_Tm0[8u * 512u * 512u], g_Tm1[8u * 512u * 512u]; // M^T
static __device__ __half g_TE0[8u * 512u * 256u], g_TE1[8u * 512u * 256u]; // E^T
static __device__ __half g_Tw0[512u * 4096u], g_Tw1[512u * 4096u];         // WVcat^T
static __device__ __half g_Wk0[8u * 512u * 512u], g_Wk1[8u * 512u * 512u]; // WK split

__device__ __forceinline__ float lrelu(float v) { return v > 0.0f ? v : 0.01f * v; }

__device__ __forceinline__ void split2(float v, __half& h0, __half& h1) {
    h0 = __float2half_rn(v);
    h1 = __float2half_rn(v - __half2float(h0));
}

__device__ __forceinline__ uint32_t h2u(__half2 v) {
    uint32_t u;
    memcpy(&u, &v, 4);
    return u;
}

// ---------------------------------------------------------------------------
// elementwise fp16 split2
// ---------------------------------------------------------------------------
__global__ __launch_bounds__(256) void k_split2e(const float* __restrict__ B,
                                                 __half* __restrict__ T0,
                                                 __half* __restrict__ T1,
                                                 size_t total) {
    for (size_t i = (size_t)blockIdx.x * 256 + threadIdx.x; i < total;
         i += (size_t)gridDim.x * 256) {
        split2(B[i], T0[i], T1[i]);
    }
}

// ---------------------------------------------------------------------------
// tiled transpose + fp16 split2:  T*[n*K+k] = split(B[k*N+n])
// grid (K/32, N/32, batch), block (32,8)
// ---------------------------------------------------------------------------
__global__ __launch_bounds__(256) void k_tsplit2(const float* __restrict__ B,
                                                 __half* __restrict__ T0,
                                                 __half* __restrict__ T1,
                                                 int K, int N) {
    __shared__ __half s0[32][33];
    __shared__ __half s1[32][33];
    const size_t base = (size_t)blockIdx.z * (size_t)K * N;
    const int k0 = blockIdx.x * 32, n0 = blockIdx.y * 32;
    const int tx = threadIdx.x, ty = threadIdx.y;
#pragma unroll
    for (int i = 0; i < 4; i++) {
        int row = ty * 4 + i;
        float v = B[base + (size_t)(k0 + row) * N + n0 + tx];
        split2(v, s0[row][tx], s1[row][tx]);
    }
    __syncthreads();
#pragma unroll
    for (int i = 0; i < 4; i++) {
        int nrow = ty * 4 + i;
        size_t o = base + (size_t)(n0 + nrow) * K + k0 + tx;
        T0[o] = s0[tx][nrow];
        T1[o] = s1[tx][nrow];
    }
}

// ---------------------------------------------------------------------------
// bv_n = b_enc @ M_n : [8,512].  grid(8), block(512).  Coalesced over j.
// ---------------------------------------------------------------------------
__global__ __launch_bounds__(512) void k_bv(const float* __restrict__ b_enc) {
    const int n = blockIdx.x, j = threadIdx.x;
    const float* Mn = g_M + (size_t)n * 512 * 512;
    float s = 0.0f;
    for (int k = 0; k < 512; k++) s += b_enc[k] * Mn[(size_t)k * 512 + j];
    g_bv[n * 512 + j] = s;
}

// ---------------------------------------------------------------------------
// Generic WMMA GEMM (round-8 proven config: 256 thr, tile 128x128).
// NT=3: split-pair 3-product.  NT=1: plain fp16 single product.
// Epilogue stages C fp32 through smem: needs >= 128*128*4 bytes dyn smem.
// bias is batched via biasHi (elements per z).
// ---------------------------------------------------------------------------
template <int BM, int NT>
__global__ __launch_bounds__(256) void k_mma(
    const float* __restrict__ Afp,
    const __half* __restrict__ A0g, const __half* __restrict__ A1g,
    const __half* __restrict__ B0g, const __half* __restrict__ B1g,
    float* __restrict__ Cf, __half* __restrict__ C0g, __half* __restrict__ C1g,
    const float* __restrict__ bias, long long biasHi, float alpha,
    int Ktot, int lda, int ldb, int ldc,
    int flags,  // 1 = lrelu on fp32 A, 2 = gather rows (b*256+a map)
    long long aHi, long long bHi, long long cHi)
{
    constexpr int WMG = 4;
    constexpr int WN  = 64;
    constexpr int NF  = 4;
    constexpr int LDA = 40;
    constexpr int LDB = 40;
    constexpr int PL  = (NT > 1) ? 2 : 1;
    constexpr int APL = BM * LDA * 2;
    constexpr int BPL = 128 * LDB * 2;
    constexpr int STAGE = PL * (APL + BPL);
    constexpr int ACH = BM * 4 / 256;
    constexpr int AF4 = BM * 8 / 256;

    extern __shared__ __align__(1024) char sm[];

    const int tid = threadIdx.x;
    const int w = tid >> 5;
    const int wm = w & (WMG - 1);
    const int wn = w / WMG;
    const long long aoff = (long long)blockIdx.z * aHi;
    const long long boff = (long long)blockIdx.z * bHi;
    const long long coff = (long long)blockIdx.z * cHi;
    const float* biasz = bias ? (bias + (long long)blockIdx.z * biasHi) : (const float*)0;
    const int m0 = blockIdx.y * BM;
    const int n0 = blockIdx.x * 128;
    const bool a_fp32 = (Afp != nullptr);
    const bool gather = (flags & 2) != 0;
    const bool do_lrelu = (flags & 1) != 0;

    int aprow[ACH], apk[ACH];
    int afrow[AF4], afk[AF4];
#pragma unroll
    for (int i = 0; i < ACH; i++) {
        int id = tid + i * 256;
        aprow[i] = id >> 2;
        apk[i] = (id & 3) * 8;
    }
#pragma unroll
    for (int i = 0; i < AF4; i++) {
        int id = tid + i * 256;
        afrow[i] = id >> 3;
        afk[i] = (id & 7) * 4;
    }
    int brow[2], bk[2];
#pragma unroll
    for (int i = 0; i < 2; i++) {
        int id = tid + i * 256;
        brow[i] = id >> 2;
        bk[i] = (id & 3) * 8;
    }

    auto a_grow = [&](int r) -> long long {
        int g = m0 + r;
        return gather ? (long long)(((g >> 6) << 8) + (g & 63)) : (long long)g;
    };

    wmma::fragment<wmma::accumulator, 16, 16, 16, float> acc[2][NF];
#pragma unroll
    for (int mf = 0; mf < 2; mf++)
#pragma unroll
        for (int nf = 0; nf < NF; nf++) wmma::fill_fragment(acc[mf][nf], 0.0f);

    uint4 ra0[ACH], ra1[ACH];
    float4 rf[AF4];
    uint4 rb0[2], rb1[2];

    auto load_tile = [&](int k0) {
        if (a_fp32) {
#pragma unroll
            for (int i = 0; i < AF4; i++)
                rf[i] = *(const float4*)(Afp + aoff + a_grow(afrow[i]) * lda + k0 + afk[i]);
        } else {
#pragma unroll
            for (int i = 0; i < ACH; i++) {
                long long r = aoff + a_grow(aprow[i]) * lda + k0 + apk[i];
                ra0[i] = *(const uint4*)(A0g + r);
                if (NT > 1) ra1[i] = *(const uint4*)(A1g + r);
            }
        }
#pragma unroll
        for (int i = 0; i < 2; i++) {
            long long r = boff + (long long)(n0 + brow[i]) * ldb + k0 + bk[i];
            rb0[i] = *(const uint4*)(B0g + r);
            if (NT > 1) rb1[i] = *(const uint4*)(B1g + r);
        }
    };

    auto store_tile = [&](int buf) {
        char* base = sm + buf * STAGE;
        char* sA0 = base;
        char* sA1 = base + APL;
        char* sB0 = base + PL * APL;
        char* sB1 = base + PL * APL + BPL;
        if (a_fp32) {
#pragma unroll
            for (int i = 0; i < AF4; i++) {
                float4 v = rf[i];
                if (do_lrelu) { v.x = lrelu(v.x); v.y = lrelu(v.y); v.z = lrelu(v.z); v.w = lrelu(v.w); }
                __half x0, x1, y0, y1, z0, z1, w0, w1;
                split2(v.x, x0, x1); split2(v.y, y0, y1);
                split2(v.z, z0, z1); split2(v.w, w0, w1);
                int off = afrow[i] * (LDA * 2) + afk[i] * 2;
                __half2 p0 = __halves2half2(x0, y0), q0 = __halves2half2(z0, w0);
                *(uint2*)(sA0 + off) = make_uint2(h2u(p0), h2u(q0));
                if (NT > 1) {
                    __half2 p1 = __halves2half2(x1, y1), q1 = __halves2half2(z1, w1);
                    *(uint2*)(sA1 + off) = make_uint2(h2u(p1), h2u(q1));
                }
            }
        } else {
#pragma unroll
            for (int i = 0; i < ACH; i++) {
                int off = aprow[i] * (LDA * 2) + apk[i] * 2;
                *(uint4*)(sA0 + off) = ra0[i];
                if (NT > 1) *(uint4*)(sA1 + off) = ra1[i];
            }
        }
#pragma unroll
        for (int i = 0; i < 2; i++) {
            int off = brow[i] * (LDB * 2) + bk[i] * 2;
            *(uint4*)(sB0 + off) = rb0[i];
            if (NT > 1) *(uint4*)(sB1 + off) = rb1[i];
        }
    };

    auto mma_tile = [&](int buf) {
        const char* base = sm + buf * STAGE;
        const __half* sA0 = (const __half*)(base);
        const __half* sA1 = (const __half*)(base + APL);
        const __half* sB0 = (const __half*)(base + PL * APL);
        const __half* sB1 = (const __half*)(base + PL * APL + BPL);
#pragma unroll
        for (int ks = 0; ks < 32; ks += 16) {
            wmma::fragment<wmma::matrix_a, 16, 16, 16, __half, wmma::row_major> a0f[2], a1f[2];
#pragma unroll
            for (int mf = 0; mf < 2; mf++) {
                int r0 = wm * 32 + mf * 16;
                wmma::load_matrix_sync(a0f[mf], sA0 + r0 * LDA + ks, LDA);
                if (NT > 1) wmma::load_matrix_sync(a1f[mf], sA1 + r0 * LDA + ks, LDA);
            }
#pragma unroll
            for (int nf = 0; nf < NF; nf++) {
                int col = wn * WN + nf * 16;
                wmma::fragment<wmma::matrix_b, 16, 16, 16, __half, wmma::col_major> b0f, b1f;
                wmma::load_matrix_sync(b0f, sB0 + col * LDB + ks, LDB);
                if (NT > 1) wmma::load_matrix_sync(b1f, sB1 + col * LDB + ks, LDB);
#pragma unroll
                for (int mf = 0; mf < 2; mf++) {
                    wmma::mma_sync(acc[mf][nf], a0f[mf], b0f, acc[mf][nf]);
                    if (NT > 1) {
                        wmma::mma_sync(acc[mf][nf], a0f[mf], b1f, acc[mf][nf]);
                        wmma::mma_sync(acc[mf][nf], a1f[mf], b0f, acc[mf][nf]);
                    }
                }
            }
        }
    };

    const int numK = Ktot >> 5;
    load_tile(0);
    for (int t = 0; t < numK; t++) {
        store_tile(t & 1);
        __syncthreads();
        if (t + 1 < numK) load_tile((t + 1) << 5);
        mma_tile(t & 1);
    }

    __syncthreads();
    float* Csm = (float*)sm;
#pragma unroll
    for (int mf = 0; mf < 2; mf++)
#pragma unroll
        for (int nf = 0; nf < NF; nf++) {
            int r0 = wm * 32 + mf * 16, c0 = wn * WN + nf * 16;
            wmma::store_matrix_sync(Csm + r0 * 128 + c0, acc[mf][nf], 128, wmma::mem_row_major);
        }
    __syncthreads();

    const int NOUT = BM * 128 / 4 / 256;
#pragma unroll
    for (int i = 0; i < NOUT; i++) {
        int f = tid + i * 256;
        int row = f >> 5, c4 = (f & 31) * 4;
        float4 v = *(float4*)(Csm + row * 128 + c4);
        v.x *= alpha; v.y *= alpha; v.z *= alpha; v.w *= alpha;
        if (biasz) {
            v.x += biasz[n0 + c4 + 0]; v.y += biasz[n0 + c4 + 1];
            v.z += biasz[n0 + c4 + 2]; v.w += biasz[n0 + c4 + 3];
        }
        long long o = coff + (long long)(m0 + row) * ldc + n0 + c4;
        if (Cf) {
            *(float4*)(Cf + o) = v;
        } else {
            __half x0, x1, y0, y1, z0, z1, w0, w1;
            split2(v.x, x0, x1); split2(v.y, y0, y1);
            split2(v.z, z0, z1); split2(v.w, w0, w1);
            __half2 p0 = __halves2half2(x0, y0), q0 = __halves2half2(z0, w0);
            *(uint2*)(C0g + o) = make_uint2(h2u(p0), h2u(q0));
            if (C1g) {
                __half2 p1 = __halves2half2(x1, y1), q1 = __halves2half2(z1, w1);
                *(uint2*)(C1g + o) = make_uint2(h2u(p1), h2u(q1));
            }
        }
    }
}

// ---------------------------------------------------------------------------
// Fused attention per (b, n) CTA (round-8 version, 256 threads):
//   S[64,256] = Q'@h^T (3-term) -> softmax -> P fp16 -> U[64,512] = P@h (1-term)
// ---------------------------------------------------------------------------
#define ATTN_SMEM 102400

__global__ __launch_bounds__(256) void k_attn() {
    extern __shared__ __align__(1024) char sm[];
    const int tid = threadIdx.x;
    const int w = tid >> 5, lane = tid & 31;
    const int wm = w & 1, wn = w >> 1;
    const int b = blockIdx.x, n = blockIdx.y;

    float* Ssm = (float*)sm;
    __half* Psm0 = (__half*)(sm + 67584);

    const __half* Qb0 = g_Q0 + ((size_t)n * 8192 + (size_t)b * 64) * 512;
    const __half* Qb1 = g_Q1 + ((size_t)n * 8192 + (size_t)b * 64) * 512;
    const __half* Hb0 = g_h0 + (size_t)b * 256 * 512;
    const __half* Hb1 = g_h1 + (size_t)b * 256 * 512;

    wmma::fragment<wmma::accumulator, 16, 16, 16, float> acc[2][4];
#pragma unroll
    for (int mf = 0; mf < 2; mf++)
#pragma unroll
        for (int nf = 0; nf < 4; nf++) wmma::fill_fragment(acc[mf][nf], 0.0f);

    // ======== phase 1: S = Q' @ h^T ========
    {
        const int arow = tid >> 2, akc = (tid & 3) * 8;
        uint4 ra0, ra1, rb0[4], rb1[4];
        auto p1_load = [&](int k0) {
            ra0 = *(const uint4*)(Qb0 + (size_t)arow * 512 + k0 + akc);
            ra1 = *(const uint4*)(Qb1 + (size_t)arow * 512 + k0 + akc);
#pragma unroll
            for (int i = 0; i < 4; i++) {
                int id = tid + i * 256;
                int br = id >> 2, bkc = (id & 3) * 8;
                rb0[i] = *(const uint4*)(Hb0 + (size_t)br * 512 + k0 + bkc);
                rb1[i] = *(const uint4*)(Hb1 + (size_t)br * 512 + k0 + bkc);
            }
        };
        auto p1_store = [&](int buf) {
            char* base = sm + buf * 51200;
            __half* sA0 = (__half*)base;
            __half* sA1 = (__half*)(base + 5120);
            __half* sB0 = (__half*)(base + 10240);
            __half* sB1 = (__half*)(base + 30720);
            *(uint4*)(sA0 + arow * 40 + akc) = ra0;
            *(uint4*)(sA1 + arow * 40 + akc) = ra1;
#pragma unroll
            for (int i = 0; i < 4; i++) {
                int id = tid + i * 256;
                int br = id >> 2, bkc = (id & 3) * 8;
                *(uint4*)(sB0 + br * 40 + bkc) = rb0[i];
                *(uint4*)(sB1 + br * 40 + bkc) = rb1[i];
            }
        };
        auto p1_mma = [&](int buf) {
            const char* base = sm + buf * 51200;
            const __half* sA0 = (const __half*)base;
            const __half* sA1 = (const __half*)(base + 5120);
            const __half* sB0 = (const __half*)(base + 10240);
            const __half* sB1 = (const __half*)(base + 30720);
#pragma unroll
            for (int ks = 0; ks < 32; ks += 16) {
                wmma::fragment<wmma::matrix_a, 16, 16, 16, __half, wmma::row_major> a0f[2], a1f[2];
#pragma unroll
                for (int mf = 0; mf < 2; mf++) {
                    int r0 = wm * 32 + mf * 16;
                    wmma::load_matrix_sync(a0f[mf], sA0 + r0 * 40 + ks, 40);
                    wmma::load_matrix_sync(a1f[mf], sA1 + r0 * 40 + ks, 40);
                }
#pragma unroll
                for (int nf = 0; nf < 4; nf++) {
                    int col = wn * 64 + nf * 16;
                    wmma::fragment<wmma::matrix_b, 16, 16, 16, __half, wmma::col_major> b0f, b1f;
                    wmma::load_matrix_sync(b0f, sB0 + col * 40 + ks, 40);
                    wmma::load_matrix_sync(b1f, sB1 + col * 40 + ks, 40);
#pragma unroll
                    for (int mf = 0; mf < 2; mf++) {
                        wmma::mma_sync(acc[mf][nf], a0f[mf], b0f, acc[mf][nf]);
                        wmma::mma_sync(acc[mf][nf], a0f[mf], b1f, acc[mf][nf]);
                        wmma::mma_sync(acc[mf][nf], a1f[mf], b0f, acc[mf][nf]);
                    }
                }
            }
        };
        p1_load(0);
        for (int t = 0; t < 16; t++) {
            p1_store(t & 1);
            __syncthreads();
            if (t + 1 < 16) p1_load((t + 1) << 5);
            p1_mma(t & 1);
        }
    }

    // ======== stage S -> smem fp32 ========
    __syncthreads();
#pragma unroll
    for (int mf = 0; mf < 2; mf++)
#pragma unroll
        for (int nf = 0; nf < 4; nf++) {
            int r0 = wm * 32 + mf * 16, c0 = wn * 64 + nf * 16;
            wmma::store_matrix_sync(Ssm + r0 * 264 + c0, acc[mf][nf], 264, wmma::mem_row_major);
        }
    __syncthreads();

    // ======== softmax ========
#pragma unroll
    for (int i = 0; i < 8; i++) {
        int r = w * 8 + i;
        float* srow = Ssm + (size_t)r * 264 + lane * 8;
        float4 v0 = *(float4*)srow;
        float4 v1 = *(float4*)(srow + 4);
        float m = fmaxf(fmaxf(fmaxf(v0.x, v0.y), fmaxf(v0.z, v0.w)),
                        fmaxf(fmaxf(v1.x, v1.y), fmaxf(v1.z, v1.w)));
#pragma unroll
        for (int off = 16; off > 0; off >>= 1)
            m = fmaxf(m, __shfl_xor_sync(0xffffffffu, m, off));
        v0.x = __expf(v0.x - m); v0.y = __expf(v0.y - m);
        v0.z = __expf(v0.z - m); v0.w = __expf(v0.w - m);
        v1.x = __expf(v1.x - m); v1.y = __expf(v1.y - m);
        v1.z = __expf(v1.z - m); v1.w = __expf(v1.w - m);
        float s = v0.x + v0.y + v0.z + v0.w + v1.x + v1.y + v1.z + v1.w;
#pragma unroll
        for (int off = 16; off > 0; off >>= 1)
            s += __shfl_xor_sync(0xffffffffu, s, off);
        const float inv = 1.0f / s;
        __align__(16) __half h0[8];
        h0[0] = __float2half_rn(v0.x * inv); h0[1] = __float2half_rn(v0.y * inv);
        h0[2] = __float2half_rn(v0.z * inv); h0[3] = __float2half_rn(v0.w * inv);
        h0[4] = __float2half_rn(v1.x * inv); h0[5] = __float2half_rn(v1.y * inv);
        h0[6] = __float2half_rn(v1.z * inv); h0[7] = __float2half_rn(v1.w * inv);
        *(uint4*)(Psm0 + (size_t)r * 264 + lane * 8) = *(uint4*)h0;
    }
    __syncthreads();

    // ======== phase 3: U = P @ h  (1-term) ========
    for (int hh = 0; hh < 2; hh++) {
        const int d0 = hh * 256;
#pragma unroll
        for (int mf = 0; mf < 2; mf++)
#pragma unroll
            for (int nf = 0; nf < 4; nf++) wmma::fill_fragment(acc[mf][nf], 0.0f);

        uint4 rh0[4];
        auto p3_load = [&](int k0) {
#pragma unroll
            for (int i = 0; i < 4; i++) {
                int id = tid + i * 256;
                int er = id >> 5, dc = id & 31;
                rh0[i] = *(const uint4*)(Hb0 + (size_t)(k0 + er) * 512 + d0 + dc * 8);
            }
        };
        auto p3_store = [&](int buf) {
            __half* sH0 = (__half*)(sm + buf * 16896);
#pragma unroll
            for (int i = 0; i < 4; i++) {
                int id = tid + i * 256;
                int er = id >> 5, dc = id & 31;
                *(uint4*)(sH0 + er * 264 + dc * 8) = rh0[i];
            }
        };
        auto p3_mma = [&](int buf, int c) {
            const __half* sH0 = (const __half*)(sm + buf * 16896);
#pragma unroll
            for (int ks = 0; ks < 32; ks += 16) {
                wmma::fragment<wmma::matrix_a, 16, 16, 16, __half, wmma::row_major> a0f[2];
#pragma unroll
                for (int mf = 0; mf < 2; mf++) {
                    int r0 = wm * 32 + mf * 16;
                    wmma::load_matrix_sync(a0f[mf], Psm0 + r0 * 264 + c * 32 + ks, 264);
                }
#pragma unroll
                for (int nf = 0; nf < 4; nf++) {
                    int col = wn * 64 + nf * 16;
                    wmma::fragment<wmma::matrix_b, 16, 16, 16, __half, wmma::row_major> b0f;
                    wmma::load_matrix_sync(b0f, sH0 + ks * 264 + col, 264);
#pragma unroll
                    for (int mf = 0; mf < 2; mf++)
                        wmma::mma_sync(acc[mf][nf], a0f[mf], b0f, acc[mf][nf]);
                }
            }
        };
        p3_load(0);
        for (int c = 0; c < 8; c++) {
            p3_store(c & 1);
            __syncthreads();
            if (c + 1 < 8) p3_load((c + 1) << 5);
            p3_mma(c & 1, c);
        }

        __syncthreads();
        float* Csm = (float*)sm;
#pragma unroll
        for (int mf = 0; mf < 2; mf++)
#pragma unroll
            for (int nf = 0; nf < 4; nf++) {
                int r0 = wm * 32 + mf * 16, c0 = wn * 64 + nf * 16;
                wmma::store_matrix_sync(Csm + r0 * 264 + c0, acc[mf][nf], 264, wmma::mem_row_major);
            }
        __syncthreads();
#pragma unroll
        for (int i = 0; i < 16; i++) {
            int id = tid + i * 256;
            int row = id >> 6, c4 = (id & 63) * 4;
            float4 v = *(float4*)(Csm + row * 264 + c4);
            __align__(8) __half h4[4];
            h4[0] = __float2half_rn(v.x); h4[1] = __float2half_rn(v.y);
            h4[2] = __float2half_rn(v.z); h4[3] = __float2half_rn(v.w);
            size_t o = (((size_t)(b * 64 + row)) * 8 + n) * 512 + d0 + c4;
            *(uint2*)(g_U0 + o) = *(uint2*)h4;
        }
        __syncthreads();
    }
}

// ---------------------------------------------------------------------------
extern "C" void kernel_launch(void* const* d_in, const int* in_sizes, int n_in,
                              void* d_out, int out_size) {
    const float* x     = (const float*)d_in[0];
    const float* W_enc = (const float*)d_in[1];
    const float* b_enc = (const float*)d_in[2];
    const float* WQ    = (const float*)d_in[3];
    const float* WK    = (const float*)d_in[4];
    const float* WV    = (const float*)d_in[5];
    float* out = (float*)d_out;

    const int SM128_3 = 2 * 2 * (128 * 40 * 2 + 128 * 40 * 2);   // 81920
    const int SM128_1 = 128 * 128 * 4;                            // 65536
    cudaFuncSetAttribute(k_mma<128, 3>, cudaFuncAttributeMaxDynamicSharedMemorySize, SM128_3);
    cudaFuncSetAttribute(k_mma<128, 1>, cudaFuncAttributeMaxDynamicSharedMemorySize, SM128_1);
    cudaFuncSetAttribute(k_attn, cudaFuncAttributeMaxDynamicSharedMemorySize, ATTN_SMEM);

    void *p_M, *p_E, *p_bv, *p_h0, *p_h1, *p_Q0, *p_Q1, *p_U0;
    void *p_e0, *p_e1, *p_m0, *p_m1, *p_E0, *p_E1, *p_w0, *p_w1, *p_k0, *p_k1;
    cudaGetSymbolAddress(&p_M, g_M);
    cudaGetSymbolAddress(&p_E, g_E);
    cudaGetSymbolAddress(&p_bv, g_bv);
    cudaGetSymbolAddress(&p_h0, g_h0); cudaGetSymbolAddress(&p_h1, g_h1);
    cudaGetSymbolAddress(&p_Q0, g_Q0); cudaGetSymbolAddress(&p_Q1, g_Q1);
    cudaGetSymbolAddress(&p_U0, g_U0);
    cudaGetSymbolAddress(&p_e0, g_Te0); cudaGetSymbolAddress(&p_e1, g_Te1);
    cudaGetSymbolAddress(&p_m0, g_Tm0); cudaGetSymbolAddress(&p_m1, g_Tm1);
    cudaGetSymbolAddress(&p_E0, g_TE0); cudaGetSymbolAddress(&p_E1, g_TE1);
    cudaGetSymbolAddress(&p_w0, g_Tw0); cudaGetSymbolAddress(&p_w1, g_Tw1);
    cudaGetSymbolAddress(&p_k0, g_Wk0); cudaGetSymbolAddress(&p_k1, g_Wk1);

    // ---- weight prep
    k_tsplit2<<<dim3(8, 16, 1), dim3(32, 8)>>>(W_enc, (__half*)p_e0, (__half*)p_e1, 256, 512);
    k_tsplit2<<<dim3(128, 16, 1), dim3(32, 8)>>>(WV, (__half*)p_w0, (__half*)p_w1, 4096, 512);
    k_split2e<<<dim3(512), 256>>>(WK, (__half*)p_k0, (__half*)p_k1, (size_t)8 * 512 * 512);

    // ---- M_n = (WQ_n @ WK_n^T) * scale
    k_mma<128, 3><<<dim3(4, 4, 8), 256, SM128_3>>>(
        WQ, nullptr, nullptr, (const __half*)p_k0, (const __half*)p_k1,
        (float*)p_M, nullptr, nullptr, nullptr, 0, 0.04419417382415922f,
        512, 512, 512, 512, /*flags*/0,
        (long long)512 * 512, (long long)512 * 512, (long long)512 * 512);

    k_tsplit2<<<dim3(16, 16, 8), dim3(32, 8)>>>((const float*)p_M, (__half*)p_m0, (__half*)p_m1, 512, 512);
    k_bv<<<dim3(8), 512>>>(b_enc);

    // ---- E_n = W_enc @ M_n   [8,256,512]  (A not batched: aHi=0)
    k_mma<128, 3><<<dim3(4, 2, 8), 256, SM128_3>>>(
        W_enc, nullptr, nullptr, (const __half*)p_m0, (const __half*)p_m1,
        (float*)p_E, nullptr, nullptr, nullptr, 0, 1.0f,
        512, 512, 512, 512, /*flags*/0,
        0, (long long)512 * 512, (long long)256 * 512);

    k_tsplit2<<<dim3(8, 16, 8), dim3(32, 8)>>>((const float*)p_E, (__half*)p_E0, (__half*)p_E1, 256, 512);

    // ---- encode: h planes = lrelu(x) @ W_enc + b
    k_mma<128, 3><<<dim3(4, 256, 1), 256, SM128_3>>>(
        x, nullptr, nullptr, (const __half*)p_e0, (const __half*)p_e1,
        nullptr, (__half*)p_h0, (__half*)p_h1, b_enc, 0, 1.0f,
        256, 256, 256, 512, /*flags*/1, 0, 0, 0);

    // ---- Q' planes = lrelu(x_a) @ E_n + bv_n   (K=256, gather, batched)
    k_mma<128, 3><<<dim3(4, 64, 8), 256, SM128_3>>>(
        x, nullptr, nullptr, (const __half*)p_E0, (const __half*)p_E1,
        nullptr, (__half*)p_Q0, (__half*)p_Q1, (const float*)p_bv, 512, 1.0f,
        256, 256, 256, 512, /*flags*/3,
        0, (long long)512 * 256, (long long)8192 * 512);

    // ---- fused attention (S 3-term -> softmax -> U 1-term fp16)
    k_attn<<<dim3(128, 8), 256, ATTN_SMEM>>>();

    // ---- out = (1/8) U @ WVcat   (1-term fp16)
    k_mma<128, 1><<<dim3(4, 64, 1), 256, SM128_1>>>(
        nullptr, (const __half*)p_U0, nullptr,
        (const __half*)p_w0, nullptr,
        out, nullptr, nullptr, nullptr, 0, 0.125f,
        4096, 4096, 4096, 512, 0, 0, 0, 0);
}

// round 12
// speedup vs baseline: 1.3700x; 1.0155x over previous
#include <cuda_runtime.h>
#include <cuda_fp16.h>
#include <mma.h>
#include <cstdint>
#include <string.h>
#include <math.h>

using namespace nvcuda;

// ===========================================================================
//  xp  = split2(lrelu(x))              [32768,256]  elementwise prep
//  M_n = (WQ_n @ WK_n^T)/sqrt(512)     [8,512,512]  WMMA 3-term
//  E_n = W_enc @ M_n                   [8,256,512]  WMMA 3-term
//  bv_n = b_enc @ M_n                  [8,512]      FFMA GEMV
//  h   = xp @ W_enc^T planes + b       [32768,512]  WMMA 3-term
//  Q'  = xp_a @ E_n^T planes + bv_n    [8,8192,512] WMMA 3-term, K=256
//  attn fused: S=Q'@h^T (3-term) -> softmax -> U=P@h (1-term fp16)
//  out = (1/8) U @ WVcat               [8192,512]   WMMA 1-term fp16
// This round: ALL mainloop global->smem staging via cp.async (no register
// staging arrays) — regs 178 -> ~120 so 2 CTAs/SM fit naturally.
// ===========================================================================

// -------------------- scratch (device globals) -----------------------------
static __device__ float  g_M [8u * 512u * 512u];
static __device__ float  g_E [8u * 256u * 512u];
static __device__ float  g_bv[8u * 512u];
static __device__ __half g_x0[32768u * 256u], g_x1[32768u * 256u];         // split lrelu(x)
static __device__ __half g_h0[32768u * 512u],  g_h1[32768u * 512u];
static __device__ __half g_Q0[8u * 8192u * 512u], g_Q1[8u * 8192u * 512u];
static __device__ __half g_U0[8192u * 4096u];
static __device__ __half g_Te0[512u * 256u],  g_Te1[512u * 256u];          // W_enc^T
static __device__ __half g_We0[256u * 512u],  g_We1[256u * 512u];          // W_enc (row)
static __device__ __half g_Tm0[8u * 512u * 512u], g_Tm1[8u * 512u * 512u]; // M^T
static __device__ __half g_TE0[8u * 512u * 256u], g_TE1[8u * 512u * 256u]; // E^T
static __device__ __half g_Tw0[512u * 4096u], g_Tw1[512u * 4096u];         // WVcat^T
static __device__ __half g_Wk0[8u * 512u * 512u], g_Wk1[8u * 512u * 512u]; // WK
static __device__ __half g_Wq0[8u * 512u * 512u], g_Wq1[8u * 512u * 512u]; // WQ

__device__ __forceinline__ float lrelu(float v) { return v > 0.0f ? v : 0.01f * v; }

__device__ __forceinline__ void split2(float v, __half& h0, __half& h1) {
    h0 = __float2half_rn(v);
    h1 = __float2half_rn(v - __half2float(h0));
}

__device__ __forceinline__ uint32_t h2u(__half2 v) {
    uint32_t u;
    memcpy(&u, &v, 4);
    return u;
}

// -------------------- cp.async helpers --------------------------------------
__device__ __forceinline__ void cp16(void* sdst, const void* gsrc) {
    uint32_t s = (uint32_t)__cvta_generic_to_shared(sdst);
    asm volatile("cp.async.cg.shared.global [%0], [%1], 16;" :: "r"(s), "l"(gsrc));
}
#define CP_COMMIT() asm volatile("cp.async.commit_group;" ::: "memory")
__device__ __forceinline__ void cp_wait0() { asm volatile("cp.async.wait_group 0;" ::: "memory"); }
__device__ __forceinline__ void cp_wait1() { asm volatile("cp.async.wait_group 1;" ::: "memory"); }

// ---------------------------------------------------------------------------
// xp = split2(lrelu(x)) elementwise, vectorized
// ---------------------------------------------------------------------------
__global__ __launch_bounds__(256) void k_xsplit(const float* __restrict__ X,
                                                __half* __restrict__ T0,
                                                __half* __restrict__ T1,
                                                size_t total4) {
    for (size_t i = (size_t)blockIdx.x * 256 + threadIdx.x; i < total4;
         i += (size_t)gridDim.x * 256) {
        float4 v = ((const float4*)X)[i];
        v.x = lrelu(v.x); v.y = lrelu(v.y); v.z = lrelu(v.z); v.w = lrelu(v.w);
        __align__(8) __half a[4], b[4];
        split2(v.x, a[0], b[0]); split2(v.y, a[1], b[1]);
        split2(v.z, a[2], b[2]); split2(v.w, a[3], b[3]);
        ((uint2*)T0)[i] = *(uint2*)a;
        ((uint2*)T1)[i] = *(uint2*)b;
    }
}

// ---------------------------------------------------------------------------
// elementwise fp16 split2 (no transpose, no lrelu)
// ---------------------------------------------------------------------------
__global__ __launch_bounds__(256) void k_split2e(const float* __restrict__ B,
                                                 __half* __restrict__ T0,
                                                 __half* __restrict__ T1,
                                                 size_t total) {
    for (size_t i = (size_t)blockIdx.x * 256 + threadIdx.x; i < total;
         i += (size_t)gridDim.x * 256) {
        split2(B[i], T0[i], T1[i]);
    }
}

// ---------------------------------------------------------------------------
// tiled transpose + fp16 split2:  T*[n*K+k] = split(B[k*N+n])
// grid (K/32, N/32, batch), block (32,8)
// ---------------------------------------------------------------------------
__global__ __launch_bounds__(256) void k_tsplit2(const float* __restrict__ B,
                                                 __half* __restrict__ T0,
                                                 __half* __restrict__ T1,
                                                 int K, int N) {
    __shared__ __half s0[32][33];
    __shared__ __half s1[32][33];
    const size_t base = (size_t)blockIdx.z * (size_t)K * N;
    const int k0 = blockIdx.x * 32, n0 = blockIdx.y * 32;
    const int tx = threadIdx.x, ty = threadIdx.y;
#pragma unroll
    for (int i = 0; i < 4; i++) {
        int row = ty * 4 + i;
        float v = B[base + (size_t)(k0 + row) * N + n0 + tx];
        split2(v, s0[row][tx], s1[row][tx]);
    }
    __syncthreads();
#pragma unroll
    for (int i = 0; i < 4; i++) {
        int nrow = ty * 4 + i;
        size_t o = base + (size_t)(n0 + nrow) * K + k0 + tx;
        T0[o] = s0[tx][nrow];
        T1[o] = s1[tx][nrow];
    }
}

// ---------------------------------------------------------------------------
// bv_n = b_enc @ M_n : [8,512]
// ---------------------------------------------------------------------------
__global__ __launch_bounds__(512) void k_bv(const float* __restrict__ b_enc) {
    const int n = blockIdx.x, j = threadIdx.x;
    const float* Mn = g_M + (size_t)n * 512 * 512;
    float s = 0.0f;
    for (int k = 0; k < 512; k++) s += b_enc[k] * Mn[(size_t)k * 512 + j];
    g_bv[n * 512 + j] = s;
}

// ---------------------------------------------------------------------------
// WMMA GEMM, 256 thr, tile 128x128, cp.async double-buffered staging.
// All operands are fp16 plane pairs (NT=3) or single plane (NT=1).
// B stored [N,K] (col-major frags).  gather!=0 -> A row map b*256+a.
// Epilogue stages C fp32 through smem (needs >= 65536 B dyn smem).
// ---------------------------------------------------------------------------
template <int NT>
__global__ __launch_bounds__(256) void k_mma(
    const __half* __restrict__ A0g, const __half* __restrict__ A1g,
    const __half* __restrict__ B0g, const __half* __restrict__ B1g,
    float* __restrict__ Cf, __half* __restrict__ C0g, __half* __restrict__ C1g,
    const float* __restrict__ bias, long long biasHi, float alpha,
    int Ktot, int lda, int ldb, int ldc, int gather,
    long long aHi, long long bHi, long long cHi)
{
    constexpr int LDA = 40, LDB = 40;
    constexpr int PL  = (NT > 1) ? 2 : 1;
    constexpr int APL = 128 * LDA * 2;
    constexpr int BPL = 128 * LDB * 2;
    constexpr int STAGE = PL * (APL + BPL);

    extern __shared__ __align__(1024) char sm[];

    const int tid = threadIdx.x;
    const int w = tid >> 5;
    const int wm = w & 3;
    const int wn = w >> 2;
    const long long aoff = (long long)blockIdx.z * aHi;
    const long long boff = (long long)blockIdx.z * bHi;
    const long long coff = (long long)blockIdx.z * cHi;
    const float* biasz = bias ? (bias + (long long)blockIdx.z * biasHi) : (const float*)0;
    const int m0 = blockIdx.y * 128;
    const int n0 = blockIdx.x * 128;

    int crow[2], ck[2];
#pragma unroll
    for (int i = 0; i < 2; i++) {
        int id = tid + i * 256;
        crow[i] = id >> 2;
        ck[i] = (id & 3) * 8;
    }

    auto a_row = [&](int r) -> long long {
        int g = m0 + r;
        return gather ? (long long)(((g >> 6) << 8) + (g & 63)) : (long long)g;
    };

    wmma::fragment<wmma::accumulator, 16, 16, 16, float> acc[2][4];
#pragma unroll
    for (int mf = 0; mf < 2; mf++)
#pragma unroll
        for (int nf = 0; nf < 4; nf++) wmma::fill_fragment(acc[mf][nf], 0.0f);

    auto cp_tile = [&](int k0, int buf) {
        char* base = sm + buf * STAGE;
        __half* sA0 = (__half*)base;
        __half* sA1 = (__half*)(base + APL);
        __half* sB0 = (__half*)(base + PL * APL);
        __half* sB1 = (__half*)(base + PL * APL + BPL);
#pragma unroll
        for (int i = 0; i < 2; i++) {
            long long ga = aoff + a_row(crow[i]) * lda + k0 + ck[i];
            cp16(sA0 + crow[i] * LDA + ck[i], A0g + ga);
            if (NT > 1) cp16(sA1 + crow[i] * LDA + ck[i], A1g + ga);
            long long gb = boff + (long long)(n0 + crow[i]) * ldb + k0 + ck[i];
            cp16(sB0 + crow[i] * LDB + ck[i], B0g + gb);
            if (NT > 1) cp16(sB1 + crow[i] * LDB + ck[i], B1g + gb);
        }
        CP_COMMIT();
    };

    auto mma_tile = [&](int buf) {
        const char* base = sm + buf * STAGE;
        const __half* sA0 = (const __half*)(base);
        const __half* sA1 = (const __half*)(base + APL);
        const __half* sB0 = (const __half*)(base + PL * APL);
        const __half* sB1 = (const __half*)(base + PL * APL + BPL);
#pragma unroll
        for (int ks = 0; ks < 32; ks += 16) {
            wmma::fragment<wmma::matrix_a, 16, 16, 16, __half, wmma::row_major> a0f[2], a1f[2];
#pragma unroll
            for (int mf = 0; mf < 2; mf++) {
                int r0 = wm * 32 + mf * 16;
                wmma::load_matrix_sync(a0f[mf], sA0 + r0 * LDA + ks, LDA);
                if (NT > 1) wmma::load_matrix_sync(a1f[mf], sA1 + r0 * LDA + ks, LDA);
            }
#pragma unroll
            for (int nf = 0; nf < 4; nf++) {
                int col = wn * 64 + nf * 16;
                wmma::fragment<wmma::matrix_b, 16, 16, 16, __half, wmma::col_major> b0f, b1f;
                wmma::load_matrix_sync(b0f, sB0 + col * LDB + ks, LDB);
                if (NT > 1) wmma::load_matrix_sync(b1f, sB1 + col * LDB + ks, LDB);
#pragma unroll
                for (int mf = 0; mf < 2; mf++) {
                    wmma::mma_sync(acc[mf][nf], a0f[mf], b0f, acc[mf][nf]);
                    if (NT > 1) {
                        wmma::mma_sync(acc[mf][nf], a0f[mf], b1f, acc[mf][nf]);
                        wmma::mma_sync(acc[mf][nf], a1f[mf], b0f, acc[mf][nf]);
                    }
                }
            }
        }
    };

    const int numK = Ktot >> 5;
    cp_tile(0, 0);
    for (int t = 0; t < numK; t++) {
        if (t + 1 < numK) {
            cp_tile((t + 1) << 5, (t + 1) & 1);
            cp_wait1();
        } else {
            cp_wait0();
        }
        __syncthreads();
        mma_tile(t & 1);
        __syncthreads();
    }

    float* Csm = (float*)sm;
#pragma unroll
    for (int mf = 0; mf < 2; mf++)
#pragma unroll
        for (int nf = 0; nf < 4; nf++) {
            int r0 = wm * 32 + mf * 16, c0 = wn * 64 + nf * 16;
            wmma::store_matrix_sync(Csm + r0 * 128 + c0, acc[mf][nf], 128, wmma::mem_row_major);
        }
    __syncthreads();

#pragma unroll
    for (int i = 0; i < 16; i++) {
        int f = tid + i * 256;
        int row = f >> 5, c4 = (f & 31) * 4;
        float4 v = *(float4*)(Csm + row * 128 + c4);
        v.x *= alpha; v.y *= alpha; v.z *= alpha; v.w *= alpha;
        if (biasz) {
            v.x += biasz[n0 + c4 + 0]; v.y += biasz[n0 + c4 + 1];
            v.z += biasz[n0 + c4 + 2]; v.w += biasz[n0 + c4 + 3];
        }
        long long o = coff + (long long)(m0 + row) * ldc + n0 + c4;
        if (Cf) {
            *(float4*)(Cf + o) = v;
        } else {
            __half x0, x1, y0, y1, z0, z1, w0, w1;
            split2(v.x, x0, x1); split2(v.y, y0, y1);
            split2(v.z, z0, z1); split2(v.w, w0, w1);
            __half2 p0 = __halves2half2(x0, y0), q0 = __halves2half2(z0, w0);
            *(uint2*)(C0g + o) = make_uint2(h2u(p0), h2u(q0));
            if (C1g) {
                __half2 p1 = __halves2half2(x1, y1), q1 = __halves2half2(z1, w1);
                *(uint2*)(C1g + o) = make_uint2(h2u(p1), h2u(q1));
            }
        }
    }
}

// ---------------------------------------------------------------------------
// Fused attention per (b, n) CTA, cp.async staging:
//   S[64,256] = Q'@h^T (3-term) -> softmax -> P fp16 -> U[64,512] = P@h (1-term)
// smem (102400): phase1 stage 2x51200 | Ssm fp32 64x264 @0, Psm0 @67584
//                phase3 stage 2x16896 @0 | epilogue Csm @0
// ---------------------------------------------------------------------------
#define ATTN_SMEM 102400

__global__ __launch_bounds__(256) void k_attn() {
    extern __shared__ __align__(1024) char sm[];
    const int tid = threadIdx.x;
    const int w = tid >> 5, lane = tid & 31;
    const int wm = w & 1, wn = w >> 1;
    const int b = blockIdx.x, n = blockIdx.y;

    float* Ssm = (float*)sm;
    __half* Psm0 = (__half*)(sm + 67584);

    const __half* Qb0 = g_Q0 + ((size_t)n * 8192 + (size_t)b * 64) * 512;
    const __half* Qb1 = g_Q1 + ((size_t)n * 8192 + (size_t)b * 64) * 512;
    const __half* Hb0 = g_h0 + (size_t)b * 256 * 512;
    const __half* Hb1 = g_h1 + (size_t)b * 256 * 512;

    wmma::fragment<wmma::accumulator, 16, 16, 16, float> acc[2][4];
#pragma unroll
    for (int mf = 0; mf < 2; mf++)
#pragma unroll
        for (int nf = 0; nf < 4; nf++) wmma::fill_fragment(acc[mf][nf], 0.0f);

    // ======== phase 1: S = Q' @ h^T  (K=512, 16 chunks, 3-term) ========
    {
        const int arow = tid >> 2, akc = (tid & 3) * 8;
        auto p1_cp = [&](int k0, int buf) {
            char* base = sm + buf * 51200;
            __half* sA0 = (__half*)base;
            __half* sA1 = (__half*)(base + 5120);
            __half* sB0 = (__half*)(base + 10240);
            __half* sB1 = (__half*)(base + 30720);
            if (tid < 256) {  // 64 rows x 4 chunks = 256
                long long ga = (size_t)arow * 512 + k0 + akc;
                cp16(sA0 + arow * 40 + akc, Qb0 + ga);
                cp16(sA1 + arow * 40 + akc, Qb1 + ga);
            }
#pragma unroll
            for (int i = 0; i < 4; i++) {
                int id = tid + i * 256;
                int br = id >> 2, bkc = (id & 3) * 8;
                long long gb = (size_t)br * 512 + k0 + bkc;
                cp16(sB0 + br * 40 + bkc, Hb0 + gb);
                cp16(sB1 + br * 40 + bkc, Hb1 + gb);
            }
            CP_COMMIT();
        };
        auto p1_mma = [&](int buf) {
            const char* base = sm + buf * 51200;
            const __half* sA0 = (const __half*)base;
            const __half* sA1 = (const __half*)(base + 5120);
            const __half* sB0 = (const __half*)(base + 10240);
            const __half* sB1 = (const __half*)(base + 30720);
#pragma unroll
            for (int ks = 0; ks < 32; ks += 16) {
                wmma::fragment<wmma::matrix_a, 16, 16, 16, __half, wmma::row_major> a0f[2], a1f[2];
#pragma unroll
                for (int mf = 0; mf < 2; mf++) {
                    int r0 = wm * 32 + mf * 16;
                    wmma::load_matrix_sync(a0f[mf], sA0 + r0 * 40 + ks, 40);
                    wmma::load_matrix_sync(a1f[mf], sA1 + r0 * 40 + ks, 40);
                }
#pragma unroll
                for (int nf = 0; nf < 4; nf++) {
                    int col = wn * 64 + nf * 16;
                    wmma::fragment<wmma::matrix_b, 16, 16, 16, __half, wmma::col_major> b0f, b1f;
                    wmma::load_matrix_sync(b0f, sB0 + col * 40 + ks, 40);
                    wmma::load_matrix_sync(b1f, sB1 + col * 40 + ks, 40);
#pragma unroll
                    for (int mf = 0; mf < 2; mf++) {
                        wmma::mma_sync(acc[mf][nf], a0f[mf], b0f, acc[mf][nf]);
                        wmma::mma_sync(acc[mf][nf], a0f[mf], b1f, acc[mf][nf]);
                        wmma::mma_sync(acc[mf][nf], a1f[mf], b0f, acc[mf][nf]);
                    }
                }
            }
        };
        p1_cp(0, 0);
        for (int t = 0; t < 16; t++) {
            if (t + 1 < 16) {
                p1_cp((t + 1) << 5, (t + 1) & 1);
                cp_wait1();
            } else {
                cp_wait0();
            }
            __syncthreads();
            p1_mma(t & 1);
            __syncthreads();
        }
    }

    // ======== stage S -> smem fp32 ========
#pragma unroll
    for (int mf = 0; mf < 2; mf++)
#pragma unroll
        for (int nf = 0; nf < 4; nf++) {
            int r0 = wm * 32 + mf * 16, c0 = wn * 64 + nf * 16;
            wmma::store_matrix_sync(Ssm + r0 * 264 + c0, acc[mf][nf], 264, wmma::mem_row_major);
        }
    __syncthreads();

    // ======== softmax ========
#pragma unroll
    for (int i = 0; i < 8; i++) {
        int r = w * 8 + i;
        float* srow = Ssm + (size_t)r * 264 + lane * 8;
        float4 v0 = *(float4*)srow;
        float4 v1 = *(float4*)(srow + 4);
        float m = fmaxf(fmaxf(fmaxf(v0.x, v0.y), fmaxf(v0.z, v0.w)),
                        fmaxf(fmaxf(v1.x, v1.y), fmaxf(v1.z, v1.w)));
#pragma unroll
        for (int off = 16; off > 0; off >>= 1)
            m = fmaxf(m, __shfl_xor_sync(0xffffffffu, m, off));
        v0.x = __expf(v0.x - m); v0.y = __expf(v0.y - m);
        v0.z = __expf(v0.z - m); v0.w = __expf(v0.w - m);
        v1.x = __expf(v1.x - m); v1.y = __expf(v1.y - m);
        v1.z = __expf(v1.z - m); v1.w = __expf(v1.w - m);
        float s = v0.x + v0.y + v0.z + v0.w + v1.x + v1.y + v1.z + v1.w;
#pragma unroll
        for (int off = 16; off > 0; off >>= 1)
            s += __shfl_xor_sync(0xffffffffu, s, off);
        const float inv = 1.0f / s;
        __align__(16) __half h0[8];
        h0[0] = __float2half_rn(v0.x * inv); h0[1] = __float2half_rn(v0.y * inv);
        h0[2] = __float2half_rn(v0.z * inv); h0[3] = __float2half_rn(v0.w * inv);
        h0[4] = __float2half_rn(v1.x * inv); h0[5] = __float2half_rn(v1.y * inv);
        h0[6] = __float2half_rn(v1.z * inv); h0[7] = __float2half_rn(v1.w * inv);
        *(uint4*)(Psm0 + (size_t)r * 264 + lane * 8) = *(uint4*)h0;
    }
    __syncthreads();

    // ======== phase 3: U = P @ h  (1-term; two 256-col halves; K=256) ====
    for (int hh = 0; hh < 2; hh++) {
        const int d0 = hh * 256;
#pragma unroll
        for (int mf = 0; mf < 2; mf++)
#pragma unroll
            for (int nf = 0; nf < 4; nf++) wmma::fill_fragment(acc[mf][nf], 0.0f);

        auto p3_cp = [&](int k0, int buf) {
            __half* sH0 = (__half*)(sm + buf * 16896);
#pragma unroll
            for (int i = 0; i < 4; i++) {
                int id = tid + i * 256;
                int er = id >> 5, dc = (id & 31) * 8;
                cp16(sH0 + er * 264 + dc, Hb0 + (size_t)(k0 + er) * 512 + d0 + dc);
            }
            CP_COMMIT();
        };
        auto p3_mma = [&](int buf, int c) {
            const __half* sH0 = (const __half*)(sm + buf * 16896);
#pragma unroll
            for (int ks = 0; ks < 32; ks += 16) {
                wmma::fragment<wmma::matrix_a, 16, 16, 16, __half, wmma::row_major> a0f[2];
#pragma unroll
                for (int mf = 0; mf < 2; mf++) {
                    int r0 = wm * 32 + mf * 16;
                    wmma::load_matrix_sync(a0f[mf], Psm0 + r0 * 264 + c * 32 + ks, 264);
                }
#pragma unroll
                for (int nf = 0; nf < 4; nf++) {
                    int col = wn * 64 + nf * 16;
                    wmma::fragment<wmma::matrix_b, 16, 16, 16, __half, wmma::row_major> b0f;
                    wmma::load_matrix_sync(b0f, sH0 + ks * 264 + col, 264);
#pragma unroll
                    for (int mf = 0; mf < 2; mf++)
                        wmma::mma_sync(acc[mf][nf], a0f[mf], b0f, acc[mf][nf]);
                }
            }
        };
        p3_cp(0, 0);
        for (int c = 0; c < 8; c++) {
            if (c + 1 < 8) {
                p3_cp((c + 1) << 5, (c + 1) & 1);
                cp_wait1();
            } else {
                cp_wait0();
            }
            __syncthreads();
            p3_mma(c & 1, c);
            __syncthreads();
        }

        float* Csm = (float*)sm;
#pragma unroll
        for (int mf = 0; mf < 2; mf++)
#pragma unroll
            for (int nf = 0; nf < 4; nf++) {
                int r0 = wm * 32 + mf * 16, c0 = wn * 64 + nf * 16;
                wmma::store_matrix_sync(Csm + r0 * 264 + c0, acc[mf][nf], 264, wmma::mem_row_major);
            }
        __syncthreads();
#pragma unroll
        for (int i = 0; i < 16; i++) {
            int id = tid + i * 256;
            int row = id >> 6, c4 = (id & 63) * 4;
            float4 v = *(float4*)(Csm + row * 264 + c4);
            __align__(8) __half h4[4];
            h4[0] = __float2half_rn(v.x); h4[1] = __float2half_rn(v.y);
            h4[2] = __float2half_rn(v.z); h4[3] = __float2half_rn(v.w);
            size_t o = (((size_t)(b * 64 + row)) * 8 + n) * 512 + d0 + c4;
            *(uint2*)(g_U0 + o) = *(uint2*)h4;
        }
        __syncthreads();
    }
}

// ---------------------------------------------------------------------------
extern "C" void kernel_launch(void* const* d_in, const int* in_sizes, int n_in,
                              void* d_out, int out_size) {
    const float* x     = (const float*)d_in[0];
    const float* W_enc = (const float*)d_in[1];
    const float* b_enc = (const float*)d_in[2];
    const float* WQ    = (const float*)d_in[3];
    const float* WK    = (const float*)d_in[4];
    const float* WV    = (const float*)d_in[5];
    float* out = (float*)d_out;

    const int SM3 = 2 * 2 * (128 * 40 * 2 + 128 * 40 * 2);   // 81920
    const int SM1 = 128 * 128 * 4;                            // 65536 (epilogue floor)
    cudaFuncSetAttribute(k_mma<3>, cudaFuncAttributeMaxDynamicSharedMemorySize, SM3);
    cudaFuncSetAttribute(k_mma<1>, cudaFuncAttributeMaxDynamicSharedMemorySize, SM1);
    cudaFuncSetAttribute(k_attn, cudaFuncAttributeMaxDynamicSharedMemorySize, ATTN_SMEM);

    void *p_M, *p_E, *p_bv, *p_x0, *p_x1, *p_h0, *p_h1, *p_Q0, *p_Q1, *p_U0;
    void *p_e0, *p_e1, *p_we0, *p_we1, *p_m0, *p_m1, *p_E0, *p_E1;
    void *p_w0, *p_w1, *p_k0, *p_k1, *p_q0, *p_q1;
    cudaGetSymbolAddress(&p_M, g_M);
    cudaGetSymbolAddress(&p_E, g_E);
    cudaGetSymbolAddress(&p_bv, g_bv);
    cudaGetSymbolAddress(&p_x0, g_x0); cudaGetSymbolAddress(&p_x1, g_x1);
    cudaGetSymbolAddress(&p_h0, g_h0); cudaGetSymbolAddress(&p_h1, g_h1);
    cudaGetSymbolAddress(&p_Q0, g_Q0); cudaGetSymbolAddress(&p_Q1, g_Q1);
    cudaGetSymbolAddress(&p_U0, g_U0);
    cudaGetSymbolAddress(&p_e0, g_Te0); cudaGetSymbolAddress(&p_e1, g_Te1);
    cudaGetSymbolAddress(&p_we0, g_We0); cudaGetSymbolAddress(&p_we1, g_We1);
    cudaGetSymbolAddress(&p_m0, g_Tm0); cudaGetSymbolAddress(&p_m1, g_Tm1);
    cudaGetSymbolAddress(&p_E0, g_TE0); cudaGetSymbolAddress(&p_E1, g_TE1);
    cudaGetSymbolAddress(&p_w0, g_Tw0); cudaGetSymbolAddress(&p_w1, g_Tw1);
    cudaGetSymbolAddress(&p_k0, g_Wk0); cudaGetSymbolAddress(&p_k1, g_Wk1);
    cudaGetSymbolAddress(&p_q0, g_Wq0); cudaGetSymbolAddress(&p_q1, g_Wq1);

    // ---- prep
    k_xsplit<<<dim3(2048), 256>>>(x, (__half*)p_x0, (__half*)p_x1, (size_t)32768 * 256 / 4);
    k_tsplit2<<<dim3(8, 16, 1), dim3(32, 8)>>>(W_enc, (__half*)p_e0, (__half*)p_e1, 256, 512);
    k_split2e<<<dim3(128), 256>>>(W_enc, (__half*)p_we0, (__half*)p_we1, (size_t)256 * 512);
    k_tsplit2<<<dim3(128, 16, 1), dim3(32, 8)>>>(WV, (__half*)p_w0, (__half*)p_w1, 4096, 512);
    k_split2e<<<dim3(512), 256>>>(WK, (__half*)p_k0, (__half*)p_k1, (size_t)8 * 512 * 512);
    k_split2e<<<dim3(512), 256>>>(WQ, (__half*)p_q0, (__half*)p_q1, (size_t)8 * 512 * 512);

    // ---- M_n = (WQ_n @ WK_n^T) * scale
    k_mma<3><<<dim3(4, 4, 8), 256, SM3>>>(
        (const __half*)p_q0, (const __half*)p_q1,
        (const __half*)p_k0, (const __half*)p_k1,
        (float*)p_M, nullptr, nullptr, nullptr, 0, 0.04419417382415922f,
        512, 512, 512, 512, 0,
        (long long)512 * 512, (long long)512 * 512, (long long)512 * 512);

    k_tsplit2<<<dim3(16, 16, 8), dim3(32, 8)>>>((const float*)p_M, (__half*)p_m0, (__half*)p_m1, 512, 512);
    k_bv<<<dim3(8), 512>>>(b_enc);

    // ---- E_n = W_enc @ M_n  [8,256,512]
    k_mma<3><<<dim3(4, 2, 8), 256, SM3>>>(
        (const __half*)p_we0, (const __half*)p_we1,
        (const __half*)p_m0, (const __half*)p_m1,
        (float*)p_E, nullptr, nullptr, nullptr, 0, 1.0f,
        512, 512, 512, 512, 0,
        0, (long long)512 * 512, (long long)256 * 512);

    k_tsplit2<<<dim3(8, 16, 8), dim3(32, 8)>>>((const float*)p_E, (__half*)p_E0, (__half*)p_E1, 256, 512);

    // ---- encode: h planes = xp @ Te + b
    k_mma<3><<<dim3(4, 256, 1), 256, SM3>>>(
        (const __half*)p_x0, (const __half*)p_x1,
        (const __half*)p_e0, (const __half*)p_e1,
        nullptr, (__half*)p_h0, (__half*)p_h1, b_enc, 0, 1.0f,
        256, 256, 256, 512, 0, 0, 0, 0);

    // ---- Q' planes = xp_a @ TE + bv  (K=256, gather, batched)
    k_mma<3><<<dim3(4, 64, 8), 256, SM3>>>(
        (const __half*)p_x0, (const __half*)p_x1,
        (const __half*)p_E0, (const __half*)p_E1,
        nullptr, (__half*)p_Q0, (__half*)p_Q1, (const float*)p_bv, 512, 1.0f,
        256, 256, 256, 512, 1,
        0, (long long)512 * 256, (long long)8192 * 512);

    // ---- fused attention
    k_attn<<<dim3(128, 8), 256, ATTN_SMEM>>>();

    // ---- out = (1/8) U @ WVcat  (1-term)
    k_mma<1><<<dim3(4, 64, 1), 256, SM1>>>(
        (const __half*)p_U0, nullptr,
        (const __half*)p_w0, nullptr,
        out, nullptr, nullptr, nullptr, 0, 0.125f,
        4096, 4096, 4096, 512, 0, 0, 0, 0);
}

// round 13
// speedup vs baseline: 1.3904x; 1.0149x over previous
#include <cuda_runtime.h>
#include <cuda_fp16.h>
#include <mma.h>
#include <cstdint>
#include <string.h>
#include <math.h>

using namespace nvcuda;

// ===========================================================================
//  xp  = split2(lrelu(x))              [32768,256]  elementwise prep
//  M_n = (WQ_n @ WK_n^T)/sqrt(512)     [8,512,512]  WMMA 3-term
//  E_n = W_enc @ M_n                   [8,256,512]  WMMA 3-term
//  bv_n = b_enc @ M_n                  [8,512]      FFMA GEMV
//  h   = xp @ W_enc^T planes + b       [32768,512]  WMMA 3-term
//  Q'  = xp_a @ E_n^T planes + bv_n    [8,8192,512] WMMA 3-term, K=256
//  attn fused: S=Q'@h^T (3-term) -> softmax -> U=P@h (1-term fp16)
//  out = (1/8) U @ WVcat               [8192,512]   WMMA 1-term fp16
// This round: 3-stage cp.async pipeline with ONE __syncthreads per K-tile
// (was 2) in k_mma and attn phase-3.
// ===========================================================================

// -------------------- scratch (device globals) -----------------------------
static __device__ float  g_M [8u * 512u * 512u];
static __device__ float  g_E [8u * 256u * 512u];
static __device__ float  g_bv[8u * 512u];
static __device__ __half g_x0[32768u * 256u], g_x1[32768u * 256u];
static __device__ __half g_h0[32768u * 512u],  g_h1[32768u * 512u];
static __device__ __half g_Q0[8u * 8192u * 512u], g_Q1[8u * 8192u * 512u];
static __device__ __half g_U0[8192u * 4096u];
static __device__ __half g_Te0[512u * 256u],  g_Te1[512u * 256u];          // W_enc^T
static __device__ __half g_We0[256u * 512u],  g_We1[256u * 512u];          // W_enc (row)
static __device__ __half g_Tm0[8u * 512u * 512u], g_Tm1[8u * 512u * 512u]; // M^T
static __device__ __half g_TE0[8u * 512u * 256u], g_TE1[8u * 512u * 256u]; // E^T
static __device__ __half g_Tw0[512u * 4096u], g_Tw1[512u * 4096u];         // WVcat^T
static __device__ __half g_Wk0[8u * 512u * 512u], g_Wk1[8u * 512u * 512u]; // WK
static __device__ __half g_Wq0[8u * 512u * 512u], g_Wq1[8u * 512u * 512u]; // WQ

__device__ __forceinline__ float lrelu(float v) { return v > 0.0f ? v : 0.01f * v; }

__device__ __forceinline__ void split2(float v, __half& h0, __half& h1) {
    h0 = __float2half_rn(v);
    h1 = __float2half_rn(v - __half2float(h0));
}

__device__ __forceinline__ uint32_t h2u(__half2 v) {
    uint32_t u;
    memcpy(&u, &v, 4);
    return u;
}

// -------------------- cp.async helpers --------------------------------------
__device__ __forceinline__ void cp16(void* sdst, const void* gsrc) {
    uint32_t s = (uint32_t)__cvta_generic_to_shared(sdst);
    asm volatile("cp.async.cg.shared.global [%0], [%1], 16;" :: "r"(s), "l"(gsrc));
}
#define CP_COMMIT() asm volatile("cp.async.commit_group;" ::: "memory")
__device__ __forceinline__ void cp_wait0() { asm volatile("cp.async.wait_group 0;" ::: "memory"); }
__device__ __forceinline__ void cp_wait1() { asm volatile("cp.async.wait_group 1;" ::: "memory"); }

// ---------------------------------------------------------------------------
// xp = split2(lrelu(x)) elementwise, vectorized
// ---------------------------------------------------------------------------
__global__ __launch_bounds__(256) void k_xsplit(const float* __restrict__ X,
                                                __half* __restrict__ T0,
                                                __half* __restrict__ T1,
                                                size_t total4) {
    for (size_t i = (size_t)blockIdx.x * 256 + threadIdx.x; i < total4;
         i += (size_t)gridDim.x * 256) {
        float4 v = ((const float4*)X)[i];
        v.x = lrelu(v.x); v.y = lrelu(v.y); v.z = lrelu(v.z); v.w = lrelu(v.w);
        __align__(8) __half a[4], b[4];
        split2(v.x, a[0], b[0]); split2(v.y, a[1], b[1]);
        split2(v.z, a[2], b[2]); split2(v.w, a[3], b[3]);
        ((uint2*)T0)[i] = *(uint2*)a;
        ((uint2*)T1)[i] = *(uint2*)b;
    }
}

// ---------------------------------------------------------------------------
// elementwise fp16 split2
// ---------------------------------------------------------------------------
__global__ __launch_bounds__(256) void k_split2e(const float* __restrict__ B,
                                                 __half* __restrict__ T0,
                                                 __half* __restrict__ T1,
                                                 size_t total) {
    for (size_t i = (size_t)blockIdx.x * 256 + threadIdx.x; i < total;
         i += (size_t)gridDim.x * 256) {
        split2(B[i], T0[i], T1[i]);
    }
}

// ---------------------------------------------------------------------------
// tiled transpose + fp16 split2:  T*[n*K+k] = split(B[k*N+n])
// ---------------------------------------------------------------------------
__global__ __launch_bounds__(256) void k_tsplit2(const float* __restrict__ B,
                                                 __half* __restrict__ T0,
                                                 __half* __restrict__ T1,
                                                 int K, int N) {
    __shared__ __half s0[32][33];
    __shared__ __half s1[32][33];
    const size_t base = (size_t)blockIdx.z * (size_t)K * N;
    const int k0 = blockIdx.x * 32, n0 = blockIdx.y * 32;
    const int tx = threadIdx.x, ty = threadIdx.y;
#pragma unroll
    for (int i = 0; i < 4; i++) {
        int row = ty * 4 + i;
        float v = B[base + (size_t)(k0 + row) * N + n0 + tx];
        split2(v, s0[row][tx], s1[row][tx]);
    }
    __syncthreads();
#pragma unroll
    for (int i = 0; i < 4; i++) {
        int nrow = ty * 4 + i;
        size_t o = base + (size_t)(n0 + nrow) * K + k0 + tx;
        T0[o] = s0[tx][nrow];
        T1[o] = s1[tx][nrow];
    }
}

// ---------------------------------------------------------------------------
// bv_n = b_enc @ M_n : [8,512]
// ---------------------------------------------------------------------------
__global__ __launch_bounds__(512) void k_bv(const float* __restrict__ b_enc) {
    const int n = blockIdx.x, j = threadIdx.x;
    const float* Mn = g_M + (size_t)n * 512 * 512;
    float s = 0.0f;
    for (int k = 0; k < 512; k++) s += b_enc[k] * Mn[(size_t)k * 512 + j];
    g_bv[n * 512 + j] = s;
}

// ---------------------------------------------------------------------------
// WMMA GEMM, 256 thr, tile 128x128, 3-stage cp.async, single sync per tile.
// ---------------------------------------------------------------------------
template <int NT>
__global__ __launch_bounds__(256) void k_mma(
    const __half* __restrict__ A0g, const __half* __restrict__ A1g,
    const __half* __restrict__ B0g, const __half* __restrict__ B1g,
    float* __restrict__ Cf, __half* __restrict__ C0g, __half* __restrict__ C1g,
    const float* __restrict__ bias, long long biasHi, float alpha,
    int Ktot, int lda, int ldb, int ldc, int gather,
    long long aHi, long long bHi, long long cHi)
{
    constexpr int LDA = 40, LDB = 40;
    constexpr int PL  = (NT > 1) ? 2 : 1;
    constexpr int APL = 128 * LDA * 2;
    constexpr int BPL = 128 * LDB * 2;
    constexpr int STAGE = PL * (APL + BPL);

    extern __shared__ __align__(1024) char sm[];

    const int tid = threadIdx.x;
    const int w = tid >> 5;
    const int wm = w & 3;
    const int wn = w >> 2;
    const long long aoff = (long long)blockIdx.z * aHi;
    const long long boff = (long long)blockIdx.z * bHi;
    const long long coff = (long long)blockIdx.z * cHi;
    const float* biasz = bias ? (bias + (long long)blockIdx.z * biasHi) : (const float*)0;
    const int m0 = blockIdx.y * 128;
    const int n0 = blockIdx.x * 128;

    int crow[2], ck[2];
#pragma unroll
    for (int i = 0; i < 2; i++) {
        int id = tid + i * 256;
        crow[i] = id >> 2;
        ck[i] = (id & 3) * 8;
    }

    auto a_row = [&](int r) -> long long {
        int g = m0 + r;
        return gather ? (long long)(((g >> 6) << 8) + (g & 63)) : (long long)g;
    };

    wmma::fragment<wmma::accumulator, 16, 16, 16, float> acc[2][4];
#pragma unroll
    for (int mf = 0; mf < 2; mf++)
#pragma unroll
        for (int nf = 0; nf < 4; nf++) wmma::fill_fragment(acc[mf][nf], 0.0f);

    auto cp_tile = [&](int k0, int buf) {
        char* base = sm + buf * STAGE;
        __half* sA0 = (__half*)base;
        __half* sA1 = (__half*)(base + APL);
        __half* sB0 = (__half*)(base + PL * APL);
        __half* sB1 = (__half*)(base + PL * APL + BPL);
#pragma unroll
        for (int i = 0; i < 2; i++) {
            long long ga = aoff + a_row(crow[i]) * lda + k0 + ck[i];
            cp16(sA0 + crow[i] * LDA + ck[i], A0g + ga);
            if (NT > 1) cp16(sA1 + crow[i] * LDA + ck[i], A1g + ga);
            long long gb = boff + (long long)(n0 + crow[i]) * ldb + k0 + ck[i];
            cp16(sB0 + crow[i] * LDB + ck[i], B0g + gb);
            if (NT > 1) cp16(sB1 + crow[i] * LDB + ck[i], B1g + gb);
        }
        CP_COMMIT();
    };

    auto mma_tile = [&](int buf) {
        const char* base = sm + buf * STAGE;
        const __half* sA0 = (const __half*)(base);
        const __half* sA1 = (const __half*)(base + APL);
        const __half* sB0 = (const __half*)(base + PL * APL);
        const __half* sB1 = (const __half*)(base + PL * APL + BPL);
#pragma unroll
        for (int ks = 0; ks < 32; ks += 16) {
            wmma::fragment<wmma::matrix_a, 16, 16, 16, __half, wmma::row_major> a0f[2], a1f[2];
#pragma unroll
            for (int mf = 0; mf < 2; mf++) {
                int r0 = wm * 32 + mf * 16;
                wmma::load_matrix_sync(a0f[mf], sA0 + r0 * LDA + ks, LDA);
                if (NT > 1) wmma::load_matrix_sync(a1f[mf], sA1 + r0 * LDA + ks, LDA);
            }
#pragma unroll
            for (int nf = 0; nf < 4; nf++) {
                int col = wn * 64 + nf * 16;
                wmma::fragment<wmma::matrix_b, 16, 16, 16, __half, wmma::col_major> b0f, b1f;
                wmma::load_matrix_sync(b0f, sB0 + col * LDB + ks, LDB);
                if (NT > 1) wmma::load_matrix_sync(b1f, sB1 + col * LDB + ks, LDB);
#pragma unroll
                for (int mf = 0; mf < 2; mf++) {
                    wmma::mma_sync(acc[mf][nf], a0f[mf], b0f, acc[mf][nf]);
                    if (NT > 1) {
                        wmma::mma_sync(acc[mf][nf], a0f[mf], b1f, acc[mf][nf]);
                        wmma::mma_sync(acc[mf][nf], a1f[mf], b0f, acc[mf][nf]);
                    }
                }
            }
        }
    };

    const int numK = Ktot >> 5;
    cp_tile(0, 0);
    if (numK > 1) cp_tile(32, 1);
    for (int t = 0; t < numK; t++) {
        if (t + 1 < numK) cp_wait1(); else cp_wait0();
        __syncthreads();
        if (t + 2 < numK) cp_tile((t + 2) << 5, (t + 2) % 3);
        mma_tile(t % 3);
    }
    __syncthreads();

    float* Csm = (float*)sm;
#pragma unroll
    for (int mf = 0; mf < 2; mf++)
#pragma unroll
        for (int nf = 0; nf < 4; nf++) {
            int r0 = wm * 32 + mf * 16, c0 = wn * 64 + nf * 16;
            wmma::store_matrix_sync(Csm + r0 * 128 + c0, acc[mf][nf], 128, wmma::mem_row_major);
        }
    __syncthreads();

#pragma unroll
    for (int i = 0; i < 16; i++) {
        int f = tid + i * 256;
        int row = f >> 5, c4 = (f & 31) * 4;
        float4 v = *(float4*)(Csm + row * 128 + c4);
        v.x *= alpha; v.y *= alpha; v.z *= alpha; v.w *= alpha;
        if (biasz) {
            v.x += biasz[n0 + c4 + 0]; v.y += biasz[n0 + c4 + 1];
            v.z += biasz[n0 + c4 + 2]; v.w += biasz[n0 + c4 + 3];
        }
        long long o = coff + (long long)(m0 + row) * ldc + n0 + c4;
        if (Cf) {
            *(float4*)(Cf + o) = v;
        } else {
            __half x0, x1, y0, y1, z0, z1, w0, w1;
            split2(v.x, x0, x1); split2(v.y, y0, y1);
            split2(v.z, z0, z1); split2(v.w, w0, w1);
            __half2 p0 = __halves2half2(x0, y0), q0 = __halves2half2(z0, w0);
            *(uint2*)(C0g + o) = make_uint2(h2u(p0), h2u(q0));
            if (C1g) {
                __half2 p1 = __halves2half2(x1, y1), q1 = __halves2half2(z1, w1);
                *(uint2*)(C1g + o) = make_uint2(h2u(p1), h2u(q1));
            }
        }
    }
}

// ---------------------------------------------------------------------------
// Fused attention per (b, n) CTA.  Phase1 2-stage cp.async (smem budget),
// phase3 3-stage single-sync.
// smem (102400): phase1 stage 2x51200 | Ssm fp32 64x264 @0, Psm0 @67584
//                phase3 stage 3x16896=50688 @0 | epilogue Csm @0
// ---------------------------------------------------------------------------
#define ATTN_SMEM 102400

__global__ __launch_bounds__(256) void k_attn() {
    extern __shared__ __align__(1024) char sm[];
    const int tid = threadIdx.x;
    const int w = tid >> 5, lane = tid & 31;
    const int wm = w & 1, wn = w >> 1;
    const int b = blockIdx.x, n = blockIdx.y;

    float* Ssm = (float*)sm;
    __half* Psm0 = (__half*)(sm + 67584);

    const __half* Qb0 = g_Q0 + ((size_t)n * 8192 + (size_t)b * 64) * 512;
    const __half* Qb1 = g_Q1 + ((size_t)n * 8192 + (size_t)b * 64) * 512;
    const __half* Hb0 = g_h0 + (size_t)b * 256 * 512;
    const __half* Hb1 = g_h1 + (size_t)b * 256 * 512;

    wmma::fragment<wmma::accumulator, 16, 16, 16, float> acc[2][4];
#pragma unroll
    for (int mf = 0; mf < 2; mf++)
#pragma unroll
        for (int nf = 0; nf < 4; nf++) wmma::fill_fragment(acc[mf][nf], 0.0f);

    // ======== phase 1: S = Q' @ h^T  (K=512, 16 chunks, 3-term) ========
    {
        const int arow = tid >> 2, akc = (tid & 3) * 8;
        auto p1_cp = [&](int k0, int buf) {
            char* base = sm + buf * 51200;
            __half* sA0 = (__half*)base;
            __half* sA1 = (__half*)(base + 5120);
            __half* sB0 = (__half*)(base + 10240);
            __half* sB1 = (__half*)(base + 30720);
            {
                long long ga = (size_t)arow * 512 + k0 + akc;
                cp16(sA0 + arow * 40 + akc, Qb0 + ga);
                cp16(sA1 + arow * 40 + akc, Qb1 + ga);
            }
#pragma unroll
            for (int i = 0; i < 4; i++) {
                int id = tid + i * 256;
                int br = id >> 2, bkc = (id & 3) * 8;
                long long gb = (size_t)br * 512 + k0 + bkc;
                cp16(sB0 + br * 40 + bkc, Hb0 + gb);
                cp16(sB1 + br * 40 + bkc, Hb1 + gb);
            }
            CP_COMMIT();
        };
        auto p1_mma = [&](int buf) {
            const char* base = sm + buf * 51200;
            const __half* sA0 = (const __half*)base;
            const __half* sA1 = (const __half*)(base + 5120);
            const __half* sB0 = (const __half*)(base + 10240);
            const __half* sB1 = (const __half*)(base + 30720);
#pragma unroll
            for (int ks = 0; ks < 32; ks += 16) {
                wmma::fragment<wmma::matrix_a, 16, 16, 16, __half, wmma::row_major> a0f[2], a1f[2];
#pragma unroll
                for (int mf = 0; mf < 2; mf++) {
                    int r0 = wm * 32 + mf * 16;
                    wmma::load_matrix_sync(a0f[mf], sA0 + r0 * 40 + ks, 40);
                    wmma::load_matrix_sync(a1f[mf], sA1 + r0 * 40 + ks, 40);
                }
#pragma unroll
                for (int nf = 0; nf < 4; nf++) {
                    int col = wn * 64 + nf * 16;
                    wmma::fragment<wmma::matrix_b, 16, 16, 16, __half, wmma::col_major> b0f, b1f;
                    wmma::load_matrix_sync(b0f, sB0 + col * 40 + ks, 40);
                    wmma::load_matrix_sync(b1f, sB1 + col * 40 + ks, 40);
#pragma unroll
                    for (int mf = 0; mf < 2; mf++) {
                        wmma::mma_sync(acc[mf][nf], a0f[mf], b0f, acc[mf][nf]);
                        wmma::mma_sync(acc[mf][nf], a0f[mf], b1f, acc[mf][nf]);
                        wmma::mma_sync(acc[mf][nf], a1f[mf], b0f, acc[mf][nf]);
                    }
                }
            }
        };
        p1_cp(0, 0);
        for (int t = 0; t < 16; t++) {
            if (t + 1 < 16) {
                p1_cp((t + 1) << 5, (t + 1) & 1);
                cp_wait1();
            } else {
                cp_wait0();
            }
            __syncthreads();
            p1_mma(t & 1);
            __syncthreads();
        }
    }

    // ======== stage S -> smem fp32 ========
#pragma unroll
    for (int mf = 0; mf < 2; mf++)
#pragma unroll
        for (int nf = 0; nf < 4; nf++) {
            int r0 = wm * 32 + mf * 16, c0 = wn * 64 + nf * 16;
            wmma::store_matrix_sync(Ssm + r0 * 264 + c0, acc[mf][nf], 264, wmma::mem_row_major);
        }
    __syncthreads();

    // ======== softmax ========
#pragma unroll
    for (int i = 0; i < 8; i++) {
        int r = w * 8 + i;
        float* srow = Ssm + (size_t)r * 264 + lane * 8;
        float4 v0 = *(float4*)srow;
        float4 v1 = *(float4*)(srow + 4);
        float m = fmaxf(fmaxf(fmaxf(v0.x, v0.y), fmaxf(v0.z, v0.w)),
                        fmaxf(fmaxf(v1.x, v1.y), fmaxf(v1.z, v1.w)));
#pragma unroll
        for (int off = 16; off > 0; off >>= 1)
            m = fmaxf(m, __shfl_xor_sync(0xffffffffu, m, off));
        v0.x = __expf(v0.x - m); v0.y = __expf(v0.y - m);
        v0.z = __expf(v0.z - m); v0.w = __expf(v0.w - m);
        v1.x = __expf(v1.x - m); v1.y = __expf(v1.y - m);
        v1.z = __expf(v1.z - m); v1.w = __expf(v1.w - m);
        float s = v0.x + v0.y + v0.z + v0.w + v1.x + v1.y + v1.z + v1.w;
#pragma unroll
        for (int off = 16; off > 0; off >>= 1)
            s += __shfl_xor_sync(0xffffffffu, s, off);
        const float inv = 1.0f / s;
        __align__(16) __half h0[8];
        h0[0] = __float2half_rn(v0.x * inv); h0[1] = __float2half_rn(v0.y * inv);
        h0[2] = __float2half_rn(v0.z * inv); h0[3] = __float2half_rn(v0.w * inv);
        h0[4] = __float2half_rn(v1.x * inv); h0[5] = __float2half_rn(v1.y * inv);
        h0[6] = __float2half_rn(v1.z * inv); h0[7] = __float2half_rn(v1.w * inv);
        *(uint4*)(Psm0 + (size_t)r * 264 + lane * 8) = *(uint4*)h0;
    }
    __syncthreads();

    // ======== phase 3: U = P @ h  (1-term; two halves; K=256; 3-stage) ====
    for (int hh = 0; hh < 2; hh++) {
        const int d0 = hh * 256;
#pragma unroll
        for (int mf = 0; mf < 2; mf++)
#pragma unroll
            for (int nf = 0; nf < 4; nf++) wmma::fill_fragment(acc[mf][nf], 0.0f);

        auto p3_cp = [&](int k0, int buf) {
            __half* sH0 = (__half*)(sm + buf * 16896);
#pragma unroll
            for (int i = 0; i < 4; i++) {
                int id = tid + i * 256;
                int er = id >> 5, dc = (id & 31) * 8;
                cp16(sH0 + er * 264 + dc, Hb0 + (size_t)(k0 + er) * 512 + d0 + dc);
            }
            CP_COMMIT();
        };
        auto p3_mma = [&](int buf, int c) {
            const __half* sH0 = (const __half*)(sm + buf * 16896);
#pragma unroll
            for (int ks = 0; ks < 32; ks += 16) {
                wmma::fragment<wmma::matrix_a, 16, 16, 16, __half, wmma::row_major> a0f[2];
#pragma unroll
                for (int mf = 0; mf < 2; mf++) {
                    int r0 = wm * 32 + mf * 16;
                    wmma::load_matrix_sync(a0f[mf], Psm0 + r0 * 264 + c * 32 + ks, 264);
                }
#pragma unroll
                for (int nf = 0; nf < 4; nf++) {
                    int col = wn * 64 + nf * 16;
                    wmma::fragment<wmma::matrix_b, 16, 16, 16, __half, wmma::row_major> b0f;
                    wmma::load_matrix_sync(b0f, sH0 + ks * 264 + col, 264);
#pragma unroll
                    for (int mf = 0; mf < 2; mf++)
                        wmma::mma_sync(acc[mf][nf], a0f[mf], b0f, acc[mf][nf]);
                }
            }
        };
        p3_cp(0, 0);
        p3_cp(32, 1);
        for (int c = 0; c < 8; c++) {
            if (c + 1 < 8) cp_wait1(); else cp_wait0();
            __syncthreads();
            if (c + 2 < 8) p3_cp((c + 2) << 5, (c + 2) % 3);
            p3_mma(c % 3, c);
        }
        __syncthreads();

        float* Csm = (float*)sm;
#pragma unroll
        for (int mf = 0; mf < 2; mf++)
#pragma unroll
            for (int nf = 0; nf < 4; nf++) {
                int r0 = wm * 32 + mf * 16, c0 = wn * 64 + nf * 16;
                wmma::store_matrix_sync(Csm + r0 * 264 + c0, acc[mf][nf], 264, wmma::mem_row_major);
            }
        __syncthreads();
#pragma unroll
        for (int i = 0; i < 16; i++) {
            int id = tid + i * 256;
            int row = id >> 6, c4 = (id & 63) * 4;
            float4 v = *(float4*)(Csm + row * 264 + c4);
            __align__(8) __half h4[4];
            h4[0] = __float2half_rn(v.x); h4[1] = __float2half_rn(v.y);
            h4[2] = __float2half_rn(v.z); h4[3] = __float2half_rn(v.w);
            size_t o = (((size_t)(b * 64 + row)) * 8 + n) * 512 + d0 + c4;
            *(uint2*)(g_U0 + o) = *(uint2*)h4;
        }
        __syncthreads();
    }
}

// ---------------------------------------------------------------------------
extern "C" void kernel_launch(void* const* d_in, const int* in_sizes, int n_in,
                              void* d_out, int out_size) {
    const float* x     = (const float*)d_in[0];
    const float* W_enc = (const float*)d_in[1];
    const float* b_enc = (const float*)d_in[2];
    const float* WQ    = (const float*)d_in[3];
    const float* WK    = (const float*)d_in[4];
    const float* WV    = (const float*)d_in[5];
    float* out = (float*)d_out;

    const int SM3 = 3 * 2 * (128 * 40 * 2 + 128 * 40 * 2);   // 122880
    const int SM1 = 128 * 128 * 4;                            // 65536 (>= 3*20480)
    cudaFuncSetAttribute(k_mma<3>, cudaFuncAttributeMaxDynamicSharedMemorySize, SM3);
    cudaFuncSetAttribute(k_mma<1>, cudaFuncAttributeMaxDynamicSharedMemorySize, SM1);
    cudaFuncSetAttribute(k_attn, cudaFuncAttributeMaxDynamicSharedMemorySize, ATTN_SMEM);

    void *p_M, *p_E, *p_bv, *p_x0, *p_x1, *p_h0, *p_h1, *p_Q0, *p_Q1, *p_U0;
    void *p_e0, *p_e1, *p_we0, *p_we1, *p_m0, *p_m1, *p_E0, *p_E1;
    void *p_w0, *p_w1, *p_k0, *p_k1, *p_q0, *p_q1;
    cudaGetSymbolAddress(&p_M, g_M);
    cudaGetSymbolAddress(&p_E, g_E);
    cudaGetSymbolAddress(&p_bv, g_bv);
    cudaGetSymbolAddress(&p_x0, g_x0); cudaGetSymbolAddress(&p_x1, g_x1);
    cudaGetSymbolAddress(&p_h0, g_h0); cudaGetSymbolAddress(&p_h1, g_h1);
    cudaGetSymbolAddress(&p_Q0, g_Q0); cudaGetSymbolAddress(&p_Q1, g_Q1);
    cudaGetSymbolAddress(&p_U0, g_U0);
    cudaGetSymbolAddress(&p_e0, g_Te0); cudaGetSymbolAddress(&p_e1, g_Te1);
    cudaGetSymbolAddress(&p_we0, g_We0); cudaGetSymbolAddress(&p_we1, g_We1);
    cudaGetSymbolAddress(&p_m0, g_Tm0); cudaGetSymbolAddress(&p_m1, g_Tm1);
    cudaGetSymbolAddress(&p_E0, g_TE0); cudaGetSymbolAddress(&p_E1, g_TE1);
    cudaGetSymbolAddress(&p_w0, g_Tw0); cudaGetSymbolAddress(&p_w1, g_Tw1);
    cudaGetSymbolAddress(&p_k0, g_Wk0); cudaGetSymbolAddress(&p_k1, g_Wk1);
    cudaGetSymbolAddress(&p_q0, g_Wq0); cudaGetSymbolAddress(&p_q1, g_Wq1);

    // ---- prep
    k_xsplit<<<dim3(2048), 256>>>(x, (__half*)p_x0, (__half*)p_x1, (size_t)32768 * 256 / 4);
    k_tsplit2<<<dim3(8, 16, 1), dim3(32, 8)>>>(W_enc, (__half*)p_e0, (__half*)p_e1, 256, 512);
    k_split2e<<<dim3(128), 256>>>(W_enc, (__half*)p_we0, (__half*)p_we1, (size_t)256 * 512);
    k_tsplit2<<<dim3(128, 16, 1), dim3(32, 8)>>>(WV, (__half*)p_w0, (__half*)p_w1, 4096, 512);
    k_split2e<<<dim3(512), 256>>>(WK, (__half*)p_k0, (__half*)p_k1, (size_t)8 * 512 * 512);
    k_split2e<<<dim3(512), 256>>>(WQ, (__half*)p_q0, (__half*)p_q1, (size_t)8 * 512 * 512);

    // ---- M_n = (WQ_n @ WK_n^T) * scale
    k_mma<3><<<dim3(4, 4, 8), 256, SM3>>>(
        (const __half*)p_q0, (const __half*)p_q1,
        (const __half*)p_k0, (const __half*)p_k1,
        (float*)p_M, nullptr, nullptr, nullptr, 0, 0.04419417382415922f,
        512, 512, 512, 512, 0,
        (long long)512 * 512, (long long)512 * 512, (long long)512 * 512);

    k_tsplit2<<<dim3(16, 16, 8), dim3(32, 8)>>>((const float*)p_M, (__half*)p_m0, (__half*)p_m1, 512, 512);
    k_bv<<<dim3(8), 512>>>(b_enc);

    // ---- E_n = W_enc @ M_n  [8,256,512]
    k_mma<3><<<dim3(4, 2, 8), 256, SM3>>>(
        (const __half*)p_we0, (const __half*)p_we1,
        (const __half*)p_m0, (const __half*)p_m1,
        (float*)p_E, nullptr, nullptr, nullptr, 0, 1.0f,
        512, 512, 512, 512, 0,
        0, (long long)512 * 512, (long long)256 * 512);

    k_tsplit2<<<dim3(8, 16, 8), dim3(32, 8)>>>((const float*)p_E, (__half*)p_E0, (__half*)p_E1, 256, 512);

    // ---- encode: h planes = xp @ Te + b
    k_mma<3><<<dim3(4, 256, 1), 256, SM3>>>(
        (const __half*)p_x0, (const __half*)p_x1,
        (const __half*)p_e0, (const __half*)p_e1,
        nullptr, (__half*)p_h0, (__half*)p_h1, b_enc, 0, 1.0f,
        256, 256, 256, 512, 0, 0, 0, 0);

    // ---- Q' planes = xp_a @ TE + bv  (K=256, gather, batched)
    k_mma<3><<<dim3(4, 64, 8), 256, SM3>>>(
        (const __half*)p_x0, (const __half*)p_x1,
        (const __half*)p_E0, (const __half*)p_E1,
        nullptr, (__half*)p_Q0, (__half*)p_Q1, (const float*)p_bv, 512, 1.0f,
        256, 256, 256, 512, 1,
        0, (long long)512 * 256, (long long)8192 * 512);

    // ---- fused attention
    k_attn<<<dim3(128, 8), 256, ATTN_SMEM>>>();

    // ---- out = (1/8) U @ WVcat  (1-term)
    k_mma<1><<<dim3(4, 64, 1), 256, SM1>>>(
        (const __half*)p_U0, nullptr,
        (const __half*)p_w0, nullptr,
        out, nullptr, nullptr, nullptr, 0, 0.125f,
        4096, 4096, 4096, 512, 0, 0, 0, 0);
}

// round 14
// speedup vs baseline: 1.4657x; 1.0541x over previous
#include <cuda_runtime.h>
#include <cuda_fp16.h>
#include <mma.h>
#include <cstdint>
#include <string.h>
#include <math.h>

using namespace nvcuda;

// ===========================================================================
//  xp  = split2(lrelu(x))              [32768,256]  elementwise prep
//  M_n = (WQ_n @ WK_n^T)/sqrt(512)     [8,512,512]  WMMA 3-term
//  E_n = W_enc @ M_n                   [8,256,512]  WMMA 3-term
//  bv_n = b_enc @ M_n                  [8,512]      FFMA GEMV
//  h   = xp @ W_enc^T planes + b       [32768,512]  WMMA 3-term
//  Q'  = xp_a @ E_n^T planes + bv_n    [8,8192,512] WMMA 3-term, K=256
//  attn fused: S=Q'@h^T (3-term) -> softmax -> U=P@h (1-term fp16)
//  out = (1/8) U @ WVcat               [8192,512]   WMMA 1-term fp16
// This round: K-chunk 64 (half the syncs), merged weight-split launches,
// launch order arranged so ncu's captured launch (#6) is the encode GEMM.
// ===========================================================================

// -------------------- scratch (device globals) -----------------------------
static __device__ float  g_M [8u * 512u * 512u];
static __device__ float  g_E [8u * 256u * 512u];
static __device__ float  g_bv[8u * 512u];
static __device__ __half g_x0[32768u * 256u], g_x1[32768u * 256u];
static __device__ __half g_h0[32768u * 512u],  g_h1[32768u * 512u];
static __device__ __half g_Q0[8u * 8192u * 512u], g_Q1[8u * 8192u * 512u];
static __device__ __half g_U0[8192u * 4096u];
static __device__ __half g_Te0[512u * 256u],  g_Te1[512u * 256u];          // W_enc^T
static __device__ __half g_We0[256u * 512u],  g_We1[256u * 512u];          // W_enc (row)
static __device__ __half g_Tm0[8u * 512u * 512u], g_Tm1[8u * 512u * 512u]; // M^T
static __device__ __half g_TE0[8u * 512u * 256u], g_TE1[8u * 512u * 256u]; // E^T
static __device__ __half g_Tw0[512u * 4096u], g_Tw1[512u * 4096u];         // WVcat^T
static __device__ __half g_Wk0[8u * 512u * 512u], g_Wk1[8u * 512u * 512u]; // WK
static __device__ __half g_Wq0[8u * 512u * 512u], g_Wq1[8u * 512u * 512u]; // WQ

__device__ __forceinline__ float lrelu(float v) { return v > 0.0f ? v : 0.01f * v; }

__device__ __forceinline__ void split2(float v, __half& h0, __half& h1) {
    h0 = __float2half_rn(v);
    h1 = __float2half_rn(v - __half2float(h0));
}

__device__ __forceinline__ uint32_t h2u(__half2 v) {
    uint32_t u;
    memcpy(&u, &v, 4);
    return u;
}

// -------------------- cp.async helpers --------------------------------------
__device__ __forceinline__ void cp16(void* sdst, const void* gsrc) {
    uint32_t s = (uint32_t)__cvta_generic_to_shared(sdst);
    asm volatile("cp.async.cg.shared.global [%0], [%1], 16;" :: "r"(s), "l"(gsrc));
}
#define CP_COMMIT() asm volatile("cp.async.commit_group;" ::: "memory")
__device__ __forceinline__ void cp_wait0() { asm volatile("cp.async.wait_group 0;" ::: "memory"); }
__device__ __forceinline__ void cp_wait1() { asm volatile("cp.async.wait_group 1;" ::: "memory"); }

// ---------------------------------------------------------------------------
// xp = split2(lrelu(x)) elementwise, vectorized
// ---------------------------------------------------------------------------
__global__ __launch_bounds__(256) void k_xsplit(const float* __restrict__ X,
                                                __half* __restrict__ T0,
                                                __half* __restrict__ T1,
                                                size_t total4) {
    for (size_t i = (size_t)blockIdx.x * 256 + threadIdx.x; i < total4;
         i += (size_t)gridDim.x * 256) {
        float4 v = ((const float4*)X)[i];
        v.x = lrelu(v.x); v.y = lrelu(v.y); v.z = lrelu(v.z); v.w = lrelu(v.w);
        __align__(8) __half a[4], b[4];
        split2(v.x, a[0], b[0]); split2(v.y, a[1], b[1]);
        split2(v.z, a[2], b[2]); split2(v.w, a[3], b[3]);
        ((uint2*)T0)[i] = *(uint2*)a;
        ((uint2*)T1)[i] = *(uint2*)b;
    }
}

// ---------------------------------------------------------------------------
// three elementwise fp16 split2 jobs fused into one launch
// ---------------------------------------------------------------------------
__global__ __launch_bounds__(256) void k_split3(
    const float* __restrict__ A, __half* __restrict__ A0, __half* __restrict__ A1, size_t na,
    const float* __restrict__ B, __half* __restrict__ B0, __half* __restrict__ B1, size_t nb,
    const float* __restrict__ C, __half* __restrict__ C0, __half* __restrict__ C1, size_t nc) {
    const size_t stride = (size_t)gridDim.x * 256;
    const size_t t0 = (size_t)blockIdx.x * 256 + threadIdx.x;
    for (size_t i = t0; i < na; i += stride) split2(A[i], A0[i], A1[i]);
    for (size_t i = t0; i < nb; i += stride) split2(B[i], B0[i], B1[i]);
    for (size_t i = t0; i < nc; i += stride) split2(C[i], C0[i], C1[i]);
}

// ---------------------------------------------------------------------------
// tiled transpose + fp16 split2:  T*[n*K+k] = split(B[k*N+n])
// ---------------------------------------------------------------------------
__global__ __launch_bounds__(256) void k_tsplit2(const float* __restrict__ B,
                                                 __half* __restrict__ T0,
                                                 __half* __restrict__ T1,
                                                 int K, int N) {
    __shared__ __half s0[32][33];
    __shared__ __half s1[32][33];
    const size_t base = (size_t)blockIdx.z * (size_t)K * N;
    const int k0 = blockIdx.x * 32, n0 = blockIdx.y * 32;
    const int tx = threadIdx.x, ty = threadIdx.y;
#pragma unroll
    for (int i = 0; i < 4; i++) {
        int row = ty * 4 + i;
        float v = B[base + (size_t)(k0 + row) * N + n0 + tx];
        split2(v, s0[row][tx], s1[row][tx]);
    }
    __syncthreads();
#pragma unroll
    for (int i = 0; i < 4; i++) {
        int nrow = ty * 4 + i;
        size_t o = base + (size_t)(n0 + nrow) * K + k0 + tx;
        T0[o] = s0[tx][nrow];
        T1[o] = s1[tx][nrow];
    }
}

// ---------------------------------------------------------------------------
// bv_n = b_enc @ M_n : [8,512]
// ---------------------------------------------------------------------------
__global__ __launch_bounds__(512) void k_bv(const float* __restrict__ b_enc) {
    const int n = blockIdx.x, j = threadIdx.x;
    const float* Mn = g_M + (size_t)n * 512 * 512;
    float s = 0.0f;
    for (int k = 0; k < 512; k++) s += b_enc[k] * Mn[(size_t)k * 512 + j];
    g_bv[n * 512 + j] = s;
}

// ---------------------------------------------------------------------------
// WMMA GEMM, 256 thr, tile 128x128, K-chunk 64, 3-stage cp.async,
// single __syncthreads per K-tile.
// ---------------------------------------------------------------------------
template <int NT>
__global__ __launch_bounds__(256) void k_mma(
    const __half* __restrict__ A0g, const __half* __restrict__ A1g,
    const __half* __restrict__ B0g, const __half* __restrict__ B1g,
    float* __restrict__ Cf, __half* __restrict__ C0g, __half* __restrict__ C1g,
    const float* __restrict__ bias, long long biasHi, float alpha,
    int Ktot, int lda, int ldb, int ldc, int gather,
    long long aHi, long long bHi, long long cHi)
{
    constexpr int LDA = 72, LDB = 72;     // 64 + 8 pad (halves)
    constexpr int PL  = (NT > 1) ? 2 : 1;
    constexpr int APL = 128 * LDA * 2;    // 18432 per plane
    constexpr int BPL = 128 * LDB * 2;
    constexpr int STAGE = PL * (APL + BPL);

    extern __shared__ __align__(1024) char sm[];

    const int tid = threadIdx.x;
    const int w = tid >> 5;
    const int wm = w & 3;
    const int wn = w >> 2;
    const long long aoff = (long long)blockIdx.z * aHi;
    const long long boff = (long long)blockIdx.z * bHi;
    const long long coff = (long long)blockIdx.z * cHi;
    const float* biasz = bias ? (bias + (long long)blockIdx.z * biasHi) : (const float*)0;
    const int m0 = blockIdx.y * 128;
    const int n0 = blockIdx.x * 128;

    // 128 rows x 8 (16B chunks) = 1024 cp per plane; 4 per thread
    int crow[4], ck[4];
#pragma unroll
    for (int i = 0; i < 4; i++) {
        int id = tid + i * 256;
        crow[i] = id >> 3;
        ck[i] = (id & 7) * 8;
    }

    auto a_row = [&](int r) -> long long {
        int g = m0 + r;
        return gather ? (long long)(((g >> 6) << 8) + (g & 63)) : (long long)g;
    };

    wmma::fragment<wmma::accumulator, 16, 16, 16, float> acc[2][4];
#pragma unroll
    for (int mf = 0; mf < 2; mf++)
#pragma unroll
        for (int nf = 0; nf < 4; nf++) wmma::fill_fragment(acc[mf][nf], 0.0f);

    auto cp_tile = [&](int k0, int buf) {
        char* base = sm + buf * STAGE;
        __half* sA0 = (__half*)base;
        __half* sA1 = (__half*)(base + APL);
        __half* sB0 = (__half*)(base + PL * APL);
        __half* sB1 = (__half*)(base + PL * APL + BPL);
#pragma unroll
        for (int i = 0; i < 4; i++) {
            long long ga = aoff + a_row(crow[i]) * lda + k0 + ck[i];
            cp16(sA0 + crow[i] * LDA + ck[i], A0g + ga);
            if (NT > 1) cp16(sA1 + crow[i] * LDA + ck[i], A1g + ga);
            long long gb = boff + (long long)(n0 + crow[i]) * ldb + k0 + ck[i];
            cp16(sB0 + crow[i] * LDB + ck[i], B0g + gb);
            if (NT > 1) cp16(sB1 + crow[i] * LDB + ck[i], B1g + gb);
        }
        CP_COMMIT();
    };

    auto mma_tile = [&](int buf) {
        const char* base = sm + buf * STAGE;
        const __half* sA0 = (const __half*)(base);
        const __half* sA1 = (const __half*)(base + APL);
        const __half* sB0 = (const __half*)(base + PL * APL);
        const __half* sB1 = (const __half*)(base + PL * APL + BPL);
#pragma unroll
        for (int ks = 0; ks < 64; ks += 16) {
            wmma::fragment<wmma::matrix_a, 16, 16, 16, __half, wmma::row_major> a0f[2], a1f[2];
#pragma unroll
            for (int mf = 0; mf < 2; mf++) {
                int r0 = wm * 32 + mf * 16;
                wmma::load_matrix_sync(a0f[mf], sA0 + r0 * LDA + ks, LDA);
                if (NT > 1) wmma::load_matrix_sync(a1f[mf], sA1 + r0 * LDA + ks, LDA);
            }
#pragma unroll
            for (int nf = 0; nf < 4; nf++) {
                int col = wn * 64 + nf * 16;
                wmma::fragment<wmma::matrix_b, 16, 16, 16, __half, wmma::col_major> b0f, b1f;
                wmma::load_matrix_sync(b0f, sB0 + col * LDB + ks, LDB);
                if (NT > 1) wmma::load_matrix_sync(b1f, sB1 + col * LDB + ks, LDB);
#pragma unroll
                for (int mf = 0; mf < 2; mf++) {
                    wmma::mma_sync(acc[mf][nf], a0f[mf], b0f, acc[mf][nf]);
                    if (NT > 1) {
                        wmma::mma_sync(acc[mf][nf], a0f[mf], b1f, acc[mf][nf]);
                        wmma::mma_sync(acc[mf][nf], a1f[mf], b0f, acc[mf][nf]);
                    }
                }
            }
        }
    };

    const int numK = Ktot >> 6;
    cp_tile(0, 0);
    if (numK > 1) cp_tile(64, 1);
    for (int t = 0; t < numK; t++) {
        if (t + 1 < numK) cp_wait1(); else cp_wait0();
        __syncthreads();
        if (t + 2 < numK) cp_tile((t + 2) << 6, (t + 2) % 3);
        mma_tile(t % 3);
    }
    __syncthreads();

    float* Csm = (float*)sm;
#pragma unroll
    for (int mf = 0; mf < 2; mf++)
#pragma unroll
        for (int nf = 0; nf < 4; nf++) {
            int r0 = wm * 32 + mf * 16, c0 = wn * 64 + nf * 16;
            wmma::store_matrix_sync(Csm + r0 * 128 + c0, acc[mf][nf], 128, wmma::mem_row_major);
        }
    __syncthreads();

#pragma unroll
    for (int i = 0; i < 16; i++) {
        int f = tid + i * 256;
        int row = f >> 5, c4 = (f & 31) * 4;
        float4 v = *(float4*)(Csm + row * 128 + c4);
        v.x *= alpha; v.y *= alpha; v.z *= alpha; v.w *= alpha;
        if (biasz) {
            v.x += biasz[n0 + c4 + 0]; v.y += biasz[n0 + c4 + 1];
            v.z += biasz[n0 + c4 + 2]; v.w += biasz[n0 + c4 + 3];
        }
        long long o = coff + (long long)(m0 + row) * ldc + n0 + c4;
        if (Cf) {
            *(float4*)(Cf + o) = v;
        } else {
            __half x0, x1, y0, y1, z0, z1, w0, w1;
            split2(v.x, x0, x1); split2(v.y, y0, y1);
            split2(v.z, z0, z1); split2(v.w, w0, w1);
            __half2 p0 = __halves2half2(x0, y0), q0 = __halves2half2(z0, w0);
            *(uint2*)(C0g + o) = make_uint2(h2u(p0), h2u(q0));
            if (C1g) {
                __half2 p1 = __halves2half2(x1, y1), q1 = __halves2half2(z1, w1);
                *(uint2*)(C1g + o) = make_uint2(h2u(p1), h2u(q1));
            }
        }
    }
}

// ---------------------------------------------------------------------------
// Fused attention per (b, n) CTA.  Phase1 2-stage cp.async, phase3 3-stage.
// smem (102400): phase1 stage 2x51200 | Ssm fp32 64x264 @0, Psm0 @67584
//                phase3 stage 3x16896=50688 @0 | epilogue Csm @0
// ---------------------------------------------------------------------------
#define ATTN_SMEM 102400

__global__ __launch_bounds__(256) void k_attn() {
    extern __shared__ __align__(1024) char sm[];
    const int tid = threadIdx.x;
    const int w = tid >> 5, lane = tid & 31;
    const int wm = w & 1, wn = w >> 1;
    const int b = blockIdx.x, n = blockIdx.y;

    float* Ssm = (float*)sm;
    __half* Psm0 = (__half*)(sm + 67584);

    const __half* Qb0 = g_Q0 + ((size_t)n * 8192 + (size_t)b * 64) * 512;
    const __half* Qb1 = g_Q1 + ((size_t)n * 8192 + (size_t)b * 64) * 512;
    const __half* Hb0 = g_h0 + (size_t)b * 256 * 512;
    const __half* Hb1 = g_h1 + (size_t)b * 256 * 512;

    wmma::fragment<wmma::accumulator, 16, 16, 16, float> acc[2][4];
#pragma unroll
    for (int mf = 0; mf < 2; mf++)
#pragma unroll
        for (int nf = 0; nf < 4; nf++) wmma::fill_fragment(acc[mf][nf], 0.0f);

    // ======== phase 1: S = Q' @ h^T  (K=512, 16 chunks, 3-term) ========
    {
        const int arow = tid >> 2, akc = (tid & 3) * 8;
        auto p1_cp = [&](int k0, int buf) {
            char* base = sm + buf * 51200;
            __half* sA0 = (__half*)base;
            __half* sA1 = (__half*)(base + 5120);
            __half* sB0 = (__half*)(base + 10240);
            __half* sB1 = (__half*)(base + 30720);
            {
                long long ga = (size_t)arow * 512 + k0 + akc;
                cp16(sA0 + arow * 40 + akc, Qb0 + ga);
                cp16(sA1 + arow * 40 + akc, Qb1 + ga);
            }
#pragma unroll
            for (int i = 0; i < 4; i++) {
                int id = tid + i * 256;
                int br = id >> 2, bkc = (id & 3) * 8;
                long long gb = (size_t)br * 512 + k0 + bkc;
                cp16(sB0 + br * 40 + bkc, Hb0 + gb);
                cp16(sB1 + br * 40 + bkc, Hb1 + gb);
            }
            CP_COMMIT();
        };
        auto p1_mma = [&](int buf) {
            const char* base = sm + buf * 51200;
            const __half* sA0 = (const __half*)base;
            const __half* sA1 = (const __half*)(base + 5120);
            const __half* sB0 = (const __half*)(base + 10240);
            const __half* sB1 = (const __half*)(base + 30720);
#pragma unroll
            for (int ks = 0; ks < 32; ks += 16) {
                wmma::fragment<wmma::matrix_a, 16, 16, 16, __half, wmma::row_major> a0f[2], a1f[2];
#pragma unroll
                for (int mf = 0; mf < 2; mf++) {
                    int r0 = wm * 32 + mf * 16;
                    wmma::load_matrix_sync(a0f[mf], sA0 + r0 * 40 + ks, 40);
                    wmma::load_matrix_sync(a1f[mf], sA1 + r0 * 40 + ks, 40);
                }
#pragma unroll
                for (int nf = 0; nf < 4; nf++) {
                    int col = wn * 64 + nf * 16;
                    wmma::fragment<wmma::matrix_b, 16, 16, 16, __half, wmma::col_major> b0f, b1f;
                    wmma::load_matrix_sync(b0f, sB0 + col * 40 + ks, 40);
                    wmma::load_matrix_sync(b1f, sB1 + col * 40 + ks, 40);
#pragma unroll
                    for (int mf = 0; mf < 2; mf++) {
                        wmma::mma_sync(acc[mf][nf], a0f[mf], b0f, acc[mf][nf]);
                        wmma::mma_sync(acc[mf][nf], a0f[mf], b1f, acc[mf][nf]);
                        wmma::mma_sync(acc[mf][nf], a1f[mf], b0f, acc[mf][nf]);
                    }
                }
            }
        };
        p1_cp(0, 0);
        for (int t = 0; t < 16; t++) {
            if (t + 1 < 16) {
                p1_cp((t + 1) << 5, (t + 1) & 1);
                cp_wait1();
            } else {
                cp_wait0();
            }
            __syncthreads();
            p1_mma(t & 1);
            __syncthreads();
        }
    }

    // ======== stage S -> smem fp32 ========
#pragma unroll
    for (int mf = 0; mf < 2; mf++)
#pragma unroll
        for (int nf = 0; nf < 4; nf++) {
            int r0 = wm * 32 + mf * 16, c0 = wn * 64 + nf * 16;
            wmma::store_matrix_sync(Ssm + r0 * 264 + c0, acc[mf][nf], 264, wmma::mem_row_major);
        }
    __syncthreads();

    // ======== softmax ========
#pragma unroll
    for (int i = 0; i < 8; i++) {
        int r = w * 8 + i;
        float* srow = Ssm + (size_t)r * 264 + lane * 8;
        float4 v0 = *(float4*)srow;
        float4 v1 = *(float4*)(srow + 4);
        float m = fmaxf(fmaxf(fmaxf(v0.x, v0.y), fmaxf(v0.z, v0.w)),
                        fmaxf(fmaxf(v1.x, v1.y), fmaxf(v1.z, v1.w)));
#pragma unroll
        for (int off = 16; off > 0; off >>= 1)
            m = fmaxf(m, __shfl_xor_sync(0xffffffffu, m, off));
        v0.x = __expf(v0.x - m); v0.y = __expf(v0.y - m);
        v0.z = __expf(v0.z - m); v0.w = __expf(v0.w - m);
        v1.x = __expf(v1.x - m); v1.y = __expf(v1.y - m);
        v1.z = __expf(v1.z - m); v1.w = __expf(v1.w - m);
        float s = v0.x + v0.y + v0.z + v0.w + v1.x + v1.y + v1.z + v1.w;
#pragma unroll
        for (int off = 16; off > 0; off >>= 1)
            s += __shfl_xor_sync(0xffffffffu, s, off);
        const float inv = 1.0f / s;
        __align__(16) __half h0[8];
        h0[0] = __float2half_rn(v0.x * inv); h0[1] = __float2half_rn(v0.y * inv);
        h0[2] = __float2half_rn(v0.z * inv); h0[3] = __float2half_rn(v0.w * inv);
        h0[4] = __float2half_rn(v1.x * inv); h0[5] = __float2half_rn(v1.y * inv);
        h0[6] = __float2half_rn(v1.z * inv); h0[7] = __float2half_rn(v1.w * inv);
        *(uint4*)(Psm0 + (size_t)r * 264 + lane * 8) = *(uint4*)h0;
    }
    __syncthreads();

    // ======== phase 3: U = P @ h  (1-term; two halves; K=256; 3-stage) ====
    for (int hh = 0; hh < 2; hh++) {
        const int d0 = hh * 256;
#pragma unroll
        for (int mf = 0; mf < 2; mf++)
#pragma unroll
            for (int nf = 0; nf < 4; nf++) wmma::fill_fragment(acc[mf][nf], 0.0f);

        auto p3_cp = [&](int k0, int buf) {
            __half* sH0 = (__half*)(sm + buf * 16896);
#pragma unroll
            for (int i = 0; i < 4; i++) {
                int id = tid + i * 256;
                int er = id >> 5, dc = (id & 31) * 8;
                cp16(sH0 + er * 264 + dc, Hb0 + (size_t)(k0 + er) * 512 + d0 + dc);
            }
            CP_COMMIT();
        };
        auto p3_mma = [&](int buf, int c) {
            const __half* sH0 = (const __half*)(sm + buf * 16896);
#pragma unroll
            for (int ks = 0; ks < 32; ks += 16) {
                wmma::fragment<wmma::matrix_a, 16, 16, 16, __half, wmma::row_major> a0f[2];
#pragma unroll
                for (int mf = 0; mf < 2; mf++) {
                    int r0 = wm * 32 + mf * 16;
                    wmma::load_matrix_sync(a0f[mf], Psm0 + r0 * 264 + c * 32 + ks, 264);
                }
#pragma unroll
                for (int nf = 0; nf < 4; nf++) {
                    int col = wn * 64 + nf * 16;
                    wmma::fragment<wmma::matrix_b, 16, 16, 16, __half, wmma::row_major> b0f;
                    wmma::load_matrix_sync(b0f, sH0 + ks * 264 + col, 264);
#pragma unroll
                    for (int mf = 0; mf < 2; mf++)
                        wmma::mma_sync(acc[mf][nf], a0f[mf], b0f, acc[mf][nf]);
                }
            }
        };
        p3_cp(0, 0);
        p3_cp(32, 1);
        for (int c = 0; c < 8; c++) {
            if (c + 1 < 8) cp_wait1(); else cp_wait0();
            __syncthreads();
            if (c + 2 < 8) p3_cp((c + 2) << 5, (c + 2) % 3);
            p3_mma(c % 3, c);
        }
        __syncthreads();

        float* Csm = (float*)sm;
#pragma unroll
        for (int mf = 0; mf < 2; mf++)
#pragma unroll
            for (int nf = 0; nf < 4; nf++) {
                int r0 = wm * 32 + mf * 16, c0 = wn * 64 + nf * 16;
                wmma::store_matrix_sync(Csm + r0 * 264 + c0, acc[mf][nf], 264, wmma::mem_row_major);
            }
        __syncthreads();
#pragma unroll
        for (int i = 0; i < 16; i++) {
            int id = tid + i * 256;
            int row = id >> 6, c4 = (id & 63) * 4;
            float4 v = *(float4*)(Csm + row * 264 + c4);
            __align__(8) __half h4[4];
            h4[0] = __float2half_rn(v.x); h4[1] = __float2half_rn(v.y);
            h4[2] = __float2half_rn(v.z); h4[3] = __float2half_rn(v.w);
            size_t o = (((size_t)(b * 64 + row)) * 8 + n) * 512 + d0 + c4;
            *(uint2*)(g_U0 + o) = *(uint2*)h4;
        }
        __syncthreads();
    }
}

// ---------------------------------------------------------------------------
extern "C" void kernel_launch(void* const* d_in, const int* in_sizes, int n_in,
                              void* d_out, int out_size) {
    const float* x     = (const float*)d_in[0];
    const float* W_enc = (const float*)d_in[1];
    const float* b_enc = (const float*)d_in[2];
    const float* WQ    = (const float*)d_in[3];
    const float* WK    = (const float*)d_in[4];
    const float* WV    = (const float*)d_in[5];
    float* out = (float*)d_out;

    const int SM3 = 3 * 2 * (128 * 72 * 2 + 128 * 72 * 2);   // 221184
    const int SM1 = 3 * (128 * 72 * 2 + 128 * 72 * 2);       // 110592 (>= 65536)
    cudaFuncSetAttribute(k_mma<3>, cudaFuncAttributeMaxDynamicSharedMemorySize, SM3);
    cudaFuncSetAttribute(k_mma<1>, cudaFuncAttributeMaxDynamicSharedMemorySize, SM1);
    cudaFuncSetAttribute(k_attn, cudaFuncAttributeMaxDynamicSharedMemorySize, ATTN_SMEM);

    void *p_M, *p_E, *p_bv, *p_x0, *p_x1, *p_h0, *p_h1, *p_Q0, *p_Q1, *p_U0;
    void *p_e0, *p_e1, *p_we0, *p_we1, *p_m0, *p_m1, *p_E0, *p_E1;
    void *p_w0, *p_w1, *p_k0, *p_k1, *p_q0, *p_q1;
    cudaGetSymbolAddress(&p_M, g_M);
    cudaGetSymbolAddress(&p_E, g_E);
    cudaGetSymbolAddress(&p_bv, g_bv);
    cudaGetSymbolAddress(&p_x0, g_x0); cudaGetSymbolAddress(&p_x1, g_x1);
    cudaGetSymbolAddress(&p_h0, g_h0); cudaGetSymbolAddress(&p_h1, g_h1);
    cudaGetSymbolAddress(&p_Q0, g_Q0); cudaGetSymbolAddress(&p_Q1, g_Q1);
    cudaGetSymbolAddress(&p_U0, g_U0);
    cudaGetSymbolAddress(&p_e0, g_Te0); cudaGetSymbolAddress(&p_e1, g_Te1);
    cudaGetSymbolAddress(&p_we0, g_We0); cudaGetSymbolAddress(&p_we1, g_We1);
    cudaGetSymbolAddress(&p_m0, g_Tm0); cudaGetSymbolAddress(&p_m1, g_Tm1);
    cudaGetSymbolAddress(&p_E0, g_TE0); cudaGetSymbolAddress(&p_E1, g_TE1);
    cudaGetSymbolAddress(&p_w0, g_Tw0); cudaGetSymbolAddress(&p_w1, g_Tw1);
    cudaGetSymbolAddress(&p_k0, g_Wk0); cudaGetSymbolAddress(&p_k1, g_Wk1);
    cudaGetSymbolAddress(&p_q0, g_Wq0); cudaGetSymbolAddress(&p_q1, g_Wq1);

    // ---- prep (ordered so launch index 5 = encode GEMM, ncu's capture)
    // 0: x split
    k_xsplit<<<dim3(2048), 256>>>(x, (__half*)p_x0, (__half*)p_x1, (size_t)32768 * 256 / 4);
    // 1: We + WK + WQ elementwise splits (fused)
    k_split3<<<dim3(512), 256>>>(
        W_enc, (__half*)p_we0, (__half*)p_we1, (size_t)256 * 512,
        WK, (__half*)p_k0, (__half*)p_k1, (size_t)8 * 512 * 512,
        WQ, (__half*)p_q0, (__half*)p_q1, (size_t)8 * 512 * 512);
    // 2: W_enc^T split
    k_tsplit2<<<dim3(8, 16, 1), dim3(32, 8)>>>(W_enc, (__half*)p_e0, (__half*)p_e1, 256, 512);
    // 3: WV^T split
    k_tsplit2<<<dim3(128, 16, 1), dim3(32, 8)>>>(WV, (__half*)p_w0, (__half*)p_w1, 4096, 512);
    // 4: M_n = (WQ_n @ WK_n^T) * scale
    k_mma<3><<<dim3(4, 4, 8), 256, SM3>>>(
        (const __half*)p_q0, (const __half*)p_q1,
        (const __half*)p_k0, (const __half*)p_k1,
        (float*)p_M, nullptr, nullptr, nullptr, 0, 0.04419417382415922f,
        512, 512, 512, 512, 0,
        (long long)512 * 512, (long long)512 * 512, (long long)512 * 512);
    // 5: encode (PROFILED): h planes = xp @ Te + b
    k_mma<3><<<dim3(4, 256, 1), 256, SM3>>>(
        (const __half*)p_x0, (const __half*)p_x1,
        (const __half*)p_e0, (const __half*)p_e1,
        nullptr, (__half*)p_h0, (__half*)p_h1, b_enc, 0, 1.0f,
        256, 256, 256, 512, 0, 0, 0, 0);
    // 6: M^T split
    k_tsplit2<<<dim3(16, 16, 8), dim3(32, 8)>>>((const float*)p_M, (__half*)p_m0, (__half*)p_m1, 512, 512);
    // 7: bv = b @ M
    k_bv<<<dim3(8), 512>>>(b_enc);
    // 8: E_n = W_enc @ M_n
    k_mma<3><<<dim3(4, 2, 8), 256, SM3>>>(
        (const __half*)p_we0, (const __half*)p_we1,
        (const __half*)p_m0, (const __half*)p_m1,
        (float*)p_E, nullptr, nullptr, nullptr, 0, 1.0f,
        512, 512, 512, 512, 0,
        0, (long long)512 * 512, (long long)256 * 512);
    // 9: E^T split
    k_tsplit2<<<dim3(8, 16, 8), dim3(32, 8)>>>((const float*)p_E, (__half*)p_E0, (__half*)p_E1, 256, 512);
    // 10: Q' = xp_a @ TE + bv  (K=256, gather, batched)
    k_mma<3><<<dim3(4, 64, 8), 256, SM3>>>(
        (const __half*)p_x0, (const __half*)p_x1,
        (const __half*)p_E0, (const __half*)p_E1,
        nullptr, (__half*)p_Q0, (__half*)p_Q1, (const float*)p_bv, 512, 1.0f,
        256, 256, 256, 512, 1,
        0, (long long)512 * 256, (long long)8192 * 512);
    // 11: fused attention
    k_attn<<<dim3(128, 8), 256, ATTN_SMEM>>>();
    // 12: out = (1/8) U @ WVcat  (1-term)
    k_mma<1><<<dim3(4, 64, 1), 256, SM1>>>(
        (const __half*)p_U0, nullptr,
        (const __half*)p_w0, nullptr,
        out, nullptr, nullptr, nullptr, 0, 0.125f,
        4096, 4096, 4096, 512, 0, 0, 0, 0);
}

// round 15
// speedup vs baseline: 1.5014x; 1.0244x over previous
#include <cuda_runtime.h>
#include <cuda_fp16.h>
#include <mma.h>
#include <cstdint>
#include <string.h>
#include <math.h>

using namespace nvcuda;

// ===========================================================================
//  xp  = split2(lrelu(x))              [32768,256]  elementwise prep
//  M_n = (WQ_n @ WK_n^T)/sqrt(512)     [8,512,512]  WMMA 3-term
//  E_n = W_enc @ M_n                   [8,256,512]  WMMA 3-term
//  bv_n = b_enc @ M_n                  [8,512]      FFMA GEMV
//  h   = xp @ W_enc^T planes + b       [32768,512]  WMMA 3-term
//  Q'  = xp_a @ E_n^T planes + bv_n    [8,8192,512] WMMA 3-term, K=256
//  attn fused: S=Q'@h^T (3-term) -> softmax -> U=P@h (1-term fp16)
//  out = (1/8) U @ WVcat               [8192,512]   WMMA 1-term fp16
// This round: attn phase-1 K=64 single-sync (32->8 syncs/CTA; smem 184320 is
// free since regs already cap k_attn at 1 CTA/SM), launch order fixed so the
// ncu capture point (#3) hits the encode GEMM.
// ===========================================================================

// -------------------- scratch (device globals) -----------------------------
static __device__ float  g_M [8u * 512u * 512u];
static __device__ float  g_E [8u * 256u * 512u];
static __device__ float  g_bv[8u * 512u];
static __device__ __half g_x0[32768u * 256u], g_x1[32768u * 256u];
static __device__ __half g_h0[32768u * 512u],  g_h1[32768u * 512u];
static __device__ __half g_Q0[8u * 8192u * 512u], g_Q1[8u * 8192u * 512u];
static __device__ __half g_U0[8192u * 4096u];
static __device__ __half g_Te0[512u * 256u],  g_Te1[512u * 256u];          // W_enc^T
static __device__ __half g_We0[256u * 512u],  g_We1[256u * 512u];          // W_enc (row)
static __device__ __half g_Tm0[8u * 512u * 512u], g_Tm1[8u * 512u * 512u]; // M^T
static __device__ __half g_TE0[8u * 512u * 256u], g_TE1[8u * 512u * 256u]; // E^T
static __device__ __half g_Tw0[512u * 4096u], g_Tw1[512u * 4096u];         // WVcat^T
static __device__ __half g_Wk0[8u * 512u * 512u], g_Wk1[8u * 512u * 512u]; // WK
static __device__ __half g_Wq0[8u * 512u * 512u], g_Wq1[8u * 512u * 512u]; // WQ

__device__ __forceinline__ float lrelu(float v) { return v > 0.0f ? v : 0.01f * v; }

__device__ __forceinline__ void split2(float v, __half& h0, __half& h1) {
    h0 = __float2half_rn(v);
    h1 = __float2half_rn(v - __half2float(h0));
}

__device__ __forceinline__ uint32_t h2u(__half2 v) {
    uint32_t u;
    memcpy(&u, &v, 4);
    return u;
}

// -------------------- cp.async helpers --------------------------------------
__device__ __forceinline__ void cp16(void* sdst, const void* gsrc) {
    uint32_t s = (uint32_t)__cvta_generic_to_shared(sdst);
    asm volatile("cp.async.cg.shared.global [%0], [%1], 16;" :: "r"(s), "l"(gsrc));
}
#define CP_COMMIT() asm volatile("cp.async.commit_group;" ::: "memory")
__device__ __forceinline__ void cp_wait0() { asm volatile("cp.async.wait_group 0;" ::: "memory"); }
__device__ __forceinline__ void cp_wait1() { asm volatile("cp.async.wait_group 1;" ::: "memory"); }

// ---------------------------------------------------------------------------
// xp = split2(lrelu(x)) elementwise, vectorized
// ---------------------------------------------------------------------------
__global__ __launch_bounds__(256) void k_xsplit(const float* __restrict__ X,
                                                __half* __restrict__ T0,
                                                __half* __restrict__ T1,
                                                size_t total4) {
    for (size_t i = (size_t)blockIdx.x * 256 + threadIdx.x; i < total4;
         i += (size_t)gridDim.x * 256) {
        float4 v = ((const float4*)X)[i];
        v.x = lrelu(v.x); v.y = lrelu(v.y); v.z = lrelu(v.z); v.w = lrelu(v.w);
        __align__(8) __half a[4], b[4];
        split2(v.x, a[0], b[0]); split2(v.y, a[1], b[1]);
        split2(v.z, a[2], b[2]); split2(v.w, a[3], b[3]);
        ((uint2*)T0)[i] = *(uint2*)a;
        ((uint2*)T1)[i] = *(uint2*)b;
    }
}

// ---------------------------------------------------------------------------
// three elementwise fp16 split2 jobs fused into one launch
// ---------------------------------------------------------------------------
__global__ __launch_bounds__(256) void k_split3(
    const float* __restrict__ A, __half* __restrict__ A0, __half* __restrict__ A1, size_t na,
    const float* __restrict__ B, __half* __restrict__ B0, __half* __restrict__ B1, size_t nb,
    const float* __restrict__ C, __half* __restrict__ C0, __half* __restrict__ C1, size_t nc) {
    const size_t stride = (size_t)gridDim.x * 256;
    const size_t t0 = (size_t)blockIdx.x * 256 + threadIdx.x;
    for (size_t i = t0; i < na; i += stride) split2(A[i], A0[i], A1[i]);
    for (size_t i = t0; i < nb; i += stride) split2(B[i], B0[i], B1[i]);
    for (size_t i = t0; i < nc; i += stride) split2(C[i], C0[i], C1[i]);
}

// ---------------------------------------------------------------------------
// tiled transpose + fp16 split2:  T*[n*K+k] = split(B[k*N+n])
// ---------------------------------------------------------------------------
__global__ __launch_bounds__(256) void k_tsplit2(const float* __restrict__ B,
                                                 __half* __restrict__ T0,
                                                 __half* __restrict__ T1,
                                                 int K, int N) {
    __shared__ __half s0[32][33];
    __shared__ __half s1[32][33];
    const size_t base = (size_t)blockIdx.z * (size_t)K * N;
    const int k0 = blockIdx.x * 32, n0 = blockIdx.y * 32;
    const int tx = threadIdx.x, ty = threadIdx.y;
#pragma unroll
    for (int i = 0; i < 4; i++) {
        int row = ty * 4 + i;
        float v = B[base + (size_t)(k0 + row) * N + n0 + tx];
        split2(v, s0[row][tx], s1[row][tx]);
    }
    __syncthreads();
#pragma unroll
    for (int i = 0; i < 4; i++) {
        int nrow = ty * 4 + i;
        size_t o = base + (size_t)(n0 + nrow) * K + k0 + tx;
        T0[o] = s0[tx][nrow];
        T1[o] = s1[tx][nrow];
    }
}

// ---------------------------------------------------------------------------
// bv_n = b_enc @ M_n : [8,512]
// ---------------------------------------------------------------------------
__global__ __launch_bounds__(512) void k_bv(const float* __restrict__ b_enc) {
    const int n = blockIdx.x, j = threadIdx.x;
    const float* Mn = g_M + (size_t)n * 512 * 512;
    float s = 0.0f;
    for (int k = 0; k < 512; k++) s += b_enc[k] * Mn[(size_t)k * 512 + j];
    g_bv[n * 512 + j] = s;
}

// ---------------------------------------------------------------------------
// WMMA GEMM, 256 thr, tile 128x128, K-chunk 64, 3-stage cp.async,
// single __syncthreads per K-tile.
// ---------------------------------------------------------------------------
template <int NT>
__global__ __launch_bounds__(256) void k_mma(
    const __half* __restrict__ A0g, const __half* __restrict__ A1g,
    const __half* __restrict__ B0g, const __half* __restrict__ B1g,
    float* __restrict__ Cf, __half* __restrict__ C0g, __half* __restrict__ C1g,
    const float* __restrict__ bias, long long biasHi, float alpha,
    int Ktot, int lda, int ldb, int ldc, int gather,
    long long aHi, long long bHi, long long cHi)
{
    constexpr int LDA = 72, LDB = 72;
    constexpr int PL  = (NT > 1) ? 2 : 1;
    constexpr int APL = 128 * LDA * 2;
    constexpr int BPL = 128 * LDB * 2;
    constexpr int STAGE = PL * (APL + BPL);

    extern __shared__ __align__(1024) char sm[];

    const int tid = threadIdx.x;
    const int w = tid >> 5;
    const int wm = w & 3;
    const int wn = w >> 2;
    const long long aoff = (long long)blockIdx.z * aHi;
    const long long boff = (long long)blockIdx.z * bHi;
    const long long coff = (long long)blockIdx.z * cHi;
    const float* biasz = bias ? (bias + (long long)blockIdx.z * biasHi) : (const float*)0;
    const int m0 = blockIdx.y * 128;
    const int n0 = blockIdx.x * 128;

    int crow[4], ck[4];
#pragma unroll
    for (int i = 0; i < 4; i++) {
        int id = tid + i * 256;
        crow[i] = id >> 3;
        ck[i] = (id & 7) * 8;
    }

    auto a_row = [&](int r) -> long long {
        int g = m0 + r;
        return gather ? (long long)(((g >> 6) << 8) + (g & 63)) : (long long)g;
    };

    wmma::fragment<wmma::accumulator, 16, 16, 16, float> acc[2][4];
#pragma unroll
    for (int mf = 0; mf < 2; mf++)
#pragma unroll
        for (int nf = 0; nf < 4; nf++) wmma::fill_fragment(acc[mf][nf], 0.0f);

    auto cp_tile = [&](int k0, int buf) {
        char* base = sm + buf * STAGE;
        __half* sA0 = (__half*)base;
        __half* sA1 = (__half*)(base + APL);
        __half* sB0 = (__half*)(base + PL * APL);
        __half* sB1 = (__half*)(base + PL * APL + BPL);
#pragma unroll
        for (int i = 0; i < 4; i++) {
            long long ga = aoff + a_row(crow[i]) * lda + k0 + ck[i];
            cp16(sA0 + crow[i] * LDA + ck[i], A0g + ga);
            if (NT > 1) cp16(sA1 + crow[i] * LDA + ck[i], A1g + ga);
            long long gb = boff + (long long)(n0 + crow[i]) * ldb + k0 + ck[i];
            cp16(sB0 + crow[i] * LDB + ck[i], B0g + gb);
            if (NT > 1) cp16(sB1 + crow[i] * LDB + ck[i], B1g + gb);
        }
        CP_COMMIT();
    };

    auto mma_tile = [&](int buf) {
        const char* base = sm + buf * STAGE;
        const __half* sA0 = (const __half*)(base);
        const __half* sA1 = (const __half*)(base + APL);
        const __half* sB0 = (const __half*)(base + PL * APL);
        const __half* sB1 = (const __half*)(base + PL * APL + BPL);
#pragma unroll
        for (int ks = 0; ks < 64; ks += 16) {
            wmma::fragment<wmma::matrix_a, 16, 16, 16, __half, wmma::row_major> a0f[2], a1f[2];
#pragma unroll
            for (int mf = 0; mf < 2; mf++) {
                int r0 = wm * 32 + mf * 16;
                wmma::load_matrix_sync(a0f[mf], sA0 + r0 * LDA + ks, LDA);
                if (NT > 1) wmma::load_matrix_sync(a1f[mf], sA1 + r0 * LDA + ks, LDA);
            }
#pragma unroll
            for (int nf = 0; nf < 4; nf++) {
                int col = wn * 64 + nf * 16;
                wmma::fragment<wmma::matrix_b, 16, 16, 16, __half, wmma::col_major> b0f, b1f;
                wmma::load_matrix_sync(b0f, sB0 + col * LDB + ks, LDB);
                if (NT > 1) wmma::load_matrix_sync(b1f, sB1 + col * LDB + ks, LDB);
#pragma unroll
                for (int mf = 0; mf < 2; mf++) {
                    wmma::mma_sync(acc[mf][nf], a0f[mf], b0f, acc[mf][nf]);
                    if (NT > 1) {
                        wmma::mma_sync(acc[mf][nf], a0f[mf], b1f, acc[mf][nf]);
                        wmma::mma_sync(acc[mf][nf], a1f[mf], b0f, acc[mf][nf]);
                    }
                }
            }
        }
    };

    const int numK = Ktot >> 6;
    cp_tile(0, 0);
    if (numK > 1) cp_tile(64, 1);
    for (int t = 0; t < numK; t++) {
        if (t + 1 < numK) cp_wait1(); else cp_wait0();
        __syncthreads();
        if (t + 2 < numK) cp_tile((t + 2) << 6, (t + 2) % 3);
        mma_tile(t % 3);
    }
    __syncthreads();

    float* Csm = (float*)sm;
#pragma unroll
    for (int mf = 0; mf < 2; mf++)
#pragma unroll
        for (int nf = 0; nf < 4; nf++) {
            int r0 = wm * 32 + mf * 16, c0 = wn * 64 + nf * 16;
            wmma::store_matrix_sync(Csm + r0 * 128 + c0, acc[mf][nf], 128, wmma::mem_row_major);
        }
    __syncthreads();

#pragma unroll
    for (int i = 0; i < 16; i++) {
        int f = tid + i * 256;
        int row = f >> 5, c4 = (f & 31) * 4;
        float4 v = *(float4*)(Csm + row * 128 + c4);
        v.x *= alpha; v.y *= alpha; v.z *= alpha; v.w *= alpha;
        if (biasz) {
            v.x += biasz[n0 + c4 + 0]; v.y += biasz[n0 + c4 + 1];
            v.z += biasz[n0 + c4 + 2]; v.w += biasz[n0 + c4 + 3];
        }
        long long o = coff + (long long)(m0 + row) * ldc + n0 + c4;
        if (Cf) {
            *(float4*)(Cf + o) = v;
        } else {
            __half x0, x1, y0, y1, z0, z1, w0, w1;
            split2(v.x, x0, x1); split2(v.y, y0, y1);
            split2(v.z, z0, z1); split2(v.w, w0, w1);
            __half2 p0 = __halves2half2(x0, y0), q0 = __halves2half2(z0, w0);
            *(uint2*)(C0g + o) = make_uint2(h2u(p0), h2u(q0));
            if (C1g) {
                __half2 p1 = __halves2half2(x1, y1), q1 = __halves2half2(z1, w1);
                *(uint2*)(C1g + o) = make_uint2(h2u(p1), h2u(q1));
            }
        }
    }
}

// ---------------------------------------------------------------------------
// Fused attention per (b, n) CTA.
// Phase1: K=64, 2-stage cp.async, SINGLE sync per K-tile (8 tiles).
//   stage layout: sA0 9216 | sA1 9216 | sB0 36864 | sB1 36864 = 92160/stage
// Phase3: 3-stage 16896 each.
// smem total 184320.  Ssm fp32 64x264 @0, Psm0 @67584 after phase1.
// ---------------------------------------------------------------------------
#define ATTN_SMEM 184320
#define P1_STAGE 92160
#define P1_APL 9216
#define P1_BOFF 18432
#define P1_BPL 36864

__global__ __launch_bounds__(256) void k_attn() {
    extern __shared__ __align__(1024) char sm[];
    const int tid = threadIdx.x;
    const int w = tid >> 5, lane = tid & 31;
    const int wm = w & 1, wn = w >> 1;
    const int b = blockIdx.x, n = blockIdx.y;

    float* Ssm = (float*)sm;
    __half* Psm0 = (__half*)(sm + 67584);

    const __half* Qb0 = g_Q0 + ((size_t)n * 8192 + (size_t)b * 64) * 512;
    const __half* Qb1 = g_Q1 + ((size_t)n * 8192 + (size_t)b * 64) * 512;
    const __half* Hb0 = g_h0 + (size_t)b * 256 * 512;
    const __half* Hb1 = g_h1 + (size_t)b * 256 * 512;

    wmma::fragment<wmma::accumulator, 16, 16, 16, float> acc[2][4];
#pragma unroll
    for (int mf = 0; mf < 2; mf++)
#pragma unroll
        for (int nf = 0; nf < 4; nf++) wmma::fill_fragment(acc[mf][nf], 0.0f);

    // ======== phase 1: S = Q' @ h^T  (K=512, 8 chunks of 64, 3-term) ======
    {
        auto p1_cp = [&](int k0, int buf) {
            char* base = sm + buf * P1_STAGE;
            __half* sA0 = (__half*)base;
            __half* sA1 = (__half*)(base + P1_APL);
            __half* sB0 = (__half*)(base + P1_BOFF);
            __half* sB1 = (__half*)(base + P1_BOFF + P1_BPL);
            // A: 64 rows x 8 chunks = 512 cps per plane; 2 per thread
#pragma unroll
            for (int i = 0; i < 2; i++) {
                int id = tid + i * 256;
                int ar = id >> 3, akc = (id & 7) * 8;
                long long ga = (size_t)ar * 512 + k0 + akc;
                cp16(sA0 + ar * 72 + akc, Qb0 + ga);
                cp16(sA1 + ar * 72 + akc, Qb1 + ga);
            }
            // B: 256 rows x 8 chunks = 2048 cps per plane; 8 per thread
#pragma unroll
            for (int i = 0; i < 8; i++) {
                int id = tid + i * 256;
                int br = id >> 3, bkc = (id & 7) * 8;
                long long gb = (size_t)br * 512 + k0 + bkc;
                cp16(sB0 + br * 72 + bkc, Hb0 + gb);
                cp16(sB1 + br * 72 + bkc, Hb1 + gb);
            }
            CP_COMMIT();
        };
        auto p1_mma = [&](int buf) {
            const char* base = sm + buf * P1_STAGE;
            const __half* sA0 = (const __half*)base;
            const __half* sA1 = (const __half*)(base + P1_APL);
            const __half* sB0 = (const __half*)(base + P1_BOFF);
            const __half* sB1 = (const __half*)(base + P1_BOFF + P1_BPL);
#pragma unroll
            for (int ks = 0; ks < 64; ks += 16) {
                wmma::fragment<wmma::matrix_a, 16, 16, 16, __half, wmma::row_major> a0f[2], a1f[2];
#pragma unroll
                for (int mf = 0; mf < 2; mf++) {
                    int r0 = wm * 32 + mf * 16;
                    wmma::load_matrix_sync(a0f[mf], sA0 + r0 * 72 + ks, 72);
                    wmma::load_matrix_sync(a1f[mf], sA1 + r0 * 72 + ks, 72);
                }
#pragma unroll
                for (int nf = 0; nf < 4; nf++) {
                    int col = wn * 64 + nf * 16;
                    wmma::fragment<wmma::matrix_b, 16, 16, 16, __half, wmma::col_major> b0f, b1f;
                    wmma::load_matrix_sync(b0f, sB0 + col * 72 + ks, 72);
                    wmma::load_matrix_sync(b1f, sB1 + col * 72 + ks, 72);
#pragma unroll
                    for (int mf = 0; mf < 2; mf++) {
                        wmma::mma_sync(acc[mf][nf], a0f[mf], b0f, acc[mf][nf]);
                        wmma::mma_sync(acc[mf][nf], a0f[mf], b1f, acc[mf][nf]);
                        wmma::mma_sync(acc[mf][nf], a1f[mf], b0f, acc[mf][nf]);
                    }
                }
            }
        };
        p1_cp(0, 0);
        for (int t = 0; t < 8; t++) {
            cp_wait0();
            __syncthreads();
            if (t + 1 < 8) p1_cp((t + 1) << 6, (t + 1) & 1);
            p1_mma(t & 1);
        }
        __syncthreads();
    }

    // ======== stage S -> smem fp32 ========
#pragma unroll
    for (int mf = 0; mf < 2; mf++)
#pragma unroll
        for (int nf = 0; nf < 4; nf++) {
            int r0 = wm * 32 + mf * 16, c0 = wn * 64 + nf * 16;
            wmma::store_matrix_sync(Ssm + r0 * 264 + c0, acc[mf][nf], 264, wmma::mem_row_major);
        }
    __syncthreads();

    // ======== softmax ========
#pragma unroll
    for (int i = 0; i < 8; i++) {
        int r = w * 8 + i;
        float* srow = Ssm + (size_t)r * 264 + lane * 8;
        float4 v0 = *(float4*)srow;
        float4 v1 = *(float4*)(srow + 4);
        float m = fmaxf(fmaxf(fmaxf(v0.x, v0.y), fmaxf(v0.z, v0.w)),
                        fmaxf(fmaxf(v1.x, v1.y), fmaxf(v1.z, v1.w)));
#pragma unroll
        for (int off = 16; off > 0; off >>= 1)
            m = fmaxf(m, __shfl_xor_sync(0xffffffffu, m, off));
        v0.x = __expf(v0.x - m); v0.y = __expf(v0.y - m);
        v0.z = __expf(v0.z - m); v0.w = __expf(v0.w - m);
        v1.x = __expf(v1.x - m); v1.y = __expf(v1.y - m);
        v1.z = __expf(v1.z - m); v1.w = __expf(v1.w - m);
        float s = v0.x + v0.y + v0.z + v0.w + v1.x + v1.y + v1.z + v1.w;
#pragma unroll
        for (int off = 16; off > 0; off >>= 1)
            s += __shfl_xor_sync(0xffffffffu, s, off);
        const float inv = 1.0f / s;
        __align__(16) __half h0[8];
        h0[0] = __float2half_rn(v0.x * inv); h0[1] = __float2half_rn(v0.y * inv);
        h0[2] = __float2half_rn(v0.z * inv); h0[3] = __float2half_rn(v0.w * inv);
        h0[4] = __float2half_rn(v1.x * inv); h0[5] = __float2half_rn(v1.y * inv);
        h0[6] = __float2half_rn(v1.z * inv); h0[7] = __float2half_rn(v1.w * inv);
        *(uint4*)(Psm0 + (size_t)r * 264 + lane * 8) = *(uint4*)h0;
    }
    __syncthreads();

    // ======== phase 3: U = P @ h  (1-term; two halves; K=256; 3-stage) ====
    for (int hh = 0; hh < 2; hh++) {
        const int d0 = hh * 256;
#pragma unroll
        for (int mf = 0; mf < 2; mf++)
#pragma unroll
            for (int nf = 0; nf < 4; nf++) wmma::fill_fragment(acc[mf][nf], 0.0f);

        auto p3_cp = [&](int k0, int buf) {
            __half* sH0 = (__half*)(sm + buf * 16896);
#pragma unroll
            for (int i = 0; i < 4; i++) {
                int id = tid + i * 256;
                int er = id >> 5, dc = (id & 31) * 8;
                cp16(sH0 + er * 264 + dc, Hb0 + (size_t)(k0 + er) * 512 + d0 + dc);
            }
            CP_COMMIT();
        };
        auto p3_mma = [&](int buf, int c) {
            const __half* sH0 = (const __half*)(sm + buf * 16896);
#pragma unroll
            for (int ks = 0; ks < 32; ks += 16) {
                wmma::fragment<wmma::matrix_a, 16, 16, 16, __half, wmma::row_major> a0f[2];
#pragma unroll
                for (int mf = 0; mf < 2; mf++) {
                    int r0 = wm * 32 + mf * 16;
                    wmma::load_matrix_sync(a0f[mf], Psm0 + r0 * 264 + c * 32 + ks, 264);
                }
#pragma unroll
                for (int nf = 0; nf < 4; nf++) {
                    int col = wn * 64 + nf * 16;
                    wmma::fragment<wmma::matrix_b, 16, 16, 16, __half, wmma::row_major> b0f;
                    wmma::load_matrix_sync(b0f, sH0 + ks * 264 + col, 264);
#pragma unroll
                    for (int mf = 0; mf < 2; mf++)
                        wmma::mma_sync(acc[mf][nf], a0f[mf], b0f, acc[mf][nf]);
                }
            }
        };
        p3_cp(0, 0);
        p3_cp(32, 1);
        for (int c = 0; c < 8; c++) {
            if (c + 1 < 8) cp_wait1(); else cp_wait0();
            __syncthreads();
            if (c + 2 < 8) p3_cp((c + 2) << 5, (c + 2) % 3);
            p3_mma(c % 3, c);
        }
        __syncthreads();

        float* Csm = (float*)sm;
#pragma unroll
        for (int mf = 0; mf < 2; mf++)
#pragma unroll
            for (int nf = 0; nf < 4; nf++) {
                int r0 = wm * 32 + mf * 16, c0 = wn * 64 + nf * 16;
                wmma::store_matrix_sync(Csm + r0 * 264 + c0, acc[mf][nf], 264, wmma::mem_row_major);
            }
        __syncthreads();
#pragma unroll
        for (int i = 0; i < 16; i++) {
            int id = tid + i * 256;
            int row = id >> 6, c4 = (id & 63) * 4;
            float4 v = *(float4*)(Csm + row * 264 + c4);
            __align__(8) __half h4[4];
            h4[0] = __float2half_rn(v.x); h4[1] = __float2half_rn(v.y);
            h4[2] = __float2half_rn(v.z); h4[3] = __float2half_rn(v.w);
            size_t o = (((size_t)(b * 64 + row)) * 8 + n) * 512 + d0 + c4;
            *(uint2*)(g_U0 + o) = *(uint2*)h4;
        }
        __syncthreads();
    }
}

// ---------------------------------------------------------------------------
extern "C" void kernel_launch(void* const* d_in, const int* in_sizes, int n_in,
                              void* d_out, int out_size) {
    const float* x     = (const float*)d_in[0];
    const float* W_enc = (const float*)d_in[1];
    const float* b_enc = (const float*)d_in[2];
    const float* WQ    = (const float*)d_in[3];
    const float* WK    = (const float*)d_in[4];
    const float* WV    = (const float*)d_in[5];
    float* out = (float*)d_out;

    const int SM3 = 3 * 2 * (128 * 72 * 2 + 128 * 72 * 2);   // 221184
    const int SM1 = 3 * (128 * 72 * 2 + 128 * 72 * 2);       // 110592
    cudaFuncSetAttribute(k_mma<3>, cudaFuncAttributeMaxDynamicSharedMemorySize, SM3);
    cudaFuncSetAttribute(k_mma<1>, cudaFuncAttributeMaxDynamicSharedMemorySize, SM1);
    cudaFuncSetAttribute(k_attn, cudaFuncAttributeMaxDynamicSharedMemorySize, ATTN_SMEM);

    void *p_M, *p_E, *p_bv, *p_x0, *p_x1, *p_h0, *p_h1, *p_Q0, *p_Q1, *p_U0;
    void *p_e0, *p_e1, *p_we0, *p_we1, *p_m0, *p_m1, *p_E0, *p_E1;
    void *p_w0, *p_w1, *p_k0, *p_k1, *p_q0, *p_q1;
    cudaGetSymbolAddress(&p_M, g_M);
    cudaGetSymbolAddress(&p_E, g_E);
    cudaGetSymbolAddress(&p_bv, g_bv);
    cudaGetSymbolAddress(&p_x0, g_x0); cudaGetSymbolAddress(&p_x1, g_x1);
    cudaGetSymbolAddress(&p_h0, g_h0); cudaGetSymbolAddress(&p_h1, g_h1);
    cudaGetSymbolAddress(&p_Q0, g_Q0); cudaGetSymbolAddress(&p_Q1, g_Q1);
    cudaGetSymbolAddress(&p_U0, g_U0);
    cudaGetSymbolAddress(&p_e0, g_Te0); cudaGetSymbolAddress(&p_e1, g_Te1);
    cudaGetSymbolAddress(&p_we0, g_We0); cudaGetSymbolAddress(&p_we1, g_We1);
    cudaGetSymbolAddress(&p_m0, g_Tm0); cudaGetSymbolAddress(&p_m1, g_Tm1);
    cudaGetSymbolAddress(&p_E0, g_TE0); cudaGetSymbolAddress(&p_E1, g_TE1);
    cudaGetSymbolAddress(&p_w0, g_Tw0); cudaGetSymbolAddress(&p_w1, g_Tw1);
    cudaGetSymbolAddress(&p_k0, g_Wk0); cudaGetSymbolAddress(&p_k1, g_Wk1);
    cudaGetSymbolAddress(&p_q0, g_Wq0); cudaGetSymbolAddress(&p_q1, g_Wq1);

    // 0: x split
    k_xsplit<<<dim3(2048), 256>>>(x, (__half*)p_x0, (__half*)p_x1, (size_t)32768 * 256 / 4);
    // 1: We + WK + WQ elementwise splits (fused)
    k_split3<<<dim3(512), 256>>>(
        W_enc, (__half*)p_we0, (__half*)p_we1, (size_t)256 * 512,
        WK, (__half*)p_k0, (__half*)p_k1, (size_t)8 * 512 * 512,
        WQ, (__half*)p_q0, (__half*)p_q1, (size_t)8 * 512 * 512);
    // 2: W_enc^T split
    k_tsplit2<<<dim3(8, 16, 1), dim3(32, 8)>>>(W_enc, (__half*)p_e0, (__half*)p_e1, 256, 512);
    // 3: encode (PROFILE TARGET): h planes = xp @ Te + b
    k_mma<3><<<dim3(4, 256, 1), 256, SM3>>>(
        (const __half*)p_x0, (const __half*)p_x1,
        (const __half*)p_e0, (const __half*)p_e1,
        nullptr, (__half*)p_h0, (__half*)p_h1, b_enc, 0, 1.0f,
        256, 256, 256, 512, 0, 0, 0, 0);
    // 4: WV^T split
    k_tsplit2<<<dim3(128, 16, 1), dim3(32, 8)>>>(WV, (__half*)p_w0, (__half*)p_w1, 4096, 512);
    // 5: M_n = (WQ_n @ WK_n^T) * scale  (secondary profile target)
    k_mma<3><<<dim3(4, 4, 8), 256, SM3>>>(
        (const __half*)p_q0, (const __half*)p_q1,
        (const __half*)p_k0, (const __half*)p_k1,
        (float*)p_M, nullptr, nullptr, nullptr, 0, 0.04419417382415922f,
        512, 512, 512, 512, 0,
        (long long)512 * 512, (long long)512 * 512, (long long)512 * 512);
    // 6: M^T split
    k_tsplit2<<<dim3(16, 16, 8), dim3(32, 8)>>>((const float*)p_M, (__half*)p_m0, (__half*)p_m1, 512, 512);
    // 7: bv = b @ M
    k_bv<<<dim3(8), 512>>>(b_enc);
    // 8: E_n = W_enc @ M_n
    k_mma<3><<<dim3(4, 2, 8), 256, SM3>>>(
        (const __half*)p_we0, (const __half*)p_we1,
        (const __half*)p_m0, (const __half*)p_m1,
        (float*)p_E, nullptr, nullptr, nullptr, 0, 1.0f,
        512, 512, 512, 512, 0,
        0, (long long)512 * 512, (long long)256 * 512);
    // 9: E^T split
    k_tsplit2<<<dim3(8, 16, 8), dim3(32, 8)>>>((const float*)p_E, (__half*)p_E0, (__half*)p_E1, 256, 512);
    // 10: Q' = xp_a @ TE + bv  (K=256, gather, batched)
    k_mma<3><<<dim3(4, 64, 8), 256, SM3>>>(
        (const __half*)p_x0, (const __half*)p_x1,
        (const __half*)p_E0, (const __half*)p_E1,
        nullptr, (__half*)p_Q0, (__half*)p_Q1, (const float*)p_bv, 512, 1.0f,
        256, 256, 256, 512, 1,
        0, (long long)512 * 256, (long long)8192 * 512);
    // 11: fused attention
    k_attn<<<dim3(128, 8), 256, ATTN_SMEM>>>();
    // 12: out = (1/8) U @ WVcat  (1-term)
    k_mma<1><<<dim3(4, 64, 1), 256, SM1>>>(
        (const __half*)p_U0, nullptr,
        (const __half*)p_w0, nullptr,
        out, nullptr, nullptr, nullptr, 0, 0.125f,
        4096, 4096, 4096, 512, 0, 0, 0, 0);
}